// round 2
// baseline (speedup 1.0000x reference)
#include <cuda_runtime.h>

#define D_MODEL   96
#define WIN       16
#define STRIDE    8
#define NHEAD     6
#define HEAD_DIM  16
#define FFN_H     192
#define L_SEQ     8192
#define NUM_WIN   1023
#define WPC       8            // windows per CTA
#define MROWS     (WPC * WIN)  // 128
#define NT        256

// smem layout (floats): s_a [128*96], then qkv region [128*288]
// qkv region is reused after attention as: s_h [128*96] + s_g [128*192]
#define SA_OFF    0
#define SQKV_OFF  (MROWS * 96)
#define SMEM_FLOATS (MROWS * 96 + MROWS * 288)

__global__ void zero_out_kernel(float* __restrict__ out, int n) {
    int i = blockIdx.x * blockDim.x + threadIdx.x;
    if (i < n) out[i] = 0.0f;
}

__device__ __forceinline__ float gelu_tanh(float x) {
    float x3 = x * x * x;
    float inner = 0.7978845608028654f * fmaf(0.044715f, x3, x);
    return 0.5f * x * (1.0f + tanhf(inner));
}

__device__ __forceinline__ int row_pos(int w0, int row) {
    int p = (w0 + (row >> 4)) * STRIDE + (row & 15);
    return p < (L_SEQ - 1) ? p : (L_SEQ - 1);
}

// ---- LayerNorm over 128 rows x 96 dims; 2 threads per row ----
__device__ __forceinline__ void ln_body(float4* v, int half,
                                        float* __restrict__ dst,
                                        const float* __restrict__ g,
                                        const float* __restrict__ bb) {
    float s = 0.f;
#pragma unroll
    for (int i = 0; i < 12; i++) s += v[i].x + v[i].y + v[i].z + v[i].w;
    s += __shfl_xor_sync(0xffffffffu, s, 1);
    float mean = s * (1.0f / 96.0f);
    float q = 0.f;
#pragma unroll
    for (int i = 0; i < 12; i++) {
        float dx = v[i].x - mean, dy = v[i].y - mean;
        float dz = v[i].z - mean, dw = v[i].w - mean;
        q = fmaf(dx, dx, q); q = fmaf(dy, dy, q);
        q = fmaf(dz, dz, q); q = fmaf(dw, dw, q);
    }
    q += __shfl_xor_sync(0xffffffffu, q, 1);
    float rstd = rsqrtf(q * (1.0f / 96.0f) + 1e-5f);
#pragma unroll
    for (int i = 0; i < 12; i++) {
        int d = half * 48 + i * 4;
        float4 gv = *(const float4*)(g + d);
        float4 bv = *(const float4*)(bb + d);
        float4 o;
        o.x = (v[i].x - mean) * rstd * gv.x + bv.x;
        o.y = (v[i].y - mean) * rstd * gv.y + bv.y;
        o.z = (v[i].z - mean) * rstd * gv.z + bv.z;
        o.w = (v[i].w - mean) * rstd * gv.w + bv.w;
        *(float4*)(dst + d) = o;
    }
}

__device__ __forceinline__ void ln_smem(const float* __restrict__ in,
                                        float* __restrict__ out,
                                        const float* __restrict__ g,
                                        const float* __restrict__ bb,
                                        int tid) {
    int row = tid >> 1, half = tid & 1;
    const float* src = in + row * 96 + half * 48;
    float4 v[12];
#pragma unroll
    for (int i = 0; i < 12; i++) v[i] = *(const float4*)(src + i * 4);
    ln_body(v, half, out + row * 96, g, bb);
}

__device__ __forceinline__ void ln_gmem(const float* __restrict__ xb,
                                        int w0,
                                        float* __restrict__ out,
                                        const float* __restrict__ g,
                                        const float* __restrict__ bb,
                                        int tid) {
    int row = tid >> 1, half = tid & 1;
    int p = row_pos(w0, row);
    const float* src = xb + (size_t)p * 96 + half * 48;
    float4 v[12];
#pragma unroll
    for (int i = 0; i < 12; i++) v[i] = *(const float4*)(src + i * 4);
    ln_body(v, half, out + row * 96, g, bb);
}

// ---- C(128xN) = A(128xK, smem) @ W(KxN, gmem) + bias ----
// EPI 0: store   1: gelu-store   2: C = seg(gmem) + acc   3: C += acc
template <int N, int K, int EPI>
__device__ __forceinline__ void gemmM(const float* __restrict__ A,
                                      const float* __restrict__ W,
                                      const float* __restrict__ bias,
                                      float* __restrict__ C,
                                      const float* __restrict__ xb,
                                      int w0, int tid) {
    const int rg = tid >> 4;          // 0..15, owns rows rg*8 .. rg*8+7
    const int cg = tid & 15;          // 0..15, owns cols j4*4 .. +3
    const int r0 = rg * 8;
    for (int j4 = cg; j4 < N / 4; j4 += 16) {
        const int j = j4 * 4;
        float4 bj = *(const float4*)(bias + j);
        float4 acc[8];
#pragma unroll
        for (int r = 0; r < 8; r++) acc[r] = bj;
#pragma unroll 2
        for (int k = 0; k < K; k += 4) {
            float4 w0v = *(const float4*)(W + (size_t)(k + 0) * N + j);
            float4 w1v = *(const float4*)(W + (size_t)(k + 1) * N + j);
            float4 w2v = *(const float4*)(W + (size_t)(k + 2) * N + j);
            float4 w3v = *(const float4*)(W + (size_t)(k + 3) * N + j);
#pragma unroll
            for (int r = 0; r < 8; r++) {
                float4 a = *(const float4*)(A + (r0 + r) * K + k);
                acc[r].x = fmaf(a.x, w0v.x, acc[r].x);
                acc[r].x = fmaf(a.y, w1v.x, acc[r].x);
                acc[r].x = fmaf(a.z, w2v.x, acc[r].x);
                acc[r].x = fmaf(a.w, w3v.x, acc[r].x);
                acc[r].y = fmaf(a.x, w0v.y, acc[r].y);
                acc[r].y = fmaf(a.y, w1v.y, acc[r].y);
                acc[r].y = fmaf(a.z, w2v.y, acc[r].y);
                acc[r].y = fmaf(a.w, w3v.y, acc[r].y);
                acc[r].z = fmaf(a.x, w0v.z, acc[r].z);
                acc[r].z = fmaf(a.y, w1v.z, acc[r].z);
                acc[r].z = fmaf(a.z, w2v.z, acc[r].z);
                acc[r].z = fmaf(a.w, w3v.z, acc[r].z);
                acc[r].w = fmaf(a.x, w0v.w, acc[r].w);
                acc[r].w = fmaf(a.y, w1v.w, acc[r].w);
                acc[r].w = fmaf(a.z, w2v.w, acc[r].w);
                acc[r].w = fmaf(a.w, w3v.w, acc[r].w);
            }
        }
#pragma unroll
        for (int r = 0; r < 8; r++) {
            const int row = r0 + r;
            float* cp = C + row * N + j;
            if (EPI == 0) {
                *(float4*)cp = acc[r];
            } else if (EPI == 1) {
                float4 o;
                o.x = gelu_tanh(acc[r].x); o.y = gelu_tanh(acc[r].y);
                o.z = gelu_tanh(acc[r].z); o.w = gelu_tanh(acc[r].w);
                *(float4*)cp = o;
            } else if (EPI == 2) {
                int p = row_pos(w0, row);
                float4 sv = *(const float4*)(xb + (size_t)p * 96 + j);
                float4 o;
                o.x = sv.x + acc[r].x; o.y = sv.y + acc[r].y;
                o.z = sv.z + acc[r].z; o.w = sv.w + acc[r].w;
                *(float4*)cp = o;
            } else {
                float4 c = *(const float4*)cp;
                c.x += acc[r].x; c.y += acc[r].y;
                c.z += acc[r].z; c.w += acc[r].w;
                *(float4*)cp = c;
            }
        }
    }
}

__global__ void __launch_bounds__(NT)
win_block_kernel(const float* __restrict__ x,
                 const float* __restrict__ ln1_g, const float* __restrict__ ln1_b,
                 const float* __restrict__ qkv_w, const float* __restrict__ qkv_b,
                 const float* __restrict__ out_w, const float* __restrict__ out_b,
                 const float* __restrict__ ln2_g, const float* __restrict__ ln2_b,
                 const float* __restrict__ ffn_w1, const float* __restrict__ ffn_b1,
                 const float* __restrict__ ffn_w2, const float* __restrict__ ffn_b2,
                 const float* __restrict__ pln_g, const float* __restrict__ pln_b,
                 float* __restrict__ out) {
    extern __shared__ float sm[];
    float* s_a   = sm + SA_OFF;        // 128 x 96
    float* s_qkv = sm + SQKV_OFF;      // 128 x 288
    float* s_h   = s_qkv;              // reuse: 128 x 96
    float* s_g   = s_qkv + MROWS * 96; // reuse: 128 x 192

    const int tid = threadIdx.x;
    const int w0  = blockIdx.x * WPC;
    const int b   = blockIdx.y;
    const float* xb = x + (size_t)b * L_SEQ * 96;

    // 1. LN1 on gmem rows -> s_a
    ln_gmem(xb, w0, s_a, ln1_g, ln1_b, tid);
    __syncthreads();

    // 2. qkv GEMM: s_a(128x96) @ qkv_w -> s_qkv(128x288)
    gemmM<288, 96, 0>(s_a, qkv_w, qkv_b, s_qkv, nullptr, w0, tid);
    __syncthreads();

    // 3. causal attention; 768 tasks = 8 win x 6 heads x 16 qt; o -> s_a
#pragma unroll
    for (int pass = 0; pass < 3; pass++) {
        const int task = tid + pass * NT;
        const int wi  = task / 96;
        const int rem = task % 96;
        const int h   = rem >> 4;
        const int qt  = rem & 15;
        const int rbase = wi * 16;
        const float* qrow = s_qkv + (rbase + qt) * 288 + h * HEAD_DIM;
        float qv[16];
#pragma unroll
        for (int d4 = 0; d4 < 4; d4++) {
            float4 t4 = *(const float4*)(qrow + d4 * 4);
            qv[d4*4+0]=t4.x; qv[d4*4+1]=t4.y; qv[d4*4+2]=t4.z; qv[d4*4+3]=t4.w;
        }
        float p[16];
        float mx = -1e30f;
#pragma unroll
        for (int kt = 0; kt < 16; kt++) {
            const float* krow = s_qkv + (rbase + kt) * 288 + 96 + h * HEAD_DIM;
            float sd = 0.f;
#pragma unroll
            for (int d4 = 0; d4 < 4; d4++) {
                float4 k4 = *(const float4*)(krow + d4 * 4);
                sd = fmaf(qv[d4*4+0], k4.x, sd);
                sd = fmaf(qv[d4*4+1], k4.y, sd);
                sd = fmaf(qv[d4*4+2], k4.z, sd);
                sd = fmaf(qv[d4*4+3], k4.w, sd);
            }
            sd *= 0.25f;
            p[kt] = (kt <= qt) ? sd : -1e30f;
            mx = fmaxf(mx, p[kt]);
        }
        float denom = 0.f;
#pragma unroll
        for (int kt = 0; kt < 16; kt++) { p[kt] = __expf(p[kt] - mx); denom += p[kt]; }
        float inv = 1.0f / denom;
        float ov[16];
#pragma unroll
        for (int d = 0; d < 16; d++) ov[d] = 0.f;
#pragma unroll
        for (int kt = 0; kt < 16; kt++) {
            const float* vrow = s_qkv + (rbase + kt) * 288 + 192 + h * HEAD_DIM;
#pragma unroll
            for (int d4 = 0; d4 < 4; d4++) {
                float4 v4 = *(const float4*)(vrow + d4 * 4);
                ov[d4*4+0] = fmaf(p[kt], v4.x, ov[d4*4+0]);
                ov[d4*4+1] = fmaf(p[kt], v4.y, ov[d4*4+1]);
                ov[d4*4+2] = fmaf(p[kt], v4.z, ov[d4*4+2]);
                ov[d4*4+3] = fmaf(p[kt], v4.w, ov[d4*4+3]);
            }
        }
        float* orow = s_a + (rbase + qt) * 96 + h * HEAD_DIM;
#pragma unroll
        for (int d = 0; d < 16; d++) orow[d] = ov[d] * inv;
    }
    __syncthreads();

    // 4. out-proj: h = seg + o@out_w + out_b -> s_h (overwrites qkv region)
    gemmM<96, 96, 2>(s_a, out_w, out_b, s_h, xb, w0, tid);
    __syncthreads();

    // 5. LN2: s_h -> s_a
    ln_smem(s_h, s_a, ln2_g, ln2_b, tid);
    __syncthreads();

    // 6. FFN1 + gelu: s_a @ w1 -> s_g
    gemmM<FFN_H, 96, 1>(s_a, ffn_w1, ffn_b1, s_g, nullptr, w0, tid);
    __syncthreads();

    // 7. FFN2: s_g @ w2 added into s_h
    gemmM<96, FFN_H, 3>(s_g, ffn_w2, ffn_b2, s_h, nullptr, w0, tid);
    __syncthreads();

    // 8. final LN: s_h -> s_a
    ln_smem(s_h, s_a, pln_g, pln_b, tid);
    __syncthreads();

    // 9. scatter-add with analytic coverage count
    for (int i = tid; i < MROWS * 96; i += NT) {
        int row = i / 96;
        int d   = i - row * 96;
        int win = w0 + (row >> 4);
        if (win < NUM_WIN) {
            int pos = win * STRIDE + (row & 15);
            float invc = (pos < STRIDE || pos >= L_SEQ - STRIDE) ? 1.0f : 0.5f;
            atomicAdd(out + ((size_t)b * L_SEQ + pos) * 96 + d, s_a[i] * invc);
        }
    }
}

extern "C" void kernel_launch(void* const* d_in, const int* in_sizes, int n_in,
                              void* d_out, int out_size) {
    const float* x      = (const float*)d_in[0];
    const float* ln1_g  = (const float*)d_in[1];
    const float* ln1_b  = (const float*)d_in[2];
    const float* qkv_w  = (const float*)d_in[3];
    const float* qkv_b  = (const float*)d_in[4];
    const float* out_w  = (const float*)d_in[5];
    const float* out_b  = (const float*)d_in[6];
    const float* ln2_g  = (const float*)d_in[7];
    const float* ln2_b  = (const float*)d_in[8];
    const float* ffn_w1 = (const float*)d_in[9];
    const float* ffn_b1 = (const float*)d_in[10];
    const float* ffn_w2 = (const float*)d_in[11];
    const float* ffn_b2 = (const float*)d_in[12];
    const float* pln_g  = (const float*)d_in[13];
    const float* pln_b  = (const float*)d_in[14];
    float* out = (float*)d_out;

    const int B = in_sizes[0] / (L_SEQ * D_MODEL);
    const int nblk = (NUM_WIN + WPC - 1) / WPC;   // 128
    const int smem_bytes = SMEM_FLOATS * sizeof(float);  // 196608

    static int attr_set = 0;
    if (!attr_set) {
        cudaFuncSetAttribute(win_block_kernel,
                             cudaFuncAttributeMaxDynamicSharedMemorySize,
                             smem_bytes);
        attr_set = 1;
    }

    zero_out_kernel<<<(out_size + 511) / 512, 512>>>(out, out_size);

    dim3 grid(nblk, B);
    win_block_kernel<<<grid, NT, smem_bytes>>>(
        x, ln1_g, ln1_b, qkv_w, qkv_b, out_w, out_b,
        ln2_g, ln2_b, ffn_w1, ffn_b1, ffn_w2, ffn_b2,
        pln_g, pln_b, out);
}

// round 3
// speedup vs baseline: 1.3203x; 1.3203x over previous
#include <cuda_runtime.h>

#define D_MODEL   96
#define WIN       16
#define STRIDE    8
#define NHEAD     6
#define HEAD_DIM  16
#define FFN_H     192
#define L_SEQ     8192
#define NUM_WIN   1023
#define WPC       4            // windows per CTA
#define MROWS     (WPC * WIN)  // 64
#define NT        256

// smem (floats): s_a [64*96], qkv region [64*288] (reused as h[64*96]+g[64*192])
#define SMEM_FLOATS (MROWS * 96 + MROWS * 288)   // 24576 floats = 96 KB

__global__ void zero_out_kernel(float* __restrict__ out, int n) {
    int i = blockIdx.x * blockDim.x + threadIdx.x;
    if (i < n) out[i] = 0.0f;
}

__device__ __forceinline__ float gelu_tanh(float x) {
    float x3 = x * x * x;
    float inner = 0.7978845608028654f * fmaf(0.044715f, x3, x);
    return 0.5f * x * (1.0f + tanhf(inner));
}

__device__ __forceinline__ int row_pos(int w0, int row) {
    int p = (w0 + (row >> 4)) * STRIDE + (row & 15);
    return p < (L_SEQ - 1) ? p : (L_SEQ - 1);
}

// ---- LayerNorm: 64 rows x 96 dims; 4 threads per row (24 floats each) ----
__device__ __forceinline__ void ln_body(float4* v, int quarter,
                                        float* __restrict__ dst,
                                        const float* __restrict__ g,
                                        const float* __restrict__ bb) {
    float s = 0.f;
#pragma unroll
    for (int i = 0; i < 6; i++) s += v[i].x + v[i].y + v[i].z + v[i].w;
    s += __shfl_xor_sync(0xffffffffu, s, 1);
    s += __shfl_xor_sync(0xffffffffu, s, 2);
    float mean = s * (1.0f / 96.0f);
    float q = 0.f;
#pragma unroll
    for (int i = 0; i < 6; i++) {
        float dx = v[i].x - mean, dy = v[i].y - mean;
        float dz = v[i].z - mean, dw = v[i].w - mean;
        q = fmaf(dx, dx, q); q = fmaf(dy, dy, q);
        q = fmaf(dz, dz, q); q = fmaf(dw, dw, q);
    }
    q += __shfl_xor_sync(0xffffffffu, q, 1);
    q += __shfl_xor_sync(0xffffffffu, q, 2);
    float rstd = rsqrtf(q * (1.0f / 96.0f) + 1e-5f);
#pragma unroll
    for (int i = 0; i < 6; i++) {
        int d = quarter * 24 + i * 4;
        float4 gv = *(const float4*)(g + d);
        float4 bv = *(const float4*)(bb + d);
        float4 o;
        o.x = (v[i].x - mean) * rstd * gv.x + bv.x;
        o.y = (v[i].y - mean) * rstd * gv.y + bv.y;
        o.z = (v[i].z - mean) * rstd * gv.z + bv.z;
        o.w = (v[i].w - mean) * rstd * gv.w + bv.w;
        *(float4*)(dst + d) = o;
    }
}

__device__ __forceinline__ void ln_smem(const float* __restrict__ in,
                                        float* __restrict__ out,
                                        const float* __restrict__ g,
                                        const float* __restrict__ bb,
                                        int tid) {
    int row = tid >> 2, quarter = tid & 3;
    const float* src = in + row * 96 + quarter * 24;
    float4 v[6];
#pragma unroll
    for (int i = 0; i < 6; i++) v[i] = *(const float4*)(src + i * 4);
    ln_body(v, quarter, out + row * 96, g, bb);
}

__device__ __forceinline__ void ln_gmem(const float* __restrict__ xb,
                                        int w0,
                                        float* __restrict__ out,
                                        const float* __restrict__ g,
                                        const float* __restrict__ bb,
                                        int tid) {
    int row = tid >> 2, quarter = tid & 3;
    int p = row_pos(w0, row);
    const float* src = xb + (size_t)p * 96 + quarter * 24;
    float4 v[6];
#pragma unroll
    for (int i = 0; i < 6; i++) v[i] = *(const float4*)(src + i * 4);
    ln_body(v, quarter, out + row * 96, g, bb);
}

// ---- C(64xN) = A(64xK, smem) @ W(KxN, gmem) + bias ----
// thread tile 4 rows x 4 cols. EPI 0: store  1: gelu  2: seg(gmem)+acc  3: C+=acc
template <int N, int K, int EPI>
__device__ __forceinline__ void gemmM(const float* __restrict__ A,
                                      const float* __restrict__ W,
                                      const float* __restrict__ bias,
                                      float* __restrict__ C,
                                      const float* __restrict__ xb,
                                      int w0, int tid) {
    const int rg = tid >> 4;          // 0..15 -> rows rg*4 .. +3
    const int cg = tid & 15;
    const int r0 = rg * 4;
    for (int j4 = cg; j4 < N / 4; j4 += 16) {
        const int j = j4 * 4;
        float4 bj = *(const float4*)(bias + j);
        float4 acc[4];
#pragma unroll
        for (int r = 0; r < 4; r++) acc[r] = bj;
#pragma unroll 4
        for (int k = 0; k < K; k += 4) {
            float4 w0v = *(const float4*)(W + (size_t)(k + 0) * N + j);
            float4 w1v = *(const float4*)(W + (size_t)(k + 1) * N + j);
            float4 w2v = *(const float4*)(W + (size_t)(k + 2) * N + j);
            float4 w3v = *(const float4*)(W + (size_t)(k + 3) * N + j);
#pragma unroll
            for (int r = 0; r < 4; r++) {
                float4 a = *(const float4*)(A + (r0 + r) * K + k);
                acc[r].x = fmaf(a.x, w0v.x, acc[r].x);
                acc[r].x = fmaf(a.y, w1v.x, acc[r].x);
                acc[r].x = fmaf(a.z, w2v.x, acc[r].x);
                acc[r].x = fmaf(a.w, w3v.x, acc[r].x);
                acc[r].y = fmaf(a.x, w0v.y, acc[r].y);
                acc[r].y = fmaf(a.y, w1v.y, acc[r].y);
                acc[r].y = fmaf(a.z, w2v.y, acc[r].y);
                acc[r].y = fmaf(a.w, w3v.y, acc[r].y);
                acc[r].z = fmaf(a.x, w0v.z, acc[r].z);
                acc[r].z = fmaf(a.y, w1v.z, acc[r].z);
                acc[r].z = fmaf(a.z, w2v.z, acc[r].z);
                acc[r].z = fmaf(a.w, w3v.z, acc[r].z);
                acc[r].w = fmaf(a.x, w0v.w, acc[r].w);
                acc[r].w = fmaf(a.y, w1v.w, acc[r].w);
                acc[r].w = fmaf(a.z, w2v.w, acc[r].w);
                acc[r].w = fmaf(a.w, w3v.w, acc[r].w);
            }
        }
#pragma unroll
        for (int r = 0; r < 4; r++) {
            const int row = r0 + r;
            float* cp = C + row * N + j;
            if (EPI == 0) {
                *(float4*)cp = acc[r];
            } else if (EPI == 1) {
                float4 o;
                o.x = gelu_tanh(acc[r].x); o.y = gelu_tanh(acc[r].y);
                o.z = gelu_tanh(acc[r].z); o.w = gelu_tanh(acc[r].w);
                *(float4*)cp = o;
            } else if (EPI == 2) {
                int p = row_pos(w0, row);
                float4 sv = *(const float4*)(xb + (size_t)p * 96 + j);
                float4 o;
                o.x = sv.x + acc[r].x; o.y = sv.y + acc[r].y;
                o.z = sv.z + acc[r].z; o.w = sv.w + acc[r].w;
                *(float4*)cp = o;
            } else {
                float4 c = *(const float4*)cp;
                c.x += acc[r].x; c.y += acc[r].y;
                c.z += acc[r].z; c.w += acc[r].w;
                *(float4*)cp = c;
            }
        }
    }
}

__global__ void __launch_bounds__(NT, 2)
win_block_kernel(const float* __restrict__ x,
                 const float* __restrict__ ln1_g, const float* __restrict__ ln1_b,
                 const float* __restrict__ qkv_w, const float* __restrict__ qkv_b,
                 const float* __restrict__ out_w, const float* __restrict__ out_b,
                 const float* __restrict__ ln2_g, const float* __restrict__ ln2_b,
                 const float* __restrict__ ffn_w1, const float* __restrict__ ffn_b1,
                 const float* __restrict__ ffn_w2, const float* __restrict__ ffn_b2,
                 const float* __restrict__ pln_g, const float* __restrict__ pln_b,
                 float* __restrict__ out) {
    extern __shared__ float sm[];
    float* s_a   = sm;                 // 64 x 96
    float* s_qkv = sm + MROWS * 96;    // 64 x 288
    float* s_h   = s_qkv;              // reuse: 64 x 96
    float* s_g   = s_qkv + MROWS * 96; // reuse: 64 x 192

    const int tid = threadIdx.x;
    const int w0  = blockIdx.x * WPC;
    const int b   = blockIdx.y;
    const float* xb = x + (size_t)b * L_SEQ * 96;

    // 1. LN1 on gmem rows -> s_a
    ln_gmem(xb, w0, s_a, ln1_g, ln1_b, tid);
    __syncthreads();

    // 2. qkv GEMM: s_a(64x96) @ qkv_w -> s_qkv(64x288)
    gemmM<288, 96, 0>(s_a, qkv_w, qkv_b, s_qkv, nullptr, w0, tid);
    __syncthreads();

    // 3. causal attention; 384 tasks = 4 win x 6 heads x 16 qt; o -> s_a
#pragma unroll
    for (int pass = 0; pass < 2; pass++) {
        const int task = tid + pass * NT;
        if (task < WPC * 96) {
            const int wi  = task / 96;
            const int rem = task % 96;
            const int h   = rem >> 4;
            const int qt  = rem & 15;
            const int rbase = wi * 16;
            const float* qrow = s_qkv + (rbase + qt) * 288 + h * HEAD_DIM;
            float qv[16];
#pragma unroll
            for (int d4 = 0; d4 < 4; d4++) {
                float4 t4 = *(const float4*)(qrow + d4 * 4);
                qv[d4*4+0]=t4.x; qv[d4*4+1]=t4.y; qv[d4*4+2]=t4.z; qv[d4*4+3]=t4.w;
            }
            float p[16];
            float mx = -1e30f;
#pragma unroll
            for (int kt = 0; kt < 16; kt++) {
                const float* krow = s_qkv + (rbase + kt) * 288 + 96 + h * HEAD_DIM;
                float sd = 0.f;
#pragma unroll
                for (int d4 = 0; d4 < 4; d4++) {
                    float4 k4 = *(const float4*)(krow + d4 * 4);
                    sd = fmaf(qv[d4*4+0], k4.x, sd);
                    sd = fmaf(qv[d4*4+1], k4.y, sd);
                    sd = fmaf(qv[d4*4+2], k4.z, sd);
                    sd = fmaf(qv[d4*4+3], k4.w, sd);
                }
                sd *= 0.25f;
                p[kt] = (kt <= qt) ? sd : -1e30f;
                mx = fmaxf(mx, p[kt]);
            }
            float denom = 0.f;
#pragma unroll
            for (int kt = 0; kt < 16; kt++) { p[kt] = __expf(p[kt] - mx); denom += p[kt]; }
            float inv = 1.0f / denom;
            float ov[16];
#pragma unroll
            for (int d = 0; d < 16; d++) ov[d] = 0.f;
#pragma unroll
            for (int kt = 0; kt < 16; kt++) {
                const float* vrow = s_qkv + (rbase + kt) * 288 + 192 + h * HEAD_DIM;
#pragma unroll
                for (int d4 = 0; d4 < 4; d4++) {
                    float4 v4 = *(const float4*)(vrow + d4 * 4);
                    ov[d4*4+0] = fmaf(p[kt], v4.x, ov[d4*4+0]);
                    ov[d4*4+1] = fmaf(p[kt], v4.y, ov[d4*4+1]);
                    ov[d4*4+2] = fmaf(p[kt], v4.z, ov[d4*4+2]);
                    ov[d4*4+3] = fmaf(p[kt], v4.w, ov[d4*4+3]);
                }
            }
            float* orow = s_a + (rbase + qt) * 96 + h * HEAD_DIM;
#pragma unroll
            for (int d = 0; d < 16; d++) orow[d] = ov[d] * inv;
        }
    }
    __syncthreads();

    // 4. out-proj: h = seg + o@out_w + out_b -> s_h (overwrites qkv region)
    gemmM<96, 96, 2>(s_a, out_w, out_b, s_h, xb, w0, tid);
    __syncthreads();

    // 5. LN2: s_h -> s_a
    ln_smem(s_h, s_a, ln2_g, ln2_b, tid);
    __syncthreads();

    // 6. FFN1 + gelu: s_a @ w1 -> s_g
    gemmM<FFN_H, 96, 1>(s_a, ffn_w1, ffn_b1, s_g, nullptr, w0, tid);
    __syncthreads();

    // 7. FFN2: s_g @ w2 added into s_h
    gemmM<96, FFN_H, 3>(s_g, ffn_w2, ffn_b2, s_h, nullptr, w0, tid);
    __syncthreads();

    // 8. final LN: s_h -> s_a
    ln_smem(s_h, s_a, pln_g, pln_b, tid);
    __syncthreads();

    // 9. scatter-add with analytic coverage count
    for (int i = tid; i < MROWS * 96; i += NT) {
        int row = i / 96;
        int d   = i - row * 96;
        int win = w0 + (row >> 4);
        if (win < NUM_WIN) {
            int pos = win * STRIDE + (row & 15);
            float invc = (pos < STRIDE || pos >= L_SEQ - STRIDE) ? 1.0f : 0.5f;
            atomicAdd(out + ((size_t)b * L_SEQ + pos) * 96 + d, s_a[i] * invc);
        }
    }
}

extern "C" void kernel_launch(void* const* d_in, const int* in_sizes, int n_in,
                              void* d_out, int out_size) {
    const float* x      = (const float*)d_in[0];
    const float* ln1_g  = (const float*)d_in[1];
    const float* ln1_b  = (const float*)d_in[2];
    const float* qkv_w  = (const float*)d_in[3];
    const float* qkv_b  = (const float*)d_in[4];
    const float* out_w  = (const float*)d_in[5];
    const float* out_b  = (const float*)d_in[6];
    const float* ln2_g  = (const float*)d_in[7];
    const float* ln2_b  = (const float*)d_in[8];
    const float* ffn_w1 = (const float*)d_in[9];
    const float* ffn_b1 = (const float*)d_in[10];
    const float* ffn_w2 = (const float*)d_in[11];
    const float* ffn_b2 = (const float*)d_in[12];
    const float* pln_g  = (const float*)d_in[13];
    const float* pln_b  = (const float*)d_in[14];
    float* out = (float*)d_out;

    const int B = in_sizes[0] / (L_SEQ * D_MODEL);
    const int nblk = (NUM_WIN + WPC - 1) / WPC;            // 256
    const int smem_bytes = SMEM_FLOATS * sizeof(float);    // 98304

    static int attr_set = 0;
    if (!attr_set) {
        cudaFuncSetAttribute(win_block_kernel,
                             cudaFuncAttributeMaxDynamicSharedMemorySize,
                             smem_bytes);
        attr_set = 1;
    }

    zero_out_kernel<<<(out_size + 511) / 512, 512>>>(out, out_size);

    dim3 grid(nblk, B);
    win_block_kernel<<<grid, NT, smem_bytes>>>(
        x, ln1_g, ln1_b, qkv_w, qkv_b, out_w, out_b,
        ln2_g, ln2_b, ffn_w1, ffn_b1, ffn_w2, ffn_b2,
        pln_g, pln_b, out);
}

// round 4
// speedup vs baseline: 2.3614x; 1.7885x over previous
#include <cuda_runtime.h>
#include <cstdint>

#define WIN       16
#define STRIDE    8
#define NHEAD     6
#define HEAD_DIM  16
#define FFN_H     192
#define L_SEQ     8192
#define NUM_WIN   1023
#define WPC       4
#define MROWS     64          // rows per CTA
#define NT        512         // 16 warps

#define PA        100         // s_a row pitch (pad: (4r+c)%32 distinct)
#define PG        196         // s_g row pitch
#define PWMAX     296         // max staged-W pitch
// smem float offsets
#define OFF_QKV   0                       // 64*288 = 18432 (aliased by s_g 64*196)
#define OFF_A     18432                   // 64*100 = 6400
#define OFF_H     (18432 + 6400)          // 64*96  = 6144
#define OFF_W     (18432 + 6400 + 6144)   // 2*16*296 = 9472
#define SMEM_FLOATS (OFF_W + 2 * 16 * PWMAX)   // 40448 floats = 161792 B

__global__ void zero_out_kernel(float* __restrict__ out, int n) {
    int i = blockIdx.x * blockDim.x + threadIdx.x;
    if (i < n) out[i] = 0.0f;
}

__device__ __forceinline__ float f2tf(float x) {
    float r;
    asm("cvt.rna.tf32.f32 %0, %1;" : "=f"(r) : "f"(x));
    return r;
}

__device__ __forceinline__ float gelu_tanh(float x) {
    float x3 = x * x * x;
    float inner = 0.7978845608028654f * fmaf(0.044715f, x3, x);
    return 0.5f * x * (1.0f + tanhf(inner));
}

__device__ __forceinline__ int row_pos(int w0, int row) {
    int p = (w0 + (row >> 4)) * STRIDE + (row & 15);
    return p < (L_SEQ - 1) ? p : (L_SEQ - 1);
}

__device__ __forceinline__ void mma_tf32(float c[4],
                                         uint32_t a0, uint32_t a1, uint32_t a2, uint32_t a3,
                                         uint32_t b0, uint32_t b1) {
    asm volatile(
        "mma.sync.aligned.m16n8k8.row.col.f32.tf32.tf32.f32 "
        "{%0,%1,%2,%3}, {%4,%5,%6,%7}, {%8,%9}, {%0,%1,%2,%3};"
        : "+f"(c[0]), "+f"(c[1]), "+f"(c[2]), "+f"(c[3])
        : "r"(a0), "r"(a1), "r"(a2), "r"(a3), "r"(b0), "r"(b1));
}

// stage W rows [kb*16, kb*16+16) x N into dst (pitch NP), tf32-rounded
template <int N, int NP>
__device__ __forceinline__ void stageW(const float* __restrict__ Wg,
                                       float* __restrict__ dst, int kb, int tid) {
    const float* src = Wg + (size_t)kb * 16 * N;   // contiguous block
    for (int i4 = tid; i4 < (16 * N) / 4; i4 += NT) {
        int idx = i4 * 4;
        int r = idx / N, cc = idx - r * N;
        float4 v = *(const float4*)(src + idx);
        v.x = f2tf(v.x); v.y = f2tf(v.y); v.z = f2tf(v.z); v.w = f2tf(v.w);
        *(float4*)(dst + r * NP + cc) = v;
    }
}

// C(64xN) = A(64xK smem, tf32-rounded, pitch AP) @ W(KxN gmem) + bias
// EPI 0: fp32 store to C (pitch CP)   1: gelu->tf32 store   2: seg(gmem)+acc -> C   3: C += acc
template <int N, int NP, int K, int EPI>
__device__ __forceinline__ void gemm_mma(const float* __restrict__ A, int AP,
                                         const float* __restrict__ Wg,
                                         const float* __restrict__ bias,
                                         float* __restrict__ C, int CP,
                                         float* __restrict__ s_w,
                                         const float* __restrict__ xb, int w0,
                                         int tid) {
    const int lane  = tid & 31;
    const int wid   = tid >> 5;
    const int strip = wid & 3;          // M strip (16 rows)
    const int nq    = wid >> 2;         // N quarter
    const int g     = lane >> 2;        // 0..7
    const int t     = lane & 3;         // 0..3
    const int NQ    = N / 4;
    const int NTILES = N / 32;          // n8-tiles per quarter

    float c[NTILES][4];
#pragma unroll
    for (int i = 0; i < NTILES; i++) {
        int j = nq * NQ + i * 8 + t * 2;
        float2 bv = *(const float2*)(bias + j);
        c[i][0] = bv.x; c[i][1] = bv.y; c[i][2] = bv.x; c[i][3] = bv.y;
    }

    const int KB = K / 16;
    stageW<N, NP>(Wg, s_w, 0, tid);
    __syncthreads();

    const int r0 = strip * 16 + g;
    for (int kb = 0; kb < KB; kb++) {
        if (kb + 1 < KB)
            stageW<N, NP>(Wg, s_w + ((kb + 1) & 1) * (16 * PWMAX), kb + 1, tid);
        const float* wb = s_w + (kb & 1) * (16 * PWMAX);
#pragma unroll
        for (int k8 = 0; k8 < 2; k8++) {
            const int kc = kb * 16 + k8 * 8;
            uint32_t a0 = __float_as_uint(A[r0 * AP + kc + t]);
            uint32_t a1 = __float_as_uint(A[(r0 + 8) * AP + kc + t]);
            uint32_t a2 = __float_as_uint(A[r0 * AP + kc + t + 4]);
            uint32_t a3 = __float_as_uint(A[(r0 + 8) * AP + kc + t + 4]);
            const float* wk = wb + (k8 * 8) * NP;
#pragma unroll
            for (int i = 0; i < NTILES; i++) {
                int n = nq * NQ + i * 8 + g;
                uint32_t b0 = __float_as_uint(wk[t * NP + n]);
                uint32_t b1 = __float_as_uint(wk[(t + 4) * NP + n]);
                mma_tf32(c[i], a0, a1, a2, a3, b0, b1);
            }
        }
        __syncthreads();
    }

    // epilogue
#pragma unroll
    for (int i = 0; i < NTILES; i++) {
        int j = nq * NQ + i * 8 + t * 2;
        int ra = r0, rb = r0 + 8;
        if (EPI == 0) {
            *(float2*)(C + ra * CP + j) = make_float2(c[i][0], c[i][1]);
            *(float2*)(C + rb * CP + j) = make_float2(c[i][2], c[i][3]);
        } else if (EPI == 1) {
            *(float2*)(C + ra * CP + j) =
                make_float2(f2tf(gelu_tanh(c[i][0])), f2tf(gelu_tanh(c[i][1])));
            *(float2*)(C + rb * CP + j) =
                make_float2(f2tf(gelu_tanh(c[i][2])), f2tf(gelu_tanh(c[i][3])));
        } else if (EPI == 2) {
            float2 sa = *(const float2*)(xb + (size_t)row_pos(w0, ra) * 96 + j);
            float2 sb = *(const float2*)(xb + (size_t)row_pos(w0, rb) * 96 + j);
            *(float2*)(C + ra * CP + j) = make_float2(sa.x + c[i][0], sa.y + c[i][1]);
            *(float2*)(C + rb * CP + j) = make_float2(sb.x + c[i][2], sb.y + c[i][3]);
        } else {
            float2 ca = *(const float2*)(C + ra * CP + j);
            float2 cb = *(const float2*)(C + rb * CP + j);
            *(float2*)(C + ra * CP + j) = make_float2(ca.x + c[i][0], ca.y + c[i][1]);
            *(float2*)(C + rb * CP + j) = make_float2(cb.x + c[i][2], cb.y + c[i][3]);
        }
    }
}

// LayerNorm: 64 rows x 96; 8 threads/row. TF: round output to tf32.
template <int TF>
__device__ __forceinline__ void ln64(const float* __restrict__ src, int sp,
                                     float* __restrict__ dst, int dp,
                                     const float* __restrict__ gg,
                                     const float* __restrict__ bb, int tid) {
    int row = tid >> 3, sub = tid & 7;
    const float* rp = src + (size_t)row * sp + sub * 12;
    float4 v[3];
#pragma unroll
    for (int i = 0; i < 3; i++) v[i] = *(const float4*)(rp + i * 4);
    float s = 0.f;
#pragma unroll
    for (int i = 0; i < 3; i++) s += v[i].x + v[i].y + v[i].z + v[i].w;
    s += __shfl_xor_sync(0xffffffffu, s, 1);
    s += __shfl_xor_sync(0xffffffffu, s, 2);
    s += __shfl_xor_sync(0xffffffffu, s, 4);
    float mean = s * (1.0f / 96.0f);
    float q = 0.f;
#pragma unroll
    for (int i = 0; i < 3; i++) {
        float dx = v[i].x - mean, dy = v[i].y - mean;
        float dz = v[i].z - mean, dw = v[i].w - mean;
        q = fmaf(dx, dx, q); q = fmaf(dy, dy, q);
        q = fmaf(dz, dz, q); q = fmaf(dw, dw, q);
    }
    q += __shfl_xor_sync(0xffffffffu, q, 1);
    q += __shfl_xor_sync(0xffffffffu, q, 2);
    q += __shfl_xor_sync(0xffffffffu, q, 4);
    float rstd = rsqrtf(q * (1.0f / 96.0f) + 1e-5f);
    float* op = dst + row * dp + sub * 12;
#pragma unroll
    for (int i = 0; i < 3; i++) {
        int d = sub * 12 + i * 4;
        float4 gv = *(const float4*)(gg + d);
        float4 bv = *(const float4*)(bb + d);
        float4 o;
        o.x = (v[i].x - mean) * rstd * gv.x + bv.x;
        o.y = (v[i].y - mean) * rstd * gv.y + bv.y;
        o.z = (v[i].z - mean) * rstd * gv.z + bv.z;
        o.w = (v[i].w - mean) * rstd * gv.w + bv.w;
        if (TF) { o.x = f2tf(o.x); o.y = f2tf(o.y); o.z = f2tf(o.z); o.w = f2tf(o.w); }
        *(float4*)(op + i * 4) = o;
    }
}

// LN1 directly from gmem rows
__device__ __forceinline__ void ln64_g(const float* __restrict__ xb, int w0,
                                       float* __restrict__ dst,
                                       const float* __restrict__ gg,
                                       const float* __restrict__ bb, int tid) {
    int row = tid >> 3, sub = tid & 7;
    int p = row_pos(w0, row);
    const float* rp = xb + (size_t)p * 96 + sub * 12;
    float4 v[3];
#pragma unroll
    for (int i = 0; i < 3; i++) v[i] = *(const float4*)(rp + i * 4);
    float s = 0.f;
#pragma unroll
    for (int i = 0; i < 3; i++) s += v[i].x + v[i].y + v[i].z + v[i].w;
    s += __shfl_xor_sync(0xffffffffu, s, 1);
    s += __shfl_xor_sync(0xffffffffu, s, 2);
    s += __shfl_xor_sync(0xffffffffu, s, 4);
    float mean = s * (1.0f / 96.0f);
    float q = 0.f;
#pragma unroll
    for (int i = 0; i < 3; i++) {
        float dx = v[i].x - mean, dy = v[i].y - mean;
        float dz = v[i].z - mean, dw = v[i].w - mean;
        q = fmaf(dx, dx, q); q = fmaf(dy, dy, q);
        q = fmaf(dz, dz, q); q = fmaf(dw, dw, q);
    }
    q += __shfl_xor_sync(0xffffffffu, q, 1);
    q += __shfl_xor_sync(0xffffffffu, q, 2);
    q += __shfl_xor_sync(0xffffffffu, q, 4);
    float rstd = rsqrtf(q * (1.0f / 96.0f) + 1e-5f);
    float* op = dst + row * PA + sub * 12;
#pragma unroll
    for (int i = 0; i < 3; i++) {
        int d = sub * 12 + i * 4;
        float4 gv = *(const float4*)(gg + d);
        float4 bv = *(const float4*)(bb + d);
        float4 o;
        o.x = f2tf((v[i].x - mean) * rstd * gv.x + bv.x);
        o.y = f2tf((v[i].y - mean) * rstd * gv.y + bv.y);
        o.z = f2tf((v[i].z - mean) * rstd * gv.z + bv.z);
        o.w = f2tf((v[i].w - mean) * rstd * gv.w + bv.w);
        *(float4*)(op + i * 4) = o;
    }
}

__global__ void __launch_bounds__(NT, 1)
win_block_kernel(const float* __restrict__ x,
                 const float* __restrict__ ln1_g, const float* __restrict__ ln1_b,
                 const float* __restrict__ qkv_w, const float* __restrict__ qkv_b,
                 const float* __restrict__ out_w, const float* __restrict__ out_b,
                 const float* __restrict__ ln2_g, const float* __restrict__ ln2_b,
                 const float* __restrict__ ffn_w1, const float* __restrict__ ffn_b1,
                 const float* __restrict__ ffn_w2, const float* __restrict__ ffn_b2,
                 const float* __restrict__ pln_g, const float* __restrict__ pln_b,
                 float* __restrict__ out) {
    extern __shared__ float sm[];
    float* s_qkv = sm + OFF_QKV;   // 64 x 288 fp32
    float* s_g   = sm + OFF_QKV;   // alias: 64 x 196 (after attention)
    float* s_a   = sm + OFF_A;     // 64 x 100 (tf32-rounded operand buffer)
    float* s_h   = sm + OFF_H;     // 64 x 96 fp32 residual
    float* s_w   = sm + OFF_W;     // 2 x 16 x 296 staged weights

    const int tid = threadIdx.x;
    const int w0  = blockIdx.x * WPC;
    const int b   = blockIdx.y;
    const float* xb = x + (size_t)b * L_SEQ * 96;

    // 1. LN1 (gmem -> s_a, tf32)
    ln64_g(xb, w0, s_a, ln1_g, ln1_b, tid);
    __syncthreads();

    // 2. qkv GEMM -> s_qkv (fp32)
    gemm_mma<288, PWMAX, 96, 0>(s_a, PA, qkv_w, qkv_b, s_qkv, 288, s_w, xb, w0, tid);
    __syncthreads();

    // 3. attention: 384 tasks (4 win x 6 heads x 16 q); out -> s_a (tf32)
    if (tid < WPC * 96) {
        const int wi  = tid / 96;
        const int rem = tid % 96;
        const int h   = rem >> 4;
        const int qt  = rem & 15;
        const int rbase = wi * 16;
        const float* qrow = s_qkv + (rbase + qt) * 288 + h * HEAD_DIM;
        float qv[16];
#pragma unroll
        for (int d4 = 0; d4 < 4; d4++) {
            float4 t4 = *(const float4*)(qrow + d4 * 4);
            qv[d4*4+0]=t4.x; qv[d4*4+1]=t4.y; qv[d4*4+2]=t4.z; qv[d4*4+3]=t4.w;
        }
        float p[16];
        float mx = -1e30f;
#pragma unroll
        for (int kt = 0; kt < 16; kt++) {
            const float* krow = s_qkv + (rbase + kt) * 288 + 96 + h * HEAD_DIM;
            float sd = 0.f;
#pragma unroll
            for (int d4 = 0; d4 < 4; d4++) {
                float4 k4 = *(const float4*)(krow + d4 * 4);
                sd = fmaf(qv[d4*4+0], k4.x, sd);
                sd = fmaf(qv[d4*4+1], k4.y, sd);
                sd = fmaf(qv[d4*4+2], k4.z, sd);
                sd = fmaf(qv[d4*4+3], k4.w, sd);
            }
            sd *= 0.25f;
            p[kt] = (kt <= qt) ? sd : -1e30f;
            mx = fmaxf(mx, p[kt]);
        }
        float denom = 0.f;
#pragma unroll
        for (int kt = 0; kt < 16; kt++) { p[kt] = __expf(p[kt] - mx); denom += p[kt]; }
        float inv = 1.0f / denom;
        float ov[16];
#pragma unroll
        for (int d = 0; d < 16; d++) ov[d] = 0.f;
#pragma unroll
        for (int kt = 0; kt < 16; kt++) {
            const float* vrow = s_qkv + (rbase + kt) * 288 + 192 + h * HEAD_DIM;
#pragma unroll
            for (int d4 = 0; d4 < 4; d4++) {
                float4 v4 = *(const float4*)(vrow + d4 * 4);
                ov[d4*4+0] = fmaf(p[kt], v4.x, ov[d4*4+0]);
                ov[d4*4+1] = fmaf(p[kt], v4.y, ov[d4*4+1]);
                ov[d4*4+2] = fmaf(p[kt], v4.z, ov[d4*4+2]);
                ov[d4*4+3] = fmaf(p[kt], v4.w, ov[d4*4+3]);
            }
        }
        float* orow = s_a + (rbase + qt) * PA + h * HEAD_DIM;
#pragma unroll
        for (int d4 = 0; d4 < 4; d4++) {
            float4 o;
            o.x = f2tf(ov[d4*4+0] * inv); o.y = f2tf(ov[d4*4+1] * inv);
            o.z = f2tf(ov[d4*4+2] * inv); o.w = f2tf(ov[d4*4+3] * inv);
            *(float4*)(orow + d4 * 4) = o;
        }
    }
    __syncthreads();

    // 4. oproj: s_h = seg + s_a @ out_w + out_b   (overwrites qkv region? no: s_h separate)
    gemm_mma<96, 104, 96, 2>(s_a, PA, out_w, out_b, s_h, 96, s_w, xb, w0, tid);
    __syncthreads();

    // 5. LN2: s_h -> s_a (tf32)
    ln64<1>(s_h, 96, s_a, PA, ln2_g, ln2_b, tid);
    __syncthreads();

    // 6. FFN1 + gelu: s_a @ w1 -> s_g (tf32) — overwrites qkv region (dead)
    gemm_mma<192, 200, 96, 1>(s_a, PA, ffn_w1, ffn_b1, s_g, PG, s_w, xb, w0, tid);
    __syncthreads();

    // 7. FFN2: s_h += s_g @ w2
    gemm_mma<96, 104, 192, 3>(s_g, PG, ffn_w2, ffn_b2, s_h, 96, s_w, xb, w0, tid);
    __syncthreads();

    // 8. final LN: s_h -> s_a (fp32, no rounding)
    ln64<0>(s_h, 96, s_a, PA, pln_g, pln_b, tid);
    __syncthreads();

    // 9. scatter-add with analytic coverage count
    for (int i = tid; i < MROWS * 96; i += NT) {
        int row = i / 96;
        int d   = i - row * 96;
        int win = w0 + (row >> 4);
        if (win < NUM_WIN) {
            int pos = win * STRIDE + (row & 15);
            float invc = (pos < STRIDE || pos >= L_SEQ - STRIDE) ? 1.0f : 0.5f;
            atomicAdd(out + ((size_t)b * L_SEQ + pos) * 96 + d,
                      s_a[row * PA + d] * invc);
        }
    }
}

extern "C" void kernel_launch(void* const* d_in, const int* in_sizes, int n_in,
                              void* d_out, int out_size) {
    const float* x      = (const float*)d_in[0];
    const float* ln1_g  = (const float*)d_in[1];
    const float* ln1_b  = (const float*)d_in[2];
    const float* qkv_w  = (const float*)d_in[3];
    const float* qkv_b  = (const float*)d_in[4];
    const float* out_w  = (const float*)d_in[5];
    const float* out_b  = (const float*)d_in[6];
    const float* ln2_g  = (const float*)d_in[7];
    const float* ln2_b  = (const float*)d_in[8];
    const float* ffn_w1 = (const float*)d_in[9];
    const float* ffn_b1 = (const float*)d_in[10];
    const float* ffn_w2 = (const float*)d_in[11];
    const float* ffn_b2 = (const float*)d_in[12];
    const float* pln_g  = (const float*)d_in[13];
    const float* pln_b  = (const float*)d_in[14];
    float* out = (float*)d_out;

    const int B = in_sizes[0] / (L_SEQ * 96);
    const int nblk = (NUM_WIN + WPC - 1) / WPC;            // 256
    const int smem_bytes = SMEM_FLOATS * sizeof(float);    // 161792

    static int attr_set = 0;
    if (!attr_set) {
        cudaFuncSetAttribute(win_block_kernel,
                             cudaFuncAttributeMaxDynamicSharedMemorySize,
                             smem_bytes);
        attr_set = 1;
    }

    zero_out_kernel<<<(out_size + 511) / 512, 512>>>(out, out_size);

    dim3 grid(nblk, B);
    win_block_kernel<<<grid, NT, smem_bytes>>>(
        x, ln1_g, ln1_b, qkv_w, qkv_b, out_w, out_b,
        ln2_g, ln2_b, ffn_w1, ffn_b1, ffn_w2, ffn_b2,
        pln_g, pln_b, out);
}

// round 5
// speedup vs baseline: 4.0643x; 1.7211x over previous
#include <cuda_runtime.h>
#include <cuda_fp16.h>
#include <cstdint>

#define WIN       16
#define STRIDE    8
#define NHEAD     6
#define HEAD_DIM  16
#define FFN_H     192
#define L_SEQ     8192
#define NUM_WIN   1023
#define WPC       4
#define MROWS     64
#define NT        512

// half pitches (ldmatrix conflict-free: pitch*2B mod 128 = 80/80/16 -> 8 distinct rows)
#define PAH       104        // s_a operand pitch (halves)
#define PGH       200        // s_g operand pitch (halves)
// smem byte offsets
#define OFF_QKV   0                    // 64*288 fp32 = 73728 (aliased later by s_g half / s_fin fp32)
#define OFF_A     73728                // 64*104 half = 13312
#define OFF_H     87040                // 64*96 fp32  = 24576
#define OFF_WA    111616               // 96*296 half = 56832
#define OFF_WB    168448               // 192*104 half = 39936
#define SMEM_BYTES 208384

// ---- pre-converted fp16 weights ----
__device__ __align__(16) __half g_wq[96 * 288];
__device__ __align__(16) __half g_wo[96 * 96];
__device__ __align__(16) __half g_w1[96 * 192];
__device__ __align__(16) __half g_w2[192 * 96];

__global__ void convert_w_kernel(const float* __restrict__ qkv_w,
                                 const float* __restrict__ out_w,
                                 const float* __restrict__ w1,
                                 const float* __restrict__ w2) {
    int i = blockIdx.x * blockDim.x + threadIdx.x;
    if (i < 96 * 288) g_wq[i] = __float2half_rn(qkv_w[i]);
    if (i < 96 * 96)  g_wo[i] = __float2half_rn(out_w[i]);
    if (i < 96 * 192) g_w1[i] = __float2half_rn(w1[i]);
    if (i < 192 * 96) g_w2[i] = __float2half_rn(w2[i]);
}

__global__ void zero_out_kernel(float* __restrict__ out, int n) {
    int i = blockIdx.x * blockDim.x + threadIdx.x;
    if (i < n) out[i] = 0.0f;
}

// ---- PTX wrappers ----
__device__ __forceinline__ uint32_t smem_u32(const void* p) {
    return (uint32_t)__cvta_generic_to_shared(p);
}
__device__ __forceinline__ void ldsm_x4(uint32_t& r0, uint32_t& r1, uint32_t& r2, uint32_t& r3, uint32_t a) {
    asm volatile("ldmatrix.sync.aligned.m8n8.x4.shared.b16 {%0,%1,%2,%3}, [%4];"
                 : "=r"(r0), "=r"(r1), "=r"(r2), "=r"(r3) : "r"(a));
}
__device__ __forceinline__ void ldsm_x4_t(uint32_t& r0, uint32_t& r1, uint32_t& r2, uint32_t& r3, uint32_t a) {
    asm volatile("ldmatrix.sync.aligned.m8n8.x4.trans.shared.b16 {%0,%1,%2,%3}, [%4];"
                 : "=r"(r0), "=r"(r1), "=r"(r2), "=r"(r3) : "r"(a));
}
__device__ __forceinline__ void ldsm_x2_t(uint32_t& r0, uint32_t& r1, uint32_t a) {
    asm volatile("ldmatrix.sync.aligned.m8n8.x2.trans.shared.b16 {%0,%1}, [%2];"
                 : "=r"(r0), "=r"(r1) : "r"(a));
}
__device__ __forceinline__ void mma16816(float c[4], uint32_t a0, uint32_t a1, uint32_t a2, uint32_t a3,
                                         uint32_t b0, uint32_t b1) {
    asm volatile("mma.sync.aligned.m16n8k16.row.col.f32.f16.f16.f32 "
                 "{%0,%1,%2,%3}, {%4,%5,%6,%7}, {%8,%9}, {%0,%1,%2,%3};"
                 : "+f"(c[0]), "+f"(c[1]), "+f"(c[2]), "+f"(c[3])
                 : "r"(a0), "r"(a1), "r"(a2), "r"(a3), "r"(b0), "r"(b1));
}
__device__ __forceinline__ void cp_wait0() {
    asm volatile("cp.async.wait_group 0;" ::: "memory");
}

// stage full K x N half weight block into smem (pitch PWh halves) via cp.async
template <int N, int PWh, int K>
__device__ __forceinline__ void stage_full(const __half* __restrict__ Wg, uint32_t dst, int tid) {
    const int CH = N / 8;            // 16B chunks per row
    for (int c = tid; c < K * CH; c += NT) {
        int r = c / CH, col = (c - r * CH) * 8;
        const __half* src = Wg + (size_t)r * N + col;
        uint32_t d = dst + (uint32_t)(r * PWh + col) * 2;
        asm volatile("cp.async.cg.shared.global [%0], [%1], 16;" :: "r"(d), "l"(src));
    }
    asm volatile("cp.async.commit_group;" ::: "memory");
}

__device__ __forceinline__ float gelu_tanh(float x) {
    float x3 = x * x * x;
    float inner = 0.7978845608028654f * fmaf(0.044715f, x3, x);
    return 0.5f * x * (1.0f + tanhf(inner));
}
__device__ __forceinline__ int row_pos(int w0, int row) {
    int p = (w0 + (row >> 4)) * STRIDE + (row & 15);
    return p < (L_SEQ - 1) ? p : (L_SEQ - 1);
}

// ---- fp16 tensor-core GEMM: C(64xN) = A(64xK half smem) @ W(KxN half smem) + bias ----
// EPI 0: fp32 store to Cf(CPf)   1: gelu -> half store to Ch(PGH)
// EPI 2: Cf = seg(gmem)+acc      3: Cf += acc
template <int N, int PWh, int K, int EPI>
__device__ __forceinline__ void gemm_h(uint32_t aU32, int PAh, uint32_t wU32,
                                       const float* __restrict__ bias,
                                       float* __restrict__ Cf, int CPf,
                                       __half* __restrict__ Ch,
                                       const float* __restrict__ xb, int w0, int tid) {
    const int lane = tid & 31, wid = tid >> 5;
    const int strip = wid & 3;                 // 16-row M strip
    const int nq = wid >> 2;                   // N quarter
    const int g = lane >> 2, t = lane & 3;
    const int NQ = N / 4;
    const int NTILES = NQ / 8;

    float c[NTILES][4];
#pragma unroll
    for (int i = 0; i < NTILES; i++) {
        int j = nq * NQ + i * 8 + t * 2;
        float2 bv = *(const float2*)(bias + j);
        c[i][0] = bv.x; c[i][1] = bv.y; c[i][2] = bv.x; c[i][3] = bv.y;
    }

    // ldmatrix lane addresses
    const int l15 = lane & 15;
    const int hi8 = (lane >= 16) ? 8 : 0;
    uint32_t aOff = aU32 + (uint32_t)((strip * 16 + l15) * PAh + hi8) * 2;
    uint32_t bOff = wU32 + (uint32_t)(l15 * PWh + nq * NQ + hi8) * 2;

#pragma unroll
    for (int k16 = 0; k16 < K / 16; k16++) {
        uint32_t a0, a1, a2, a3;
        ldsm_x4(a0, a1, a2, a3, aOff + k16 * 32);
        uint32_t bb = bOff + (uint32_t)(k16 * 16 * PWh) * 2;
#pragma unroll
        for (int p = 0; p < NTILES / 2; p++) {
            uint32_t b0, b1, b2, b3;
            ldsm_x4_t(b0, b1, b2, b3, bb + p * 32);
            mma16816(c[2 * p], a0, a1, a2, a3, b0, b1);
            mma16816(c[2 * p + 1], a0, a1, a2, a3, b2, b3);
        }
        if (NTILES & 1) {
            uint32_t b0, b1;
            ldsm_x2_t(b0, b1, bb + (NTILES / 2) * 32);
            mma16816(c[NTILES - 1], a0, a1, a2, a3, b0, b1);
        }
    }

    const int ra = strip * 16 + g, rb = ra + 8;
#pragma unroll
    for (int i = 0; i < NTILES; i++) {
        int j = nq * NQ + i * 8 + t * 2;
        if (EPI == 0) {
            *(float2*)(Cf + ra * CPf + j) = make_float2(c[i][0], c[i][1]);
            *(float2*)(Cf + rb * CPf + j) = make_float2(c[i][2], c[i][3]);
        } else if (EPI == 1) {
            *(__half2*)(Ch + ra * PGH + j) = __floats2half2_rn(gelu_tanh(c[i][0]), gelu_tanh(c[i][1]));
            *(__half2*)(Ch + rb * PGH + j) = __floats2half2_rn(gelu_tanh(c[i][2]), gelu_tanh(c[i][3]));
        } else if (EPI == 2) {
            float2 sa = *(const float2*)(xb + (size_t)row_pos(w0, ra) * 96 + j);
            float2 sb = *(const float2*)(xb + (size_t)row_pos(w0, rb) * 96 + j);
            *(float2*)(Cf + ra * CPf + j) = make_float2(sa.x + c[i][0], sa.y + c[i][1]);
            *(float2*)(Cf + rb * CPf + j) = make_float2(sb.x + c[i][2], sb.y + c[i][3]);
        } else {
            float2 ca = *(const float2*)(Cf + ra * CPf + j);
            float2 cb = *(const float2*)(Cf + rb * CPf + j);
            *(float2*)(Cf + ra * CPf + j) = make_float2(ca.x + c[i][0], ca.y + c[i][1]);
            *(float2*)(Cf + rb * CPf + j) = make_float2(cb.x + c[i][2], cb.y + c[i][3]);
        }
    }
}

// ---- LayerNorm 64x96, 8 threads/row. OUT: 0 = half to dst_h (pitch PAH), 1 = fp32 to dst_f (pitch 96)
template <int OUT, int SRC>   // SRC: 0 = smem fp32 pitch 96, 1 = gmem rows via row_pos
__device__ __forceinline__ void ln64(const float* __restrict__ src, const float* __restrict__ xb, int w0,
                                     __half* __restrict__ dst_h, float* __restrict__ dst_f,
                                     const float* __restrict__ gg, const float* __restrict__ bb, int tid) {
    int row = tid >> 3, sub = tid & 7;
    const float* rp;
    if (SRC == 0) rp = src + row * 96 + sub * 12;
    else          rp = xb + (size_t)row_pos(w0, row) * 96 + sub * 12;
    float4 v[3];
#pragma unroll
    for (int i = 0; i < 3; i++) v[i] = *(const float4*)(rp + i * 4);
    float s = 0.f;
#pragma unroll
    for (int i = 0; i < 3; i++) s += v[i].x + v[i].y + v[i].z + v[i].w;
    s += __shfl_xor_sync(0xffffffffu, s, 1);
    s += __shfl_xor_sync(0xffffffffu, s, 2);
    s += __shfl_xor_sync(0xffffffffu, s, 4);
    float mean = s * (1.0f / 96.0f);
    float q = 0.f;
#pragma unroll
    for (int i = 0; i < 3; i++) {
        float dx = v[i].x - mean, dy = v[i].y - mean;
        float dz = v[i].z - mean, dw = v[i].w - mean;
        q = fmaf(dx, dx, q); q = fmaf(dy, dy, q);
        q = fmaf(dz, dz, q); q = fmaf(dw, dw, q);
    }
    q += __shfl_xor_sync(0xffffffffu, q, 1);
    q += __shfl_xor_sync(0xffffffffu, q, 2);
    q += __shfl_xor_sync(0xffffffffu, q, 4);
    float rstd = rsqrtf(q * (1.0f / 96.0f) + 1e-5f);
#pragma unroll
    for (int i = 0; i < 3; i++) {
        int d = sub * 12 + i * 4;
        float4 gv = *(const float4*)(gg + d);
        float4 bv = *(const float4*)(bb + d);
        float ox = (v[i].x - mean) * rstd * gv.x + bv.x;
        float oy = (v[i].y - mean) * rstd * gv.y + bv.y;
        float oz = (v[i].z - mean) * rstd * gv.z + bv.z;
        float ow = (v[i].w - mean) * rstd * gv.w + bv.w;
        if (OUT == 0) {
            *(__half2*)(dst_h + row * PAH + d)     = __floats2half2_rn(ox, oy);
            *(__half2*)(dst_h + row * PAH + d + 2) = __floats2half2_rn(oz, ow);
        } else {
            *(float4*)(dst_f + row * 96 + d) = make_float4(ox, oy, oz, ow);
        }
    }
}

__global__ void __launch_bounds__(NT, 1)
win_block_kernel(const float* __restrict__ x,
                 const float* __restrict__ ln1_g, const float* __restrict__ ln1_b,
                 const float* __restrict__ qkv_b,
                 const float* __restrict__ out_b,
                 const float* __restrict__ ln2_g, const float* __restrict__ ln2_b,
                 const float* __restrict__ ffn_b1, const float* __restrict__ ffn_b2,
                 const float* __restrict__ pln_g, const float* __restrict__ pln_b,
                 float* __restrict__ out) {
    extern __shared__ char sm[];
    float*  s_qkv = (float*)(sm + OFF_QKV);   // 64 x 288 fp32
    __half* s_a   = (__half*)(sm + OFF_A);    // 64 x PAH half (GEMM A operand)
    float*  s_h   = (float*)(sm + OFF_H);     // 64 x 96 fp32 residual
    __half* s_g   = (__half*)(sm + OFF_QKV);  // alias: 64 x PGH half (gelu out)
    float*  s_fin = (float*)(sm + OFF_QKV);   // alias: 64 x 96 fp32 final LN

    const uint32_t uA  = smem_u32(s_a);
    const uint32_t uG  = smem_u32(s_g);
    const uint32_t uWA = smem_u32(sm + OFF_WA);
    const uint32_t uWB = smem_u32(sm + OFF_WB);

    const int tid = threadIdx.x;
    const int w0  = blockIdx.x * WPC;
    const int b   = blockIdx.y;
    const float* xb = x + (size_t)b * L_SEQ * 96;

    // S1: qkv weights -> bufA (overlaps LN1)
    stage_full<288, 296, 96>(g_wq, uWA, tid);

    // LN1: gmem -> s_a (half)
    ln64<0, 1>(nullptr, xb, w0, s_a, nullptr, ln1_g, ln1_b, tid);

    cp_wait0(); __syncthreads();

    // S2: oproj weights -> bufB (overlaps G1 + attention)
    stage_full<96, 104, 96>(g_wo, uWB, tid);

    // G1: qkv = A @ Wq -> s_qkv fp32
    gemm_h<288, 296, 96, 0>(uA, PAH, uWA, qkv_b, s_qkv, 288, nullptr, xb, w0, tid);
    __syncthreads();

    // attention: 384 tasks (4 win x 6 heads x 16 q) -> s_a (half)
    if (tid < WPC * 96) {
        const int wi  = tid / 96;
        const int rem = tid % 96;
        const int h   = rem >> 4;
        const int qt  = rem & 15;
        const int rbase = wi * 16;
        const float* qrow = s_qkv + (rbase + qt) * 288 + h * HEAD_DIM;
        float qv[16];
#pragma unroll
        for (int d4 = 0; d4 < 4; d4++) {
            float4 t4 = *(const float4*)(qrow + d4 * 4);
            qv[d4*4+0]=t4.x; qv[d4*4+1]=t4.y; qv[d4*4+2]=t4.z; qv[d4*4+3]=t4.w;
        }
        float p[16];
        float mx = -1e30f;
#pragma unroll
        for (int kt = 0; kt < 16; kt++) {
            const float* krow = s_qkv + (rbase + kt) * 288 + 96 + h * HEAD_DIM;
            float sd = 0.f;
#pragma unroll
            for (int d4 = 0; d4 < 4; d4++) {
                float4 k4 = *(const float4*)(krow + d4 * 4);
                sd = fmaf(qv[d4*4+0], k4.x, sd);
                sd = fmaf(qv[d4*4+1], k4.y, sd);
                sd = fmaf(qv[d4*4+2], k4.z, sd);
                sd = fmaf(qv[d4*4+3], k4.w, sd);
            }
            sd *= 0.25f;
            p[kt] = (kt <= qt) ? sd : -1e30f;
            mx = fmaxf(mx, p[kt]);
        }
        float denom = 0.f;
#pragma unroll
        for (int kt = 0; kt < 16; kt++) { p[kt] = __expf(p[kt] - mx); denom += p[kt]; }
        float inv = 1.0f / denom;
        float ov[16];
#pragma unroll
        for (int d = 0; d < 16; d++) ov[d] = 0.f;
#pragma unroll
        for (int kt = 0; kt < 16; kt++) {
            const float* vrow = s_qkv + (rbase + kt) * 288 + 192 + h * HEAD_DIM;
#pragma unroll
            for (int d4 = 0; d4 < 4; d4++) {
                float4 v4 = *(const float4*)(vrow + d4 * 4);
                ov[d4*4+0] = fmaf(p[kt], v4.x, ov[d4*4+0]);
                ov[d4*4+1] = fmaf(p[kt], v4.y, ov[d4*4+1]);
                ov[d4*4+2] = fmaf(p[kt], v4.z, ov[d4*4+2]);
                ov[d4*4+3] = fmaf(p[kt], v4.w, ov[d4*4+3]);
            }
        }
        __half* orow = s_a + (rbase + qt) * PAH + h * HEAD_DIM;
#pragma unroll
        for (int d2 = 0; d2 < 8; d2++)
            *(__half2*)(orow + d2 * 2) = __floats2half2_rn(ov[d2*2] * inv, ov[d2*2+1] * inv);
    }

    cp_wait0(); __syncthreads();

    // S3: ffn1 weights -> bufA (overlaps G2 + LN2)
    stage_full<192, 200, 96>(g_w1, uWA, tid);

    // G2: s_h = seg + attnout @ Wo + bo
    gemm_h<96, 104, 96, 2>(uA, PAH, uWB, out_b, s_h, 96, nullptr, xb, w0, tid);
    __syncthreads();

    // LN2: s_h -> s_a (half)
    ln64<0, 0>(s_h, nullptr, 0, s_a, nullptr, ln2_g, ln2_b, tid);

    cp_wait0(); __syncthreads();

    // S4: ffn2 weights -> bufB (overlaps G3)
    stage_full<96, 104, 192>(g_w2, uWB, tid);

    // G3: gelu(s_a @ W1 + b1) -> s_g (half)  [overwrites dead qkv region]
    gemm_h<192, 200, 96, 1>(uA, PAH, uWA, ffn_b1, nullptr, 0, s_g, xb, w0, tid);

    cp_wait0(); __syncthreads();

    // G4: s_h += s_g @ W2 + b2
    gemm_h<96, 104, 192, 3>(uG, PGH, uWB, ffn_b2, s_h, 96, nullptr, xb, w0, tid);
    __syncthreads();

    // final LN: s_h -> s_fin fp32
    ln64<1, 0>(s_h, nullptr, 0, nullptr, s_fin, pln_g, pln_b, tid);
    __syncthreads();

    // scatter-add with analytic coverage count
    for (int i = tid; i < MROWS * 96; i += NT) {
        int row = i / 96;
        int d   = i - row * 96;
        int win = w0 + (row >> 4);
        if (win < NUM_WIN) {
            int pos = win * STRIDE + (row & 15);
            float invc = (pos < STRIDE || pos >= L_SEQ - STRIDE) ? 1.0f : 0.5f;
            atomicAdd(out + ((size_t)b * L_SEQ + pos) * 96 + d, s_fin[row * 96 + d] * invc);
        }
    }
}

extern "C" void kernel_launch(void* const* d_in, const int* in_sizes, int n_in,
                              void* d_out, int out_size) {
    const float* x      = (const float*)d_in[0];
    const float* ln1_g  = (const float*)d_in[1];
    const float* ln1_b  = (const float*)d_in[2];
    const float* qkv_w  = (const float*)d_in[3];
    const float* qkv_b  = (const float*)d_in[4];
    const float* out_w  = (const float*)d_in[5];
    const float* out_b  = (const float*)d_in[6];
    const float* ln2_g  = (const float*)d_in[7];
    const float* ln2_b  = (const float*)d_in[8];
    const float* ffn_w1 = (const float*)d_in[9];
    const float* ffn_b1 = (const float*)d_in[10];
    const float* ffn_w2 = (const float*)d_in[11];
    const float* ffn_b2 = (const float*)d_in[12];
    const float* pln_g  = (const float*)d_in[13];
    const float* pln_b  = (const float*)d_in[14];
    float* out = (float*)d_out;

    const int B = in_sizes[0] / (L_SEQ * 96);
    const int nblk = (NUM_WIN + WPC - 1) / WPC;   // 256

    static int attr_set = 0;
    if (!attr_set) {
        cudaFuncSetAttribute(win_block_kernel,
                             cudaFuncAttributeMaxDynamicSharedMemorySize, SMEM_BYTES);
        attr_set = 1;
    }

    convert_w_kernel<<<(96 * 288 + 511) / 512, 512>>>(qkv_w, out_w, ffn_w1, ffn_w2);
    zero_out_kernel<<<(out_size + 511) / 512, 512>>>(out, out_size);

    dim3 grid(nblk, B);
    win_block_kernel<<<grid, NT, SMEM_BYTES>>>(
        x, ln1_g, ln1_b, qkv_b, out_b, ln2_g, ln2_b,
        ffn_b1, ffn_b2, pln_g, pln_b, out);
}

// round 7
// speedup vs baseline: 4.6882x; 1.1535x over previous
#include <cuda_runtime.h>
#include <cuda_fp16.h>
#include <cstdint>

#define WIN       16
#define STRIDE    8
#define NHEAD     6
#define FFN_H     192
#define L_SEQ     8192
#define NUM_WIN   1023
#define WPC       4
#define MROWS     64
#define NT        512

#define PQH       288        // s_qkv pitch (halves)
#define PAH       104        // s_a pitch (halves) — ldsm conflict-free (13r mod 8 distinct)
#define PGH       200        // s_g pitch (halves) — (25r mod 8 distinct)
#define PW        104        // weight chunk pitch (halves)

// smem byte offsets
#define OFF_QKV   0                       // 64*288*2 = 36864 (aliased by s_g half / s_fin fp32)
#define OFF_A     36864                   // 64*104*2 = 13312
#define OFF_H     50176                   // 64*96*4  = 24576
#define OFF_W0    74752                   // 96*104*2 = 19968
#define OFF_W1    94720                   // 96*104*2 = 19968
#define SMEM_BYTES 114688

// ---- pre-converted fp16 weights ----
__device__ __align__(16) __half g_wq[96 * 288];
__device__ __align__(16) __half g_wo[96 * 96];
__device__ __align__(16) __half g_w1[96 * 192];
__device__ __align__(16) __half g_w2[192 * 96];

__global__ void convert_w_kernel(const float* __restrict__ qkv_w,
                                 const float* __restrict__ out_w,
                                 const float* __restrict__ w1,
                                 const float* __restrict__ w2) {
    int i = blockIdx.x * blockDim.x + threadIdx.x;
    if (i < 96 * 288) g_wq[i] = __float2half_rn(qkv_w[i]);
    if (i < 96 * 96)  g_wo[i] = __float2half_rn(out_w[i]);
    if (i < 96 * 192) g_w1[i] = __float2half_rn(w1[i]);
    if (i < 192 * 96) g_w2[i] = __float2half_rn(w2[i]);
}

__global__ void zero_out_kernel(float* __restrict__ out, int n) {
    int i = blockIdx.x * blockDim.x + threadIdx.x;
    if (i < n) out[i] = 0.0f;
}

// ---- PTX wrappers ----
__device__ __forceinline__ uint32_t smem_u32(const void* p) {
    return (uint32_t)__cvta_generic_to_shared(p);
}
__device__ __forceinline__ void ldsm_x4(uint32_t& r0, uint32_t& r1, uint32_t& r2, uint32_t& r3, uint32_t a) {
    asm volatile("ldmatrix.sync.aligned.m8n8.x4.shared.b16 {%0,%1,%2,%3}, [%4];"
                 : "=r"(r0), "=r"(r1), "=r"(r2), "=r"(r3) : "r"(a));
}
__device__ __forceinline__ void ldsm_x4_t(uint32_t& r0, uint32_t& r1, uint32_t& r2, uint32_t& r3, uint32_t a) {
    asm volatile("ldmatrix.sync.aligned.m8n8.x4.trans.shared.b16 {%0,%1,%2,%3}, [%4];"
                 : "=r"(r0), "=r"(r1), "=r"(r2), "=r"(r3) : "r"(a));
}
__device__ __forceinline__ void ldsm_x2_t(uint32_t& r0, uint32_t& r1, uint32_t a) {
    asm volatile("ldmatrix.sync.aligned.m8n8.x2.trans.shared.b16 {%0,%1}, [%2];"
                 : "=r"(r0), "=r"(r1) : "r"(a));
}
__device__ __forceinline__ void mma16816(float c[4], uint32_t a0, uint32_t a1, uint32_t a2, uint32_t a3,
                                         uint32_t b0, uint32_t b1) {
    asm volatile("mma.sync.aligned.m16n8k16.row.col.f32.f16.f16.f32 "
                 "{%0,%1,%2,%3}, {%4,%5,%6,%7}, {%8,%9}, {%0,%1,%2,%3};"
                 : "+f"(c[0]), "+f"(c[1]), "+f"(c[2]), "+f"(c[3])
                 : "r"(a0), "r"(a1), "r"(a2), "r"(a3), "r"(b0), "r"(b1));
}
#define CP_COMMIT() asm volatile("cp.async.commit_group;" ::: "memory")
#define CP_WAIT(n)  asm volatile("cp.async.wait_group %0;" :: "n"(n) : "memory")

// stage a 96x96 half block (src row-stride ldN) into smem chunk buffer (pitch PW)
__device__ __forceinline__ void stage96(const __half* __restrict__ src, int ldN,
                                        uint32_t dst, int tid) {
    for (int c = tid; c < 96 * 12; c += NT) {
        int r = c / 12, k = (c - r * 12) * 8;
        uint32_t d = dst + (uint32_t)(r * PW + k) * 2;
        asm volatile("cp.async.cg.shared.global [%0], [%1], 16;"
                     :: "r"(d), "l"(src + (size_t)r * ldN + k));
    }
    CP_COMMIT();
}

__device__ __forceinline__ float gelu_tanh(float x) {
    float x3 = x * x * x;
    float inner = 0.7978845608028654f * fmaf(0.044715f, x3, x);
    return 0.5f * x * (1.0f + tanhf(inner));
}
__device__ __forceinline__ int row_pos(int w0, int row) {
    int p = (w0 + (row >> 4)) * STRIDE + (row & 15);
    return p < (L_SEQ - 1) ? p : (L_SEQ - 1);
}

// ---- C(64x96) += A(64x(96*KC) half smem) @ W  (W staged as KC 96x96 chunks) ----
// EPI 0: half store to Ch   1: gelu->half store to Ch   2: Cf = seg(gmem)+acc   3: Cf += acc
template <int KC, int EPI>
__device__ __forceinline__ void gemm96(uint32_t aBase, int aPitchH,
                                       uint32_t bBase0, uint32_t bBase1,
                                       const float* __restrict__ bias,
                                       __half* __restrict__ Ch, int CPh,
                                       float* __restrict__ Cf,
                                       const float* __restrict__ xb, int w0, int tid) {
    const int lane = tid & 31, wid = tid >> 5;
    const int strip = wid & 3;            // 16-row M strip
    const int nq = wid >> 2;              // 24-col N quarter
    const int g = lane >> 2, t = lane & 3;
    const int l15 = lane & 15;
    const int hi8 = (lane >= 16) ? 8 : 0;

    float c[3][4];
#pragma unroll
    for (int i = 0; i < 3; i++) {
        float2 bv = *(const float2*)(bias + nq * 24 + i * 8 + t * 2);
        c[i][0] = bv.x; c[i][1] = bv.y; c[i][2] = bv.x; c[i][3] = bv.y;
    }

    const uint32_t aOff = aBase + (uint32_t)((strip * 16 + l15) * aPitchH + hi8) * 2;
    const uint32_t bLane = (uint32_t)(l15 * PW + nq * 24 + hi8) * 2;

#pragma unroll
    for (int kc = 0; kc < KC; kc++) {
        uint32_t aO = aOff + kc * 96 * 2;
        uint32_t bO = (kc == 0 ? bBase0 : bBase1) + bLane;
#pragma unroll
        for (int k16 = 0; k16 < 6; k16++) {
            uint32_t a0, a1, a2, a3;
            ldsm_x4(a0, a1, a2, a3, aO + k16 * 32);
            uint32_t bb = bO + (uint32_t)(k16 * 16 * PW) * 2;
            uint32_t b0, b1, b2, b3;
            ldsm_x4_t(b0, b1, b2, b3, bb);
            mma16816(c[0], a0, a1, a2, a3, b0, b1);
            mma16816(c[1], a0, a1, a2, a3, b2, b3);
            uint32_t b4, b5;
            ldsm_x2_t(b4, b5, bb + 32);
            mma16816(c[2], a0, a1, a2, a3, b4, b5);
        }
    }

    const int ra = strip * 16 + g, rb = ra + 8;
#pragma unroll
    for (int i = 0; i < 3; i++) {
        int j = nq * 24 + i * 8 + t * 2;
        if (EPI == 0) {
            *(__half2*)(Ch + ra * CPh + j) = __floats2half2_rn(c[i][0], c[i][1]);
            *(__half2*)(Ch + rb * CPh + j) = __floats2half2_rn(c[i][2], c[i][3]);
        } else if (EPI == 1) {
            *(__half2*)(Ch + ra * CPh + j) = __floats2half2_rn(gelu_tanh(c[i][0]), gelu_tanh(c[i][1]));
            *(__half2*)(Ch + rb * CPh + j) = __floats2half2_rn(gelu_tanh(c[i][2]), gelu_tanh(c[i][3]));
        } else if (EPI == 2) {
            float2 sa = *(const float2*)(xb + (size_t)row_pos(w0, ra) * 96 + j);
            float2 sb = *(const float2*)(xb + (size_t)row_pos(w0, rb) * 96 + j);
            *(float2*)(Cf + ra * 96 + j) = make_float2(sa.x + c[i][0], sa.y + c[i][1]);
            *(float2*)(Cf + rb * 96 + j) = make_float2(sb.x + c[i][2], sb.y + c[i][3]);
        } else {
            float2 ca = *(const float2*)(Cf + ra * 96 + j);
            float2 cb = *(const float2*)(Cf + rb * 96 + j);
            *(float2*)(Cf + ra * 96 + j) = make_float2(ca.x + c[i][0], ca.y + c[i][1]);
            *(float2*)(Cf + rb * 96 + j) = make_float2(cb.x + c[i][2], cb.y + c[i][3]);
        }
    }
}

// ---- LayerNorm 64x96, 8 threads/row.  OUT 0: half->dst_h(PAH)  1: fp32->dst_f(96)
template <int OUT, int SRC>   // SRC 0: smem fp32 pitch 96   1: gmem rows via row_pos
__device__ __forceinline__ void ln64(const float* __restrict__ src, const float* __restrict__ xb, int w0,
                                     __half* __restrict__ dst_h, float* __restrict__ dst_f,
                                     const float* __restrict__ gg, const float* __restrict__ bb, int tid) {
    int row = tid >> 3, sub = tid & 7;
    const float* rp = (SRC == 0) ? (src + row * 96 + sub * 12)
                                 : (xb + (size_t)row_pos(w0, row) * 96 + sub * 12);
    float4 v[3];
#pragma unroll
    for (int i = 0; i < 3; i++) v[i] = *(const float4*)(rp + i * 4);
    float s = 0.f;
#pragma unroll
    for (int i = 0; i < 3; i++) s += v[i].x + v[i].y + v[i].z + v[i].w;
    s += __shfl_xor_sync(0xffffffffu, s, 1);
    s += __shfl_xor_sync(0xffffffffu, s, 2);
    s += __shfl_xor_sync(0xffffffffu, s, 4);
    float mean = s * (1.0f / 96.0f);
    float q = 0.f;
#pragma unroll
    for (int i = 0; i < 3; i++) {
        float dx = v[i].x - mean, dy = v[i].y - mean;
        float dz = v[i].z - mean, dw = v[i].w - mean;
        q = fmaf(dx, dx, q); q = fmaf(dy, dy, q);
        q = fmaf(dz, dz, q); q = fmaf(dw, dw, q);
    }
    q += __shfl_xor_sync(0xffffffffu, q, 1);
    q += __shfl_xor_sync(0xffffffffu, q, 2);
    q += __shfl_xor_sync(0xffffffffu, q, 4);
    float rstd = rsqrtf(q * (1.0f / 96.0f) + 1e-5f);
#pragma unroll
    for (int i = 0; i < 3; i++) {
        int d = sub * 12 + i * 4;
        float4 gv = *(const float4*)(gg + d);
        float4 bv = *(const float4*)(bb + d);
        float ox = (v[i].x - mean) * rstd * gv.x + bv.x;
        float oy = (v[i].y - mean) * rstd * gv.y + bv.y;
        float oz = (v[i].z - mean) * rstd * gv.z + bv.z;
        float ow = (v[i].w - mean) * rstd * gv.w + bv.w;
        if (OUT == 0) {
            *(__half2*)(dst_h + row * PAH + d)     = __floats2half2_rn(ox, oy);
            *(__half2*)(dst_h + row * PAH + d + 2) = __floats2half2_rn(oz, ow);
        } else {
            *(float4*)(dst_f + row * 96 + d) = make_float4(ox, oy, oz, ow);
        }
    }
}

__global__ void __launch_bounds__(NT, 2)
win_block_kernel(const float* __restrict__ x,
                 const float* __restrict__ ln1_g, const float* __restrict__ ln1_b,
                 const float* __restrict__ qkv_b,
                 const float* __restrict__ out_b,
                 const float* __restrict__ ln2_g, const float* __restrict__ ln2_b,
                 const float* __restrict__ ffn_b1, const float* __restrict__ ffn_b2,
                 const float* __restrict__ pln_g, const float* __restrict__ pln_b,
                 float* __restrict__ out) {
    extern __shared__ char sm[];
    __half* s_qkv = (__half*)(sm + OFF_QKV);  // 64 x 288 half (Q|K|V)
    __half* s_a   = (__half*)(sm + OFF_A);    // 64 x PAH half (LN out / attn out; GEMM A)
    float*  s_h   = (float*)(sm + OFF_H);     // 64 x 96 fp32 residual
    __half* s_g   = (__half*)(sm + OFF_QKV);  // alias: 64 x PGH half (gelu out)
    float*  s_fin = (float*)(sm + OFF_QKV);   // alias: 64 x 96 fp32 final LN

    const uint32_t uQ  = smem_u32(s_qkv);
    const uint32_t uA  = smem_u32(s_a);
    const uint32_t uG  = smem_u32(s_g);
    const uint32_t uW0 = smem_u32(sm + OFF_W0);
    const uint32_t uW1 = smem_u32(sm + OFF_W1);

    const int tid = threadIdx.x;
    const int w0  = blockIdx.x * WPC;
    const int b   = blockIdx.y;
    const float* xb = x + (size_t)b * L_SEQ * 96;

    // chunk 0: Wq[:,0:96] -> buf0
    stage96(g_wq, 288, uW0, tid);

    // LN1: gmem -> s_a (half)
    ln64<0, 1>(nullptr, xb, w0, s_a, nullptr, ln1_g, ln1_b, tid);

    // chunk 1: Wq[:,96:192] -> buf1
    stage96(g_wq + 96, 288, uW1, tid);
    CP_WAIT(1); __syncthreads();

    // G1 chunk0 -> s_qkv[:,0:96]
    gemm96<1, 0>(uA, PAH, uW0, 0, qkv_b, s_qkv, PQH, nullptr, xb, w0, tid);
    __syncthreads();

    stage96(g_wq + 192, 288, uW0, tid);      // chunk 2
    CP_WAIT(1); __syncthreads();
    gemm96<1, 0>(uA, PAH, uW1, 0, qkv_b + 96, s_qkv + 96, PQH, nullptr, xb, w0, tid);
    __syncthreads();

    stage96(g_wo, 96, uW1, tid);             // chunk 3
    CP_WAIT(1); __syncthreads();
    gemm96<1, 0>(uA, PAH, uW0, 0, qkv_b + 192, s_qkv + 192, PQH, nullptr, xb, w0, tid);
    __syncthreads();

    stage96(g_w1, 192, uW0, tid);            // chunk 4 (overlaps attention)

    // attention: 384 tasks (4 win x 6 heads x 16 q); read s_qkv half, write s_a half
    if (tid < WPC * 96) {
        const int wi  = tid / 96;
        const int rem = tid % 96;
        const int h   = rem >> 4;
        const int qt  = rem & 15;
        const int rbase = wi * 16;
        const __half2* q2 = (const __half2*)(s_qkv + (rbase + qt) * PQH + h * 16);
        float qv[16];
#pragma unroll
        for (int i = 0; i < 8; i++) {
            float2 f = __half22float2(q2[i]);
            qv[2 * i] = f.x; qv[2 * i + 1] = f.y;
        }
        float p[16];
        float mx = -1e30f;
#pragma unroll
        for (int kt = 0; kt < 16; kt++) {
            const __half2* k2 = (const __half2*)(s_qkv + (rbase + kt) * PQH + 96 + h * 16);
            float sd = 0.f;
#pragma unroll
            for (int i = 0; i < 8; i++) {
                float2 f = __half22float2(k2[i]);
                sd = fmaf(qv[2 * i], f.x, sd);
                sd = fmaf(qv[2 * i + 1], f.y, sd);
            }
            sd *= 0.25f;
            p[kt] = (kt <= qt) ? sd : -1e30f;
            mx = fmaxf(mx, p[kt]);
        }
        float denom = 0.f;
#pragma unroll
        for (int kt = 0; kt < 16; kt++) { p[kt] = __expf(p[kt] - mx); denom += p[kt]; }
        float inv = 1.0f / denom;
        float ov[16];
#pragma unroll
        for (int d = 0; d < 16; d++) ov[d] = 0.f;
#pragma unroll
        for (int kt = 0; kt < 16; kt++) {
            const __half2* v2 = (const __half2*)(s_qkv + (rbase + kt) * PQH + 192 + h * 16);
#pragma unroll
            for (int i = 0; i < 8; i++) {
                float2 f = __half22float2(v2[i]);
                ov[2 * i]     = fmaf(p[kt], f.x, ov[2 * i]);
                ov[2 * i + 1] = fmaf(p[kt], f.y, ov[2 * i + 1]);
            }
        }
        __half* orow = s_a + (rbase + qt) * PAH + h * 16;
#pragma unroll
        for (int i = 0; i < 8; i++)
            *(__half2*)(orow + 2 * i) = __floats2half2_rn(ov[2 * i] * inv, ov[2 * i + 1] * inv);
    }
    CP_WAIT(1); __syncthreads();

    // G2: s_h = seg + attn @ Wo + bo  (buf1 = chunk3)
    gemm96<1, 2>(uA, PAH, uW1, 0, out_b, nullptr, 0, s_h, xb, w0, tid);
    __syncthreads();

    // LN2: s_h -> s_a (half)
    ln64<0, 0>(s_h, nullptr, 0, s_a, nullptr, ln2_g, ln2_b, tid);

    stage96(g_w1 + 96, 192, uW1, tid);       // chunk 5
    CP_WAIT(1); __syncthreads();

    // G3 chunk0: gelu(s_a @ W1a) -> s_g[:,0:96]
    gemm96<1, 1>(uA, PAH, uW0, 0, ffn_b1, s_g, PGH, nullptr, xb, w0, tid);
    __syncthreads();

    stage96(g_w2, 96, uW0, tid);             // chunk 6 (W2 rows 0..95)
    CP_WAIT(1); __syncthreads();
    gemm96<1, 1>(uA, PAH, uW1, 0, ffn_b1 + 96, s_g + 96, PGH, nullptr, xb, w0, tid);
    __syncthreads();

    stage96(g_w2 + 96 * 96, 96, uW1, tid);   // chunk 7 (W2 rows 96..191)
    CP_WAIT(0); __syncthreads();

    // G4: s_h += s_g @ W2 + b2  (K=192 across buf0+buf1)
    gemm96<2, 3>(uG, PGH, uW0, uW1, ffn_b2, nullptr, 0, s_h, xb, w0, tid);
    __syncthreads();

    // final LN: s_h -> s_fin fp32
    ln64<1, 0>(s_h, nullptr, 0, nullptr, s_fin, pln_g, pln_b, tid);
    __syncthreads();

    // scatter: combine intra-CTA overlaps in smem; atomics only for boundary rows
    int nw = NUM_WIN - w0; if (nw > WPC) nw = WPC;
    const int LP = nw * 8 + 8;
    for (int i = tid; i < LP * 96; i += NT) {
        int lp = i / 96, d = i - lp * 96;
        int pos = w0 * STRIDE + lp;
        size_t oidx = ((size_t)b * L_SEQ + pos) * 96 + d;
        if (lp >= 8 && lp < nw * 8) {
            int wiH = lp >> 3, r = lp & 7;
            float vH = s_fin[(wiH * 16 + r) * 96 + d];
            float vL = s_fin[((wiH - 1) * 16 + r + 8) * 96 + d];
            out[oidx] = (vH + vL) * 0.5f;
        } else if (lp < 8) {
            float invc = (pos < STRIDE) ? 1.0f : 0.5f;
            atomicAdd(out + oidx, s_fin[lp * 96 + d] * invc);
        } else {
            int r = lp - (nw - 1) * 8;   // 8..15
            float invc = (pos >= L_SEQ - STRIDE) ? 1.0f : 0.5f;
            atomicAdd(out + oidx, s_fin[((nw - 1) * 16 + r) * 96 + d] * invc);
        }
    }
}

extern "C" void kernel_launch(void* const* d_in, const int* in_sizes, int n_in,
                              void* d_out, int out_size) {
    const float* x      = (const float*)d_in[0];
    const float* ln1_g  = (const float*)d_in[1];
    const float* ln1_b  = (const float*)d_in[2];
    const float* qkv_w  = (const float*)d_in[3];
    const float* qkv_b  = (const float*)d_in[4];
    const float* out_w  = (const float*)d_in[5];
    const float* out_b  = (const float*)d_in[6];
    const float* ln2_g  = (const float*)d_in[7];
    const float* ln2_b  = (const float*)d_in[8];
    const float* ffn_w1 = (const float*)d_in[9];
    const float* ffn_b1 = (const float*)d_in[10];
    const float* ffn_w2 = (const float*)d_in[11];
    const float* ffn_b2 = (const float*)d_in[12];
    const float* pln_g  = (const float*)d_in[13];
    const float* pln_b  = (const float*)d_in[14];
    float* out = (float*)d_out;

    const int B = in_sizes[0] / (L_SEQ * 96);
    const int nblk = (NUM_WIN + WPC - 1) / WPC;   // 256

    static int attr_set = 0;
    if (!attr_set) {
        cudaFuncSetAttribute(win_block_kernel,
                             cudaFuncAttributeMaxDynamicSharedMemorySize, SMEM_BYTES);
        attr_set = 1;
    }

    convert_w_kernel<<<(96 * 288 + 511) / 512, 512>>>(qkv_w, out_w, ffn_w1, ffn_w2);
    zero_out_kernel<<<(out_size + 511) / 512, 512>>>(out, out_size);

    dim3 grid(nblk, B);
    win_block_kernel<<<grid, NT, SMEM_BYTES>>>(
        x, ln1_g, ln1_b, qkv_b, out_b, ln2_g, ln2_b,
        ffn_b1, ffn_b2, pln_g, pln_b, out);
}

// round 9
// speedup vs baseline: 5.6322x; 1.2013x over previous
#include <cuda_runtime.h>
#include <cuda_fp16.h>
#include <cstdint>

#define WIN       16
#define STRIDE    8
#define L_SEQ     8192
#define NUM_WIN   1023
#define WPC       4
#define MROWS     64
#define NT        256

#define PQH       288        // s_qkv pitch (halves)
#define PAH       104        // s_a pitch (halves) — ldsm conflict-free
#define PGH       200        // s_g pitch (halves) — ldsm conflict-free

// smem byte offsets
#define OFF_QKV   0          // 64*288*2 = 36864  (aliased by s_h fp32 after attention)
#define OFF_A     36864      // 64*104*2 = 13312  (s_fin fp32 aliases A+G at the end)
#define OFF_G     50176      // 64*200*2 = 25600
#define SMEM_BYTES 75776

// packed B-fragment weight chunks (uint2 per lane), offsets in uint2 units
#define PB_Q0   0
#define PB_Q1   2304
#define PB_Q2   4608
#define PB_O    6912
#define PB_F1A  9216
#define PB_F1B  11520
#define PB_W2   13824
#define PB_TOTAL 18432

__device__ __align__(16) uint2 g_pb[PB_TOTAL];

// ---- prep: zero output + pack weights into mma B-fragment layout ----
// B frag (m16n8k16, row.col): b0 = {W[kb+(l&3)*2, n], W[kb+(l&3)*2+1, n]},
// b1 = same with k+8, n = colbase + nt*8 + (l>>2), kb = k16*16.
__global__ void prep_kernel(const float* __restrict__ qkv_w,
                            const float* __restrict__ out_w,
                            const float* __restrict__ w1,
                            const float* __restrict__ w2,
                            float* __restrict__ out, int out_n) {
    int i = blockIdx.x * blockDim.x + threadIdx.x;
    if (i < out_n) out[i] = 0.0f;
    if (i < PB_TOTAL) {
        const float* W; int ldn, colbase, rem;
        if (i < PB_O)        { int ch = i / 2304; rem = i % 2304; W = qkv_w; ldn = 288; colbase = ch * 96; }
        else if (i < PB_F1A) { rem = i - PB_O;    W = out_w; ldn = 96;  colbase = 0; }
        else if (i < PB_W2)  { int ch = (i - PB_F1A) / 2304; rem = (i - PB_F1A) % 2304; W = w1; ldn = 192; colbase = ch * 96; }
        else                 { rem = i - PB_W2;   W = w2;    ldn = 96;  colbase = 0; }
        int k16  = rem / (12 * 32);
        int r2   = rem % (12 * 32);
        int nt   = r2 / 32;
        int lane = r2 % 32;
        int n  = colbase + nt * 8 + (lane >> 2);
        int kb = k16 * 16 + (lane & 3) * 2;
        __half2 lo = __floats2half2_rn(W[(size_t)kb * ldn + n],       W[(size_t)(kb + 1) * ldn + n]);
        __half2 hi = __floats2half2_rn(W[(size_t)(kb + 8) * ldn + n], W[(size_t)(kb + 9) * ldn + n]);
        uint2 v;
        v.x = *(uint32_t*)&lo;
        v.y = *(uint32_t*)&hi;
        g_pb[i] = v;
    }
}

// ---- PTX wrappers ----
__device__ __forceinline__ uint32_t smem_u32(const void* p) {
    return (uint32_t)__cvta_generic_to_shared(p);
}
__device__ __forceinline__ void ldsm_x4(uint32_t& r0, uint32_t& r1, uint32_t& r2, uint32_t& r3, uint32_t a) {
    asm volatile("ldmatrix.sync.aligned.m8n8.x4.shared.b16 {%0,%1,%2,%3}, [%4];"
                 : "=r"(r0), "=r"(r1), "=r"(r2), "=r"(r3) : "r"(a));
}
__device__ __forceinline__ void mma16816(float c[4], uint32_t a0, uint32_t a1, uint32_t a2, uint32_t a3,
                                         uint32_t b0, uint32_t b1) {
    asm volatile("mma.sync.aligned.m16n8k16.row.col.f32.f16.f16.f32 "
                 "{%0,%1,%2,%3}, {%4,%5,%6,%7}, {%8,%9}, {%0,%1,%2,%3};"
                 : "+f"(c[0]), "+f"(c[1]), "+f"(c[2]), "+f"(c[3])
                 : "r"(a0), "r"(a1), "r"(a2), "r"(a3), "r"(b0), "r"(b1));
}

__device__ __forceinline__ float gelu_tanh(float x) {
    float x3 = x * x * x;
    float inner = 0.7978845608028654f * fmaf(0.044715f, x3, x);
    return 0.5f * x * (1.0f + tanhf(inner));
}
__device__ __forceinline__ int row_pos(int w0, int row) {
    int p = (w0 + (row >> 4)) * STRIDE + (row & 15);
    return p < (L_SEQ - 1) ? p : (L_SEQ - 1);
}

// ---- GEMM: C(64x96) = A(64x(16*KT) half smem) @ Wpacked + bias, 8 warps ----
// EPI 0: half->Ch  1: gelu->half->Ch  2: Cf = seg(gmem)+acc  3: Cf += acc
template <int KT, int EPI>
__device__ __forceinline__ void gemm_g(uint32_t aBase, int aPitchH,
                                       const uint2* __restrict__ pb,
                                       const float* __restrict__ bias,
                                       __half* __restrict__ Ch, int CPh,
                                       float* __restrict__ Cf,
                                       const float* __restrict__ xb, int w0, int tid) {
    const int lane = tid & 31, wid = tid >> 5;
    const int strip = wid & 3;       // 16-row M strip
    const int nq = wid >> 2;         // 48-col N half
    const int g = lane >> 2, t = lane & 3;
    const int l15 = lane & 15;
    const int hi8 = (lane >= 16) ? 8 : 0;

    float c[6][4];
#pragma unroll
    for (int i = 0; i < 6; i++) {
        float2 bv = *(const float2*)(bias + nq * 48 + i * 8 + t * 2);
        c[i][0] = bv.x; c[i][1] = bv.y; c[i][2] = bv.x; c[i][3] = bv.y;
    }

    const uint32_t aOff = aBase + (uint32_t)((strip * 16 + l15) * aPitchH + hi8) * 2;
    const uint2* pw = pb + (nq * 6) * 32 + lane;

#pragma unroll
    for (int k16 = 0; k16 < KT; k16++) {
        uint32_t a0, a1, a2, a3;
        ldsm_x4(a0, a1, a2, a3, aOff + k16 * 32);
#pragma unroll
        for (int i = 0; i < 6; i++) {
            uint2 bv = __ldg(&pw[(k16 * 12 + i) * 32]);
            mma16816(c[i], a0, a1, a2, a3, bv.x, bv.y);
        }
    }

    const int ra = strip * 16 + g, rb = ra + 8;
#pragma unroll
    for (int i = 0; i < 6; i++) {
        int j = nq * 48 + i * 8 + t * 2;
        if (EPI == 0) {
            *(__half2*)(Ch + ra * CPh + j) = __floats2half2_rn(c[i][0], c[i][1]);
            *(__half2*)(Ch + rb * CPh + j) = __floats2half2_rn(c[i][2], c[i][3]);
        } else if (EPI == 1) {
            *(__half2*)(Ch + ra * CPh + j) = __floats2half2_rn(gelu_tanh(c[i][0]), gelu_tanh(c[i][1]));
            *(__half2*)(Ch + rb * CPh + j) = __floats2half2_rn(gelu_tanh(c[i][2]), gelu_tanh(c[i][3]));
        } else if (EPI == 2) {
            float2 sa = *(const float2*)(xb + (size_t)row_pos(w0, ra) * 96 + j);
            float2 sb = *(const float2*)(xb + (size_t)row_pos(w0, rb) * 96 + j);
            *(float2*)(Cf + ra * 96 + j) = make_float2(sa.x + c[i][0], sa.y + c[i][1]);
            *(float2*)(Cf + rb * 96 + j) = make_float2(sb.x + c[i][2], sb.y + c[i][3]);
        } else {
            float2 ca = *(const float2*)(Cf + ra * 96 + j);
            float2 cb = *(const float2*)(Cf + rb * 96 + j);
            *(float2*)(Cf + ra * 96 + j) = make_float2(ca.x + c[i][0], ca.y + c[i][1]);
            *(float2*)(Cf + rb * 96 + j) = make_float2(cb.x + c[i][2], cb.y + c[i][3]);
        }
    }
}

// ---- LayerNorm 64x96, 4 threads/row (NT=256).
// OUT 0: half->dst_h(PAH)  1: fp32->dst_f(96).  SRC 0: smem fp32(96)  1: gmem rows
template <int OUT, int SRC>
__device__ __forceinline__ void ln64(const float* __restrict__ src, const float* __restrict__ xb, int w0,
                                     __half* __restrict__ dst_h, float* __restrict__ dst_f,
                                     const float* __restrict__ gg, const float* __restrict__ bb, int tid) {
    int row = tid >> 2, quarter = tid & 3;
    const float* rp = (SRC == 0) ? (src + row * 96 + quarter * 24)
                                 : (xb + (size_t)row_pos(w0, row) * 96 + quarter * 24);
    float4 v[6];
#pragma unroll
    for (int i = 0; i < 6; i++) v[i] = *(const float4*)(rp + i * 4);
    float s = 0.f;
#pragma unroll
    for (int i = 0; i < 6; i++) s += v[i].x + v[i].y + v[i].z + v[i].w;
    s += __shfl_xor_sync(0xffffffffu, s, 1);
    s += __shfl_xor_sync(0xffffffffu, s, 2);
    float mean = s * (1.0f / 96.0f);
    float q = 0.f;
#pragma unroll
    for (int i = 0; i < 6; i++) {
        float dx = v[i].x - mean, dy = v[i].y - mean;
        float dz = v[i].z - mean, dw = v[i].w - mean;
        q = fmaf(dx, dx, q); q = fmaf(dy, dy, q);
        q = fmaf(dz, dz, q); q = fmaf(dw, dw, q);
    }
    q += __shfl_xor_sync(0xffffffffu, q, 1);
    q += __shfl_xor_sync(0xffffffffu, q, 2);
    float rstd = rsqrtf(q * (1.0f / 96.0f) + 1e-5f);
#pragma unroll
    for (int i = 0; i < 6; i++) {
        int d = quarter * 24 + i * 4;
        float4 gv = *(const float4*)(gg + d);
        float4 bv = *(const float4*)(bb + d);
        float ox = (v[i].x - mean) * rstd * gv.x + bv.x;
        float oy = (v[i].y - mean) * rstd * gv.y + bv.y;
        float oz = (v[i].z - mean) * rstd * gv.z + bv.z;
        float ow = (v[i].w - mean) * rstd * gv.w + bv.w;
        if (OUT == 0) {
            *(__half2*)(dst_h + row * PAH + d)     = __floats2half2_rn(ox, oy);
            *(__half2*)(dst_h + row * PAH + d + 2) = __floats2half2_rn(oz, ow);
        } else {
            *(float4*)(dst_f + row * 96 + d) = make_float4(ox, oy, oz, ow);
        }
    }
}

// attention body for one task (win, head, qt)
__device__ __forceinline__ void attn_task(const __half* __restrict__ s_qkv,
                                          __half* __restrict__ s_a, int task) {
    const int wi  = task / 96;
    const int rem = task % 96;
    const int h   = rem >> 4;
    const int qt  = rem & 15;
    const int rbase = wi * 16;
    const __half2* q2 = (const __half2*)(s_qkv + (rbase + qt) * PQH + h * 16);
    float qv[16];
#pragma unroll
    for (int i = 0; i < 8; i++) {
        float2 f = __half22float2(q2[i]);
        qv[2 * i] = f.x; qv[2 * i + 1] = f.y;
    }
    float p[16];
    float mx = -1e30f;
#pragma unroll
    for (int kt = 0; kt < 16; kt++) {
        const __half2* k2 = (const __half2*)(s_qkv + (rbase + kt) * PQH + 96 + h * 16);
        float sd = 0.f;
#pragma unroll
        for (int i = 0; i < 8; i++) {
            float2 f = __half22float2(k2[i]);
            sd = fmaf(qv[2 * i], f.x, sd);
            sd = fmaf(qv[2 * i + 1], f.y, sd);
        }
        sd *= 0.25f;
        p[kt] = (kt <= qt) ? sd : -1e30f;
        mx = fmaxf(mx, p[kt]);
    }
    float denom = 0.f;
#pragma unroll
    for (int kt = 0; kt < 16; kt++) { p[kt] = __expf(p[kt] - mx); denom += p[kt]; }
    float inv = 1.0f / denom;
    float ov[16];
#pragma unroll
    for (int d = 0; d < 16; d++) ov[d] = 0.f;
#pragma unroll
    for (int kt = 0; kt < 16; kt++) {
        const __half2* v2 = (const __half2*)(s_qkv + (rbase + kt) * PQH + 192 + h * 16);
#pragma unroll
        for (int i = 0; i < 8; i++) {
            float2 f = __half22float2(v2[i]);
            ov[2 * i]     = fmaf(p[kt], f.x, ov[2 * i]);
            ov[2 * i + 1] = fmaf(p[kt], f.y, ov[2 * i + 1]);
        }
    }
    __half* orow = s_a + (rbase + qt) * PAH + h * 16;
#pragma unroll
    for (int i = 0; i < 8; i++)
        *(__half2*)(orow + 2 * i) = __floats2half2_rn(ov[2 * i] * inv, ov[2 * i + 1] * inv);
}

__global__ void __launch_bounds__(NT, 3)
win_block_kernel(const float* __restrict__ x,
                 const float* __restrict__ ln1_g, const float* __restrict__ ln1_b,
                 const float* __restrict__ qkv_b,
                 const float* __restrict__ out_b,
                 const float* __restrict__ ln2_g, const float* __restrict__ ln2_b,
                 const float* __restrict__ ffn_b1, const float* __restrict__ ffn_b2,
                 const float* __restrict__ pln_g, const float* __restrict__ pln_b,
                 float* __restrict__ out) {
    extern __shared__ char sm[];
    __half* s_qkv = (__half*)(sm + OFF_QKV);  // 64 x 288 half (Q|K|V)
    __half* s_a   = (__half*)(sm + OFF_A);    // 64 x PAH half
    __half* s_g   = (__half*)(sm + OFF_G);    // 64 x PGH half
    float*  s_h   = (float*)(sm + OFF_QKV);   // alias over dead qkv (fp32 residual)
    float*  s_fin = (float*)(sm + OFF_A);     // alias over dead a+g (final LN fp32)

    const uint32_t uA = smem_u32(s_a);
    const uint32_t uG = smem_u32(s_g);

    const int tid = threadIdx.x;
    const int w0  = blockIdx.x * WPC;
    const int b   = blockIdx.y;
    const float* xb = x + (size_t)b * L_SEQ * 96;

    // LN1: gmem -> s_a (half)
    ln64<0, 1>(nullptr, xb, w0, s_a, nullptr, ln1_g, ln1_b, tid);
    __syncthreads();

    // G1: Q, K, V GEMMs back-to-back (B streamed from L2) -> s_qkv
    gemm_g<6, 0>(uA, PAH, g_pb + PB_Q0, qkv_b,       s_qkv,       PQH, nullptr, xb, w0, tid);
    gemm_g<6, 0>(uA, PAH, g_pb + PB_Q1, qkv_b + 96,  s_qkv + 96,  PQH, nullptr, xb, w0, tid);
    gemm_g<6, 0>(uA, PAH, g_pb + PB_Q2, qkv_b + 192, s_qkv + 192, PQH, nullptr, xb, w0, tid);
    __syncthreads();

    // attention: 384 tasks over 256 threads
    attn_task(s_qkv, s_a, tid);
    if (tid < 128) attn_task(s_qkv, s_a, tid + 256);
    __syncthreads();

    // G2: s_h = seg + attn @ Wo + bo   (s_h aliases dead qkv)
    gemm_g<6, 2>(uA, PAH, g_pb + PB_O, out_b, nullptr, 0, s_h, xb, w0, tid);
    __syncthreads();

    // LN2: s_h -> s_a (half)
    ln64<0, 0>(s_h, nullptr, 0, s_a, nullptr, ln2_g, ln2_b, tid);
    __syncthreads();

    // G3: gelu(s_a @ W1 + b1) -> s_g (two N=96 halves)
    gemm_g<6, 1>(uA, PAH, g_pb + PB_F1A, ffn_b1,      s_g,      PGH, nullptr, xb, w0, tid);
    gemm_g<6, 1>(uA, PAH, g_pb + PB_F1B, ffn_b1 + 96, s_g + 96, PGH, nullptr, xb, w0, tid);
    __syncthreads();

    // G4: s_h += s_g @ W2 + b2  (K=192)
    gemm_g<12, 3>(uG, PGH, g_pb + PB_W2, ffn_b2, nullptr, 0, s_h, xb, w0, tid);
    __syncthreads();

    // final LN: s_h -> s_fin fp32 (aliases dead a+g)
    ln64<1, 0>(s_h, nullptr, 0, nullptr, s_fin, pln_g, pln_b, tid);
    __syncthreads();

    // scatter: intra-CTA overlaps combined in smem; atomics only at CTA boundaries
    int nw = NUM_WIN - w0; if (nw > WPC) nw = WPC;
    const int LP = nw * 8 + 8;
    for (int i = tid; i < LP * 96; i += NT) {
        int lp = i / 96, d = i - lp * 96;
        int pos = w0 * STRIDE + lp;
        size_t oidx = ((size_t)b * L_SEQ + pos) * 96 + d;
        if (lp >= 8 && lp < nw * 8) {
            int wiH = lp >> 3, r = lp & 7;
            float vH = s_fin[(wiH * 16 + r) * 96 + d];
            float vL = s_fin[((wiH - 1) * 16 + r + 8) * 96 + d];
            out[oidx] = (vH + vL) * 0.5f;
        } else if (lp < 8) {
            float invc = (pos < STRIDE) ? 1.0f : 0.5f;
            atomicAdd(out + oidx, s_fin[lp * 96 + d] * invc);
        } else {
            int r = lp - (nw - 1) * 8;   // 8..15
            float invc = (pos >= L_SEQ - STRIDE) ? 1.0f : 0.5f;
            atomicAdd(out + oidx, s_fin[((nw - 1) * 16 + r) * 96 + d] * invc);
        }
    }
}

extern "C" void kernel_launch(void* const* d_in, const int* in_sizes, int n_in,
                              void* d_out, int out_size) {
    const float* x      = (const float*)d_in[0];
    const float* ln1_g  = (const float*)d_in[1];
    const float* ln1_b  = (const float*)d_in[2];
    const float* qkv_w  = (const float*)d_in[3];
    const float* qkv_b  = (const float*)d_in[4];
    const float* out_w  = (const float*)d_in[5];
    const float* out_b  = (const float*)d_in[6];
    const float* ln2_g  = (const float*)d_in[7];
    const float* ln2_b  = (const float*)d_in[8];
    const float* ffn_w1 = (const float*)d_in[9];
    const float* ffn_b1 = (const float*)d_in[10];
    const float* ffn_w2 = (const float*)d_in[11];
    const float* ffn_b2 = (const float*)d_in[12];
    const float* pln_g  = (const float*)d_in[13];
    const float* pln_b  = (const float*)d_in[14];
    float* out = (float*)d_out;

    const int B = in_sizes[0] / (L_SEQ * 96);
    const int nblk = (NUM_WIN + WPC - 1) / WPC;   // 256

    static int attr_set = 0;
    if (!attr_set) {
        cudaFuncSetAttribute(win_block_kernel,
                             cudaFuncAttributeMaxDynamicSharedMemorySize, SMEM_BYTES);
        attr_set = 1;
    }

    prep_kernel<<<(out_size + 255) / 256, 256>>>(qkv_w, out_w, ffn_w1, ffn_w2, out, out_size);

    dim3 grid(nblk, B);
    win_block_kernel<<<grid, NT, SMEM_BYTES>>>(
        x, ln1_g, ln1_b, qkv_b, out_b, ln2_g, ln2_b,
        ffn_b1, ffn_b2, pln_g, pln_b, out);
}

// round 10
// speedup vs baseline: 5.9715x; 1.0602x over previous
#include <cuda_runtime.h>
#include <cuda_fp16.h>
#include <cstdint>

#define WIN       16
#define STRIDE    8
#define L_SEQ     8192
#define NUM_WIN   1023
#define WPC       4
#define MROWS     64
#define NT        256

#define PQK       200        // s_qk pitch (halves): Q cols 0-95, K cols 96-191
#define PVT       72         // s_vt pitch (halves): rows=d(96), cols=token(64)
#define PAH       104        // s_a pitch (halves)
#define PGH       200        // s_g pitch (halves)

// smem byte offsets (regions alias across phases)
#define OFF_QK    0          // s_qk 64*200*2=25600 ; later s_h 64*96*4=24576
#define OFF_VT    25600      // s_vt 96*72*2=13824 ; later s_g 64*200*2=25600 ; s_fin 24576
#define OFF_A     51200      // s_a 64*104*2=13312
#define SMEM_BYTES 64512

// packed B fragments: uint4 = b-frags for two consecutive k16 steps
// chunk layout: [kp][ntile(12)][lane(32)]; 96-K chunk = 3*12*32 = 1152 uint4
#define PB4_Q     0          // 3 chunks (Q,K,V)
#define PB4_O     3456
#define PB4_F1    4608       // 2 chunks
#define PB4_W2    6912       // K=192: 6*12*32 = 2304
#define PB4_TOTAL 9216

__device__ __align__(16) uint4 g_pb4[PB4_TOTAL];

__global__ void prep_kernel(const float* __restrict__ qkv_w,
                            const float* __restrict__ out_w,
                            const float* __restrict__ w1,
                            const float* __restrict__ w2,
                            float* __restrict__ out, int out_n) {
    int i = blockIdx.x * blockDim.x + threadIdx.x;
    if (i < out_n) out[i] = 0.0f;
    if (i < PB4_TOTAL) {
        const float* W; int ldn, colbase, rem;
        if (i < PB4_O)       { int ch = i / 1152; rem = i % 1152; W = qkv_w; ldn = 288; colbase = ch * 96; }
        else if (i < PB4_F1) { rem = i - PB4_O; W = out_w; ldn = 96; colbase = 0; }
        else if (i < PB4_W2) { int ch = (i - PB4_F1) / 1152; rem = (i - PB4_F1) % 1152; W = w1; ldn = 192; colbase = ch * 96; }
        else                 { rem = i - PB4_W2; W = w2; ldn = 96; colbase = 0; }
        int kp   = rem / (12 * 32);
        int r2   = rem % (12 * 32);
        int nt   = r2 / 32;
        int lane = r2 % 32;
        int n   = colbase + nt * 8 + (lane >> 2);
        int kb0 = (2 * kp) * 16 + (lane & 3) * 2;
        int kb1 = kb0 + 16;
        __half2 vx = __floats2half2_rn(W[(size_t)kb0 * ldn + n],       W[(size_t)(kb0 + 1) * ldn + n]);
        __half2 vy = __floats2half2_rn(W[(size_t)(kb0 + 8) * ldn + n], W[(size_t)(kb0 + 9) * ldn + n]);
        __half2 vz = __floats2half2_rn(W[(size_t)kb1 * ldn + n],       W[(size_t)(kb1 + 1) * ldn + n]);
        __half2 vw = __floats2half2_rn(W[(size_t)(kb1 + 8) * ldn + n], W[(size_t)(kb1 + 9) * ldn + n]);
        uint4 v;
        v.x = *(uint32_t*)&vx; v.y = *(uint32_t*)&vy;
        v.z = *(uint32_t*)&vz; v.w = *(uint32_t*)&vw;
        g_pb4[i] = v;
    }
}

// ---- PTX wrappers ----
__device__ __forceinline__ uint32_t smem_u32(const void* p) {
    return (uint32_t)__cvta_generic_to_shared(p);
}
__device__ __forceinline__ void ldsm_x4(uint32_t& r0, uint32_t& r1, uint32_t& r2, uint32_t& r3, uint32_t a) {
    asm volatile("ldmatrix.sync.aligned.m8n8.x4.shared.b16 {%0,%1,%2,%3}, [%4];"
                 : "=r"(r0), "=r"(r1), "=r"(r2), "=r"(r3) : "r"(a));
}
__device__ __forceinline__ void mma16816(float c[4], uint32_t a0, uint32_t a1, uint32_t a2, uint32_t a3,
                                         uint32_t b0, uint32_t b1) {
    asm volatile("mma.sync.aligned.m16n8k16.row.col.f32.f16.f16.f32 "
                 "{%0,%1,%2,%3}, {%4,%5,%6,%7}, {%8,%9}, {%0,%1,%2,%3};"
                 : "+f"(c[0]), "+f"(c[1]), "+f"(c[2]), "+f"(c[3])
                 : "r"(a0), "r"(a1), "r"(a2), "r"(a3), "r"(b0), "r"(b1));
}

__device__ __forceinline__ float gelu_tanh(float x) {
    float x3 = x * x * x;
    float inner = 0.7978845608028654f * fmaf(0.044715f, x3, x);
    return 0.5f * x * (1.0f + tanhf(inner));
}
__device__ __forceinline__ int row_pos(int w0, int row) {
    int p = (w0 + (row >> 4)) * STRIDE + (row & 15);
    return p < (L_SEQ - 1) ? p : (L_SEQ - 1);
}

// ---- K=96 GEMM over NC chunks with cached A fragments ----
// EPI 1: gelu->half (Ch pitch CPh, col c*96)   2: Cf = seg+acc   5: qkv special
//   (EPI 5: chunks 0,1 -> half to Ch (Q|K at col c*96); chunk 2 -> transposed half to vt)
template <int NC, int EPI>
__device__ __forceinline__ void gemm6(uint32_t aBase, int aPitchH,
                                      const uint4* __restrict__ pb4,
                                      const float* __restrict__ bias,
                                      __half* __restrict__ Ch, int CPh,
                                      float* __restrict__ Cf,
                                      __half* __restrict__ vt,
                                      const float* __restrict__ xb, int w0, int tid) {
    const int lane = tid & 31, wid = tid >> 5;
    const int strip = wid & 3;       // 16-row M strip
    const int nq = wid >> 2;         // 48-col N half
    const int g = lane >> 2, t = lane & 3;
    const int l15 = lane & 15;
    const int hi8 = (lane >= 16) ? 8 : 0;

    const uint32_t aOff = aBase + (uint32_t)((strip * 16 + l15) * aPitchH + hi8) * 2;
    uint32_t a[6][4];
#pragma unroll
    for (int k16 = 0; k16 < 6; k16++)
        ldsm_x4(a[k16][0], a[k16][1], a[k16][2], a[k16][3], aOff + k16 * 32);

    const int ra = strip * 16 + g, rb = ra + 8;

#pragma unroll
    for (int c = 0; c < NC; c++) {
        float acc[6][4];
#pragma unroll
        for (int i = 0; i < 6; i++) {
            float2 bv = *(const float2*)(bias + c * 96 + nq * 48 + i * 8 + t * 2);
            acc[i][0] = bv.x; acc[i][1] = bv.y; acc[i][2] = bv.x; acc[i][3] = bv.y;
        }
        const uint4* pw = pb4 + c * 1152 + (nq * 6) * 32 + lane;
#pragma unroll
        for (int kp = 0; kp < 3; kp++) {
            uint4 bv[6];
#pragma unroll
            for (int i = 0; i < 6; i++) bv[i] = __ldg(&pw[(kp * 12 + i) * 32]);
#pragma unroll
            for (int i = 0; i < 6; i++) {
                mma16816(acc[i], a[2*kp][0], a[2*kp][1], a[2*kp][2], a[2*kp][3], bv[i].x, bv[i].y);
                mma16816(acc[i], a[2*kp+1][0], a[2*kp+1][1], a[2*kp+1][2], a[2*kp+1][3], bv[i].z, bv[i].w);
            }
        }
#pragma unroll
        for (int i = 0; i < 6; i++) {
            int j = nq * 48 + i * 8 + t * 2;
            if (EPI == 1) {
                *(__half2*)(Ch + ra * CPh + c * 96 + j) = __floats2half2_rn(gelu_tanh(acc[i][0]), gelu_tanh(acc[i][1]));
                *(__half2*)(Ch + rb * CPh + c * 96 + j) = __floats2half2_rn(gelu_tanh(acc[i][2]), gelu_tanh(acc[i][3]));
            } else if (EPI == 2) {
                float2 sa = *(const float2*)(xb + (size_t)row_pos(w0, ra) * 96 + j);
                float2 sb = *(const float2*)(xb + (size_t)row_pos(w0, rb) * 96 + j);
                *(float2*)(Cf + ra * 96 + j) = make_float2(sa.x + acc[i][0], sa.y + acc[i][1]);
                *(float2*)(Cf + rb * 96 + j) = make_float2(sb.x + acc[i][2], sb.y + acc[i][3]);
            } else {  // EPI 5
                if (c < 2) {
                    *(__half2*)(Ch + ra * CPh + c * 96 + j) = __floats2half2_rn(acc[i][0], acc[i][1]);
                    *(__half2*)(Ch + rb * CPh + c * 96 + j) = __floats2half2_rn(acc[i][2], acc[i][3]);
                } else {
                    vt[j * PVT + ra]       = __float2half_rn(acc[i][0]);
                    vt[(j + 1) * PVT + ra] = __float2half_rn(acc[i][1]);
                    vt[j * PVT + rb]       = __float2half_rn(acc[i][2]);
                    vt[(j + 1) * PVT + rb] = __float2half_rn(acc[i][3]);
                }
            }
        }
    }
}

// ---- K=192 GEMM (ffn2), EPI: Cf += acc ----
__device__ __forceinline__ void gemm12_acc(uint32_t aBase, int aPitchH,
                                           const uint4* __restrict__ pb4,
                                           const float* __restrict__ bias,
                                           float* __restrict__ Cf, int tid) {
    const int lane = tid & 31, wid = tid >> 5;
    const int strip = wid & 3;
    const int nq = wid >> 2;
    const int g = lane >> 2, t = lane & 3;
    const int l15 = lane & 15;
    const int hi8 = (lane >= 16) ? 8 : 0;

    float acc[6][4];
#pragma unroll
    for (int i = 0; i < 6; i++) {
        float2 bv = *(const float2*)(bias + nq * 48 + i * 8 + t * 2);
        acc[i][0] = bv.x; acc[i][1] = bv.y; acc[i][2] = bv.x; acc[i][3] = bv.y;
    }
    const uint32_t aOff = aBase + (uint32_t)((strip * 16 + l15) * aPitchH + hi8) * 2;
    const uint4* pw = pb4 + (nq * 6) * 32 + lane;
#pragma unroll
    for (int kp = 0; kp < 6; kp++) {
        uint32_t a0[4], a1[4];
        ldsm_x4(a0[0], a0[1], a0[2], a0[3], aOff + (2 * kp) * 32);
        ldsm_x4(a1[0], a1[1], a1[2], a1[3], aOff + (2 * kp + 1) * 32);
        uint4 bv[6];
#pragma unroll
        for (int i = 0; i < 6; i++) bv[i] = __ldg(&pw[(kp * 12 + i) * 32]);
#pragma unroll
        for (int i = 0; i < 6; i++) {
            mma16816(acc[i], a0[0], a0[1], a0[2], a0[3], bv[i].x, bv[i].y);
            mma16816(acc[i], a1[0], a1[1], a1[2], a1[3], bv[i].z, bv[i].w);
        }
    }
    const int ra = strip * 16 + g, rb = ra + 8;
#pragma unroll
    for (int i = 0; i < 6; i++) {
        int j = nq * 48 + i * 8 + t * 2;
        float2 ca = *(const float2*)(Cf + ra * 96 + j);
        float2 cb = *(const float2*)(Cf + rb * 96 + j);
        *(float2*)(Cf + ra * 96 + j) = make_float2(ca.x + acc[i][0], ca.y + acc[i][1]);
        *(float2*)(Cf + rb * 96 + j) = make_float2(cb.x + acc[i][2], cb.y + acc[i][3]);
    }
}

// ---- tensor-core attention: 24 (win,head) pairs, 3 per warp ----
__device__ __forceinline__ void attn_mma(uint32_t uQK, uint32_t uVT,
                                         __half* __restrict__ s_a, int tid) {
    const int lane = tid & 31, wid = tid >> 5;
    const int l15 = lane & 15;
    const int lh8 = (lane >= 16) ? 8 : 0;
    const int g = lane >> 2, t = lane & 3;
    const int c0 = 2 * t, c1 = 2 * t + 1, c2 = 2 * t + 8, c3 = 2 * t + 9;

#pragma unroll
    for (int it = 0; it < 3; it++) {
        const int pair = wid + it * 8;       // 0..23
        const int wi = pair / 6, h = pair % 6;
        const int rbase = wi * 16;

        uint32_t qA = uQK + (uint32_t)(((rbase + l15) * PQK + h * 16 + lh8) * 2);
        uint32_t kA = uQK + (uint32_t)(((rbase + l15) * PQK + 96 + h * 16 + lh8) * 2);
        uint32_t vA = uVT + (uint32_t)(((h * 16 + l15) * PVT + rbase + lh8) * 2);

        uint32_t a0, a1, a2, a3, k0, k1, k2, k3, v0, v1, v2, v3;
        ldsm_x4(a0, a1, a2, a3, qA);
        ldsm_x4(k0, k1, k2, k3, kA);
        ldsm_x4(v0, v1, v2, v3, vA);

        float s0[4] = {0.f, 0.f, 0.f, 0.f};
        float s1[4] = {0.f, 0.f, 0.f, 0.f};
        mma16816(s0, a0, a1, a2, a3, k0, k2);   // S cols kt 0-7
        mma16816(s1, a0, a1, a2, a3, k1, k3);   // S cols kt 8-15

        // rows g (x0*) and g+8 (x1*); scale 0.25, causal mask
        float x00 = (c0 <= g) ? s0[0] * 0.25f : -1e30f;
        float x01 = (c1 <= g) ? s0[1] * 0.25f : -1e30f;
        float x02 = (c2 <= g) ? s1[0] * 0.25f : -1e30f;
        float x03 = (c3 <= g) ? s1[1] * 0.25f : -1e30f;
        int g8 = g + 8;
        float x10 = (c0 <= g8) ? s0[2] * 0.25f : -1e30f;
        float x11 = (c1 <= g8) ? s0[3] * 0.25f : -1e30f;
        float x12 = (c2 <= g8) ? s1[2] * 0.25f : -1e30f;
        float x13 = (c3 <= g8) ? s1[3] * 0.25f : -1e30f;

        float m0 = fmaxf(fmaxf(x00, x01), fmaxf(x02, x03));
        float m1 = fmaxf(fmaxf(x10, x11), fmaxf(x12, x13));
        m0 = fmaxf(m0, __shfl_xor_sync(0xffffffffu, m0, 1));
        m0 = fmaxf(m0, __shfl_xor_sync(0xffffffffu, m0, 2));
        m1 = fmaxf(m1, __shfl_xor_sync(0xffffffffu, m1, 1));
        m1 = fmaxf(m1, __shfl_xor_sync(0xffffffffu, m1, 2));

        float e00 = __expf(x00 - m0), e01 = __expf(x01 - m0);
        float e02 = __expf(x02 - m0), e03 = __expf(x03 - m0);
        float e10 = __expf(x10 - m1), e11 = __expf(x11 - m1);
        float e12 = __expf(x12 - m1), e13 = __expf(x13 - m1);

        float d0 = e00 + e01 + e02 + e03;
        float d1 = e10 + e11 + e12 + e13;
        d0 += __shfl_xor_sync(0xffffffffu, d0, 1);
        d0 += __shfl_xor_sync(0xffffffffu, d0, 2);
        d1 += __shfl_xor_sync(0xffffffffu, d1, 1);
        d1 += __shfl_xor_sync(0xffffffffu, d1, 2);
        float i0 = 1.0f / d0, i1 = 1.0f / d1;

        // P fragments (A-layout for PV mma)
        __half2 p0 = __floats2half2_rn(e00 * i0, e01 * i0);
        __half2 p1 = __floats2half2_rn(e10 * i1, e11 * i1);
        __half2 p2 = __floats2half2_rn(e02 * i0, e03 * i0);
        __half2 p3 = __floats2half2_rn(e12 * i1, e13 * i1);
        uint32_t pa0 = *(uint32_t*)&p0, pa1 = *(uint32_t*)&p1;
        uint32_t pa2 = *(uint32_t*)&p2, pa3 = *(uint32_t*)&p3;

        float o0[4] = {0.f, 0.f, 0.f, 0.f};
        float o1[4] = {0.f, 0.f, 0.f, 0.f};
        mma16816(o0, pa0, pa1, pa2, pa3, v0, v2);   // O cols d 0-7
        mma16816(o1, pa0, pa1, pa2, pa3, v1, v3);   // O cols d 8-15

        __half* ba = s_a + (rbase + g) * PAH + h * 16;
        __half* bb = s_a + (rbase + g8) * PAH + h * 16;
        *(__half2*)(ba + 2 * t)     = __floats2half2_rn(o0[0], o0[1]);
        *(__half2*)(ba + 8 + 2 * t) = __floats2half2_rn(o1[0], o1[1]);
        *(__half2*)(bb + 2 * t)     = __floats2half2_rn(o0[2], o0[3]);
        *(__half2*)(bb + 8 + 2 * t) = __floats2half2_rn(o1[2], o1[3]);
    }
}

// ---- LayerNorm 64x96, 4 threads/row ----
template <int OUT, int SRC>   // OUT 0: half->dst_h(PAH) 1: fp32->dst_f(96); SRC 0: smem(96) 1: gmem
__device__ __forceinline__ void ln64(const float* __restrict__ src, const float* __restrict__ xb, int w0,
                                     __half* __restrict__ dst_h, float* __restrict__ dst_f,
                                     const float* __restrict__ gg, const float* __restrict__ bb, int tid) {
    int row = tid >> 2, quarter = tid & 3;
    const float* rp = (SRC == 0) ? (src + row * 96 + quarter * 24)
                                 : (xb + (size_t)row_pos(w0, row) * 96 + quarter * 24);
    float4 v[6];
#pragma unroll
    for (int i = 0; i < 6; i++) v[i] = *(const float4*)(rp + i * 4);
    float s = 0.f;
#pragma unroll
    for (int i = 0; i < 6; i++) s += v[i].x + v[i].y + v[i].z + v[i].w;
    s += __shfl_xor_sync(0xffffffffu, s, 1);
    s += __shfl_xor_sync(0xffffffffu, s, 2);
    float mean = s * (1.0f / 96.0f);
    float q = 0.f;
#pragma unroll
    for (int i = 0; i < 6; i++) {
        float dx = v[i].x - mean, dy = v[i].y - mean;
        float dz = v[i].z - mean, dw = v[i].w - mean;
        q = fmaf(dx, dx, q); q = fmaf(dy, dy, q);
        q = fmaf(dz, dz, q); q = fmaf(dw, dw, q);
    }
    q += __shfl_xor_sync(0xffffffffu, q, 1);
    q += __shfl_xor_sync(0xffffffffu, q, 2);
    float rstd = rsqrtf(q * (1.0f / 96.0f) + 1e-5f);
#pragma unroll
    for (int i = 0; i < 6; i++) {
        int d = quarter * 24 + i * 4;
        float4 gv = *(const float4*)(gg + d);
        float4 bv = *(const float4*)(bb + d);
        float ox = (v[i].x - mean) * rstd * gv.x + bv.x;
        float oy = (v[i].y - mean) * rstd * gv.y + bv.y;
        float oz = (v[i].z - mean) * rstd * gv.z + bv.z;
        float ow = (v[i].w - mean) * rstd * gv.w + bv.w;
        if (OUT == 0) {
            *(__half2*)(dst_h + row * PAH + d)     = __floats2half2_rn(ox, oy);
            *(__half2*)(dst_h + row * PAH + d + 2) = __floats2half2_rn(oz, ow);
        } else {
            *(float4*)(dst_f + row * 96 + d) = make_float4(ox, oy, oz, ow);
        }
    }
}

__global__ void __launch_bounds__(NT, 3)
win_block_kernel(const float* __restrict__ x,
                 const float* __restrict__ ln1_g, const float* __restrict__ ln1_b,
                 const float* __restrict__ qkv_b,
                 const float* __restrict__ out_b,
                 const float* __restrict__ ln2_g, const float* __restrict__ ln2_b,
                 const float* __restrict__ ffn_b1, const float* __restrict__ ffn_b2,
                 const float* __restrict__ pln_g, const float* __restrict__ pln_b,
                 float* __restrict__ out) {
    extern __shared__ char sm[];
    __half* s_qk  = (__half*)(sm + OFF_QK);   // 64 x 200 (Q|K)
    __half* s_vt  = (__half*)(sm + OFF_VT);   // 96 x 72 (V^T)
    __half* s_a   = (__half*)(sm + OFF_A);    // 64 x 104
    float*  s_h   = (float*)(sm + OFF_QK);    // alias (residual fp32)
    __half* s_g   = (__half*)(sm + OFF_VT);   // alias (gelu out 64x200)
    float*  s_fin = (float*)(sm + OFF_VT);    // alias (final LN fp32)

    const uint32_t uQK = smem_u32(s_qk);
    const uint32_t uVT = smem_u32(s_vt);
    const uint32_t uA  = smem_u32(s_a);
    const uint32_t uG  = smem_u32(s_g);

    const int tid = threadIdx.x;
    const int w0  = blockIdx.x * WPC;
    const int b   = blockIdx.y;
    const float* xb = x + (size_t)b * L_SEQ * 96;

    // LN1: gmem -> s_a (half)
    ln64<0, 1>(nullptr, xb, w0, s_a, nullptr, ln1_g, ln1_b, tid);
    __syncthreads();

    // G1: Q,K -> s_qk; V -> s_vt transposed (A frags cached across chunks)
    gemm6<3, 5>(uA, PAH, g_pb4 + PB4_Q, qkv_b, s_qk, PQK, nullptr, s_vt, xb, w0, tid);
    __syncthreads();

    // attention (tensor cores) -> s_a
    attn_mma(uQK, uVT, s_a, tid);
    __syncthreads();

    // G2: s_h = seg + attn @ Wo + bo  (aliases dead s_qk)
    gemm6<1, 2>(uA, PAH, g_pb4 + PB4_O, out_b, nullptr, 0, s_h, nullptr, xb, w0, tid);
    __syncthreads();

    // LN2: s_h -> s_a
    ln64<0, 0>(s_h, nullptr, 0, s_a, nullptr, ln2_g, ln2_b, tid);
    __syncthreads();

    // G3: gelu(s_a @ W1 + b1) -> s_g (aliases dead s_vt)
    gemm6<2, 1>(uA, PAH, g_pb4 + PB4_F1, ffn_b1, s_g, PGH, nullptr, nullptr, xb, w0, tid);
    __syncthreads();

    // G4: s_h += s_g @ W2 + b2
    gemm12_acc(uG, PGH, g_pb4 + PB4_W2, ffn_b2, s_h, tid);
    __syncthreads();

    // final LN: s_h -> s_fin
    ln64<1, 0>(s_h, nullptr, 0, nullptr, s_fin, pln_g, pln_b, tid);
    __syncthreads();

    // scatter: intra-CTA overlaps combined; atomics only at CTA boundaries
    int nw = NUM_WIN - w0; if (nw > WPC) nw = WPC;
    const int LP = nw * 8 + 8;
    for (int i = tid; i < LP * 96; i += NT) {
        int lp = i / 96, d = i - lp * 96;
        int pos = w0 * STRIDE + lp;
        size_t oidx = ((size_t)b * L_SEQ + pos) * 96 + d;
        if (lp >= 8 && lp < nw * 8) {
            int wiH = lp >> 3, r = lp & 7;
            float vH = s_fin[(wiH * 16 + r) * 96 + d];
            float vL = s_fin[((wiH - 1) * 16 + r + 8) * 96 + d];
            out[oidx] = (vH + vL) * 0.5f;
        } else if (lp < 8) {
            float invc = (pos < STRIDE) ? 1.0f : 0.5f;
            atomicAdd(out + oidx, s_fin[lp * 96 + d] * invc);
        } else {
            int r = lp - (nw - 1) * 8;
            float invc = (pos >= L_SEQ - STRIDE) ? 1.0f : 0.5f;
            atomicAdd(out + oidx, s_fin[((nw - 1) * 16 + r) * 96 + d] * invc);
        }
    }
}

extern "C" void kernel_launch(void* const* d_in, const int* in_sizes, int n_in,
                              void* d_out, int out_size) {
    const float* x      = (const float*)d_in[0];
    const float* ln1_g  = (const float*)d_in[1];
    const float* ln1_b  = (const float*)d_in[2];
    const float* qkv_w  = (const float*)d_in[3];
    const float* qkv_b  = (const float*)d_in[4];
    const float* out_w  = (const float*)d_in[5];
    const float* out_b  = (const float*)d_in[6];
    const float* ln2_g  = (const float*)d_in[7];
    const float* ln2_b  = (const float*)d_in[8];
    const float* ffn_w1 = (const float*)d_in[9];
    const float* ffn_b1 = (const float*)d_in[10];
    const float* ffn_w2 = (const float*)d_in[11];
    const float* ffn_b2 = (const float*)d_in[12];
    const float* pln_g  = (const float*)d_in[13];
    const float* pln_b  = (const float*)d_in[14];
    float* out = (float*)d_out;

    const int B = in_sizes[0] / (L_SEQ * 96);
    const int nblk = (NUM_WIN + WPC - 1) / WPC;   // 256

    static int attr_set = 0;
    if (!attr_set) {
        cudaFuncSetAttribute(win_block_kernel,
                             cudaFuncAttributeMaxDynamicSharedMemorySize, SMEM_BYTES);
        attr_set = 1;
    }

    prep_kernel<<<(out_size + 255) / 256, 256>>>(qkv_w, out_w, ffn_w1, ffn_w2, out, out_size);

    dim3 grid(nblk, B);
    win_block_kernel<<<grid, NT, SMEM_BYTES>>>(
        x, ln1_g, ln1_b, qkv_b, out_b, ln2_g, ln2_b,
        ffn_b1, ffn_b2, pln_g, pln_b, out);
}

// round 11
// speedup vs baseline: 6.1686x; 1.0330x over previous
#include <cuda_runtime.h>
#include <cuda_fp16.h>
#include <cstdint>

#define WIN       16
#define STRIDE    8
#define L_SEQ     8192
#define NUM_WIN   1023
#define WPC       4
#define MROWS     64
#define NT        256

#define PQK       200        // s_qk pitch (halves): Q cols 0-95 (pre-scaled by 0.25), K cols 96-191
#define PVH       104        // s_v pitch (halves): V row-major 64x96
#define PAH       104        // s_a pitch (halves)
#define PGH       200        // s_g pitch (halves)

// smem byte offsets (regions alias across phases)
#define OFF_QK    0          // s_qk 64*200*2=25600 ; later s_h fp32 64*96*4=24576
#define OFF_V     25600      // s_v 64*104*2=13312 ; later s_g 64*200*2=25600 ; s_fin 24576
#define OFF_A     51200      // s_a 64*104*2=13312
#define SMEM_BYTES 64512

// packed B fragments: uint4 = b-frags for two consecutive k16 steps
// chunk layout: [kp][ntile(12)][lane(32)]; 96-K chunk = 3*12*32 = 1152 uint4
#define PB4_Q     0          // 3 chunks (Q,K,V)
#define PB4_O     3456
#define PB4_F1    4608       // 2 chunks
#define PB4_W2    6912       // K=192: 6*12*32 = 2304
#define PB4_TOTAL 9216

__device__ __align__(16) uint4 g_pb4[PB4_TOTAL];

__global__ void prep_kernel(const float* __restrict__ qkv_w,
                            const float* __restrict__ out_w,
                            const float* __restrict__ w1,
                            const float* __restrict__ w2,
                            float* __restrict__ out, int out_n) {
    int i = blockIdx.x * blockDim.x + threadIdx.x;
    if (i < out_n) out[i] = 0.0f;
    if (i < PB4_TOTAL) {
        const float* W; int ldn, colbase, rem;
        if (i < PB4_O)       { int ch = i / 1152; rem = i % 1152; W = qkv_w; ldn = 288; colbase = ch * 96; }
        else if (i < PB4_F1) { rem = i - PB4_O; W = out_w; ldn = 96; colbase = 0; }
        else if (i < PB4_W2) { int ch = (i - PB4_F1) / 1152; rem = (i - PB4_F1) % 1152; W = w1; ldn = 192; colbase = ch * 96; }
        else                 { rem = i - PB4_W2; W = w2; ldn = 96; colbase = 0; }
        int kp   = rem / (12 * 32);
        int r2   = rem % (12 * 32);
        int nt   = r2 / 32;
        int lane = r2 % 32;
        int n   = colbase + nt * 8 + (lane >> 2);
        int kb0 = (2 * kp) * 16 + (lane & 3) * 2;
        int kb1 = kb0 + 16;
        __half2 vx = __floats2half2_rn(W[(size_t)kb0 * ldn + n],       W[(size_t)(kb0 + 1) * ldn + n]);
        __half2 vy = __floats2half2_rn(W[(size_t)(kb0 + 8) * ldn + n], W[(size_t)(kb0 + 9) * ldn + n]);
        __half2 vz = __floats2half2_rn(W[(size_t)kb1 * ldn + n],       W[(size_t)(kb1 + 1) * ldn + n]);
        __half2 vw = __floats2half2_rn(W[(size_t)(kb1 + 8) * ldn + n], W[(size_t)(kb1 + 9) * ldn + n]);
        uint4 v;
        v.x = *(uint32_t*)&vx; v.y = *(uint32_t*)&vy;
        v.z = *(uint32_t*)&vz; v.w = *(uint32_t*)&vw;
        g_pb4[i] = v;
    }
}

// ---- PTX wrappers ----
__device__ __forceinline__ uint32_t smem_u32(const void* p) {
    return (uint32_t)__cvta_generic_to_shared(p);
}
__device__ __forceinline__ void ldsm_x4(uint32_t& r0, uint32_t& r1, uint32_t& r2, uint32_t& r3, uint32_t a) {
    asm volatile("ldmatrix.sync.aligned.m8n8.x4.shared.b16 {%0,%1,%2,%3}, [%4];"
                 : "=r"(r0), "=r"(r1), "=r"(r2), "=r"(r3) : "r"(a));
}
__device__ __forceinline__ void ldsm_x4_t(uint32_t& r0, uint32_t& r1, uint32_t& r2, uint32_t& r3, uint32_t a) {
    asm volatile("ldmatrix.sync.aligned.m8n8.x4.trans.shared.b16 {%0,%1,%2,%3}, [%4];"
                 : "=r"(r0), "=r"(r1), "=r"(r2), "=r"(r3) : "r"(a));
}
__device__ __forceinline__ void mma16816(float c[4], uint32_t a0, uint32_t a1, uint32_t a2, uint32_t a3,
                                         uint32_t b0, uint32_t b1) {
    asm volatile("mma.sync.aligned.m16n8k16.row.col.f32.f16.f16.f32 "
                 "{%0,%1,%2,%3}, {%4,%5,%6,%7}, {%8,%9}, {%0,%1,%2,%3};"
                 : "+f"(c[0]), "+f"(c[1]), "+f"(c[2]), "+f"(c[3])
                 : "r"(a0), "r"(a1), "r"(a2), "r"(a3), "r"(b0), "r"(b1));
}

__device__ __forceinline__ float gelu_tanh(float x) {
    float x3 = x * x * x;
    float inner = 0.7978845608028654f * fmaf(0.044715f, x3, x);
    return 0.5f * x * (1.0f + tanhf(inner));
}
__device__ __forceinline__ int row_pos(int w0, int row) {
    int p = (w0 + (row >> 4)) * STRIDE + (row & 15);
    return p < (L_SEQ - 1) ? p : (L_SEQ - 1);
}

// ---- K=96 GEMM over NC chunks with cached A fragments ----
// EPI 1: gelu->half (Ch pitch CPh, col c*96)   2: Cf = seg+acc   5: qkv special
//   (EPI 5: chunk0 -> Q*0.25 to Ch col 0; chunk1 -> K to Ch col 96; chunk2 -> V to Cv)
template <int NC, int EPI>
__device__ __forceinline__ void gemm6(uint32_t aBase, int aPitchH,
                                      const uint4* __restrict__ pb4,
                                      const float* __restrict__ bias,
                                      __half* __restrict__ Ch, int CPh,
                                      float* __restrict__ Cf,
                                      __half* __restrict__ Cv,
                                      const float* __restrict__ xb, int w0, int tid) {
    const int lane = tid & 31, wid = tid >> 5;
    const int strip = wid & 3;       // 16-row M strip
    const int nq = wid >> 2;         // 48-col N half
    const int g = lane >> 2, t = lane & 3;
    const int l15 = lane & 15;
    const int hi8 = (lane >= 16) ? 8 : 0;

    const uint32_t aOff = aBase + (uint32_t)((strip * 16 + l15) * aPitchH + hi8) * 2;
    uint32_t a[6][4];
#pragma unroll
    for (int k16 = 0; k16 < 6; k16++)
        ldsm_x4(a[k16][0], a[k16][1], a[k16][2], a[k16][3], aOff + k16 * 32);

    const int ra = strip * 16 + g, rb = ra + 8;

#pragma unroll
    for (int c = 0; c < NC; c++) {
        float acc[6][4];
#pragma unroll
        for (int i = 0; i < 6; i++) {
            float2 bv = *(const float2*)(bias + c * 96 + nq * 48 + i * 8 + t * 2);
            acc[i][0] = bv.x; acc[i][1] = bv.y; acc[i][2] = bv.x; acc[i][3] = bv.y;
        }
        const uint4* pw = pb4 + c * 1152 + (nq * 6) * 32 + lane;
#pragma unroll
        for (int kp = 0; kp < 3; kp++) {
            uint4 bv[6];
#pragma unroll
            for (int i = 0; i < 6; i++) bv[i] = __ldg(&pw[(kp * 12 + i) * 32]);
#pragma unroll
            for (int i = 0; i < 6; i++) {
                mma16816(acc[i], a[2*kp][0], a[2*kp][1], a[2*kp][2], a[2*kp][3], bv[i].x, bv[i].y);
                mma16816(acc[i], a[2*kp+1][0], a[2*kp+1][1], a[2*kp+1][2], a[2*kp+1][3], bv[i].z, bv[i].w);
            }
        }
#pragma unroll
        for (int i = 0; i < 6; i++) {
            int j = nq * 48 + i * 8 + t * 2;
            if (EPI == 1) {
                *(__half2*)(Ch + ra * CPh + c * 96 + j) = __floats2half2_rn(gelu_tanh(acc[i][0]), gelu_tanh(acc[i][1]));
                *(__half2*)(Ch + rb * CPh + c * 96 + j) = __floats2half2_rn(gelu_tanh(acc[i][2]), gelu_tanh(acc[i][3]));
            } else if (EPI == 2) {
                float2 sa = *(const float2*)(xb + (size_t)row_pos(w0, ra) * 96 + j);
                float2 sb = *(const float2*)(xb + (size_t)row_pos(w0, rb) * 96 + j);
                *(float2*)(Cf + ra * 96 + j) = make_float2(sa.x + acc[i][0], sa.y + acc[i][1]);
                *(float2*)(Cf + rb * 96 + j) = make_float2(sb.x + acc[i][2], sb.y + acc[i][3]);
            } else {  // EPI 5 (qkv)
                if (c == 0) {   // Q, pre-scaled by 1/sqrt(d)=0.25
                    *(__half2*)(Ch + ra * CPh + j) = __floats2half2_rn(acc[i][0] * 0.25f, acc[i][1] * 0.25f);
                    *(__half2*)(Ch + rb * CPh + j) = __floats2half2_rn(acc[i][2] * 0.25f, acc[i][3] * 0.25f);
                } else if (c == 1) {   // K
                    *(__half2*)(Ch + ra * CPh + 96 + j) = __floats2half2_rn(acc[i][0], acc[i][1]);
                    *(__half2*)(Ch + rb * CPh + 96 + j) = __floats2half2_rn(acc[i][2], acc[i][3]);
                } else {               // V row-major
                    *(__half2*)(Cv + ra * PVH + j) = __floats2half2_rn(acc[i][0], acc[i][1]);
                    *(__half2*)(Cv + rb * PVH + j) = __floats2half2_rn(acc[i][2], acc[i][3]);
                }
            }
        }
    }
}

// ---- K=192 GEMM (ffn2), EPI: Cf += acc ----
__device__ __forceinline__ void gemm12_acc(uint32_t aBase, int aPitchH,
                                           const uint4* __restrict__ pb4,
                                           const float* __restrict__ bias,
                                           float* __restrict__ Cf, int tid) {
    const int lane = tid & 31, wid = tid >> 5;
    const int strip = wid & 3;
    const int nq = wid >> 2;
    const int g = lane >> 2, t = lane & 3;
    const int l15 = lane & 15;
    const int hi8 = (lane >= 16) ? 8 : 0;

    float acc[6][4];
#pragma unroll
    for (int i = 0; i < 6; i++) {
        float2 bv = *(const float2*)(bias + nq * 48 + i * 8 + t * 2);
        acc[i][0] = bv.x; acc[i][1] = bv.y; acc[i][2] = bv.x; acc[i][3] = bv.y;
    }
    const uint32_t aOff = aBase + (uint32_t)((strip * 16 + l15) * aPitchH + hi8) * 2;
    const uint4* pw = pb4 + (nq * 6) * 32 + lane;
#pragma unroll
    for (int kp = 0; kp < 6; kp++) {
        uint32_t a0[4], a1[4];
        ldsm_x4(a0[0], a0[1], a0[2], a0[3], aOff + (2 * kp) * 32);
        ldsm_x4(a1[0], a1[1], a1[2], a1[3], aOff + (2 * kp + 1) * 32);
        uint4 bv[6];
#pragma unroll
        for (int i = 0; i < 6; i++) bv[i] = __ldg(&pw[(kp * 12 + i) * 32]);
#pragma unroll
        for (int i = 0; i < 6; i++) {
            mma16816(acc[i], a0[0], a0[1], a0[2], a0[3], bv[i].x, bv[i].y);
            mma16816(acc[i], a1[0], a1[1], a1[2], a1[3], bv[i].z, bv[i].w);
        }
    }
    const int ra = strip * 16 + g, rb = ra + 8;
#pragma unroll
    for (int i = 0; i < 6; i++) {
        int j = nq * 48 + i * 8 + t * 2;
        float2 ca = *(const float2*)(Cf + ra * 96 + j);
        float2 cb = *(const float2*)(Cf + rb * 96 + j);
        *(float2*)(Cf + ra * 96 + j) = make_float2(ca.x + acc[i][0], ca.y + acc[i][1]);
        *(float2*)(Cf + rb * 96 + j) = make_float2(cb.x + acc[i][2], cb.y + acc[i][3]);
    }
}

// ---- tensor-core attention: 24 (win,head) pairs, 3 per warp ----
// Q pre-scaled by 0.25; no-max softmax (scores bounded, masked lanes -> p=0)
__device__ __forceinline__ void attn_mma(uint32_t uQK, uint32_t uV,
                                         __half* __restrict__ s_a, int tid) {
    const int lane = tid & 31, wid = tid >> 5;
    const int l15 = lane & 15;
    const int lh8 = (lane >= 16) ? 8 : 0;
    const int g = lane >> 2, t = lane & 3;
    const int c0 = 2 * t, c1 = 2 * t + 1, c2 = 2 * t + 8, c3 = 2 * t + 9;

#pragma unroll
    for (int it = 0; it < 3; it++) {
        const int pair = wid + it * 8;       // 0..23
        const int wi = pair / 6, h = pair % 6;
        const int rbase = wi * 16;

        uint32_t qA = uQK + (uint32_t)(((rbase + l15) * PQK + h * 16 + lh8) * 2);
        uint32_t kA = uQK + (uint32_t)(((rbase + l15) * PQK + 96 + h * 16 + lh8) * 2);
        uint32_t vA = uV  + (uint32_t)(((rbase + l15) * PVH + h * 16 + lh8) * 2);

        uint32_t a0, a1, a2, a3, k0, k1, k2, k3, v0, v1, v2, v3;
        ldsm_x4(a0, a1, a2, a3, qA);
        ldsm_x4(k0, k1, k2, k3, kA);
        ldsm_x4_t(v0, v1, v2, v3, vA);   // V row-major, transposed fragment

        float s0[4] = {0.f, 0.f, 0.f, 0.f};
        float s1[4] = {0.f, 0.f, 0.f, 0.f};
        mma16816(s0, a0, a1, a2, a3, k0, k2);   // S cols kt 0-7
        mma16816(s1, a0, a1, a2, a3, k1, k3);   // S cols kt 8-15

        // exp with causal mask (no max-subtraction; Q pre-scaled)
        int g8 = g + 8;
        float e00 = (c0 <= g)  ? __expf(s0[0]) : 0.f;
        float e01 = (c1 <= g)  ? __expf(s0[1]) : 0.f;
        float e02 = (c2 <= g)  ? __expf(s1[0]) : 0.f;
        float e03 = (c3 <= g)  ? __expf(s1[1]) : 0.f;
        float e10 = (c0 <= g8) ? __expf(s0[2]) : 0.f;
        float e11 = (c1 <= g8) ? __expf(s0[3]) : 0.f;
        float e12 = (c2 <= g8) ? __expf(s1[2]) : 0.f;
        float e13 = (c3 <= g8) ? __expf(s1[3]) : 0.f;

        float d0 = e00 + e01 + e02 + e03;
        float d1 = e10 + e11 + e12 + e13;
        d0 += __shfl_xor_sync(0xffffffffu, d0, 1);
        d0 += __shfl_xor_sync(0xffffffffu, d0, 2);
        d1 += __shfl_xor_sync(0xffffffffu, d1, 1);
        d1 += __shfl_xor_sync(0xffffffffu, d1, 2);
        float i0 = 1.0f / d0, i1 = 1.0f / d1;

        // P fragments (A-layout for PV mma)
        __half2 p0 = __floats2half2_rn(e00 * i0, e01 * i0);
        __half2 p1 = __floats2half2_rn(e10 * i1, e11 * i1);
        __half2 p2 = __floats2half2_rn(e02 * i0, e03 * i0);
        __half2 p3 = __floats2half2_rn(e12 * i1, e13 * i1);
        uint32_t pa0 = *(uint32_t*)&p0, pa1 = *(uint32_t*)&p1;
        uint32_t pa2 = *(uint32_t*)&p2, pa3 = *(uint32_t*)&p3;

        float o0[4] = {0.f, 0.f, 0.f, 0.f};
        float o1[4] = {0.f, 0.f, 0.f, 0.f};
        mma16816(o0, pa0, pa1, pa2, pa3, v0, v1);   // O cols d 0-7
        mma16816(o1, pa0, pa1, pa2, pa3, v2, v3);   // O cols d 8-15

        __half* ba = s_a + (rbase + g) * PAH + h * 16;
        __half* bb = s_a + (rbase + g8) * PAH + h * 16;
        *(__half2*)(ba + 2 * t)     = __floats2half2_rn(o0[0], o0[1]);
        *(__half2*)(ba + 8 + 2 * t) = __floats2half2_rn(o1[0], o1[1]);
        *(__half2*)(bb + 2 * t)     = __floats2half2_rn(o0[2], o0[3]);
        *(__half2*)(bb + 8 + 2 * t) = __floats2half2_rn(o1[2], o1[3]);
    }
}

// ---- LayerNorm 64x96, 4 threads/row ----
template <int OUT, int SRC>   // OUT 0: half->dst_h(PAH) 1: fp32->dst_f(96); SRC 0: smem(96) 1: gmem
__device__ __forceinline__ void ln64(const float* __restrict__ src, const float* __restrict__ xb, int w0,
                                     __half* __restrict__ dst_h, float* __restrict__ dst_f,
                                     const float* __restrict__ gg, const float* __restrict__ bb, int tid) {
    int row = tid >> 2, quarter = tid & 3;
    const float* rp = (SRC == 0) ? (src + row * 96 + quarter * 24)
                                 : (xb + (size_t)row_pos(w0, row) * 96 + quarter * 24);
    float4 v[6];
#pragma unroll
    for (int i = 0; i < 6; i++) v[i] = *(const float4*)(rp + i * 4);
    float s = 0.f;
#pragma unroll
    for (int i = 0; i < 6; i++) s += v[i].x + v[i].y + v[i].z + v[i].w;
    s += __shfl_xor_sync(0xffffffffu, s, 1);
    s += __shfl_xor_sync(0xffffffffu, s, 2);
    float mean = s * (1.0f / 96.0f);
    float q = 0.f;
#pragma unroll
    for (int i = 0; i < 6; i++) {
        float dx = v[i].x - mean, dy = v[i].y - mean;
        float dz = v[i].z - mean, dw = v[i].w - mean;
        q = fmaf(dx, dx, q); q = fmaf(dy, dy, q);
        q = fmaf(dz, dz, q); q = fmaf(dw, dw, q);
    }
    q += __shfl_xor_sync(0xffffffffu, q, 1);
    q += __shfl_xor_sync(0xffffffffu, q, 2);
    float rstd = rsqrtf(q * (1.0f / 96.0f) + 1e-5f);
#pragma unroll
    for (int i = 0; i < 6; i++) {
        int d = quarter * 24 + i * 4;
        float4 gv = *(const float4*)(gg + d);
        float4 bv = *(const float4*)(bb + d);
        float ox = (v[i].x - mean) * rstd * gv.x + bv.x;
        float oy = (v[i].y - mean) * rstd * gv.y + bv.y;
        float oz = (v[i].z - mean) * rstd * gv.z + bv.z;
        float ow = (v[i].w - mean) * rstd * gv.w + bv.w;
        if (OUT == 0) {
            *(__half2*)(dst_h + row * PAH + d)     = __floats2half2_rn(ox, oy);
            *(__half2*)(dst_h + row * PAH + d + 2) = __floats2half2_rn(oz, ow);
        } else {
            *(float4*)(dst_f + row * 96 + d) = make_float4(ox, oy, oz, ow);
        }
    }
}

__global__ void __launch_bounds__(NT, 3)
win_block_kernel(const float* __restrict__ x,
                 const float* __restrict__ ln1_g, const float* __restrict__ ln1_b,
                 const float* __restrict__ qkv_b,
                 const float* __restrict__ out_b,
                 const float* __restrict__ ln2_g, const float* __restrict__ ln2_b,
                 const float* __restrict__ ffn_b1, const float* __restrict__ ffn_b2,
                 const float* __restrict__ pln_g, const float* __restrict__ pln_b,
                 float* __restrict__ out) {
    extern __shared__ char sm[];
    __half* s_qk  = (__half*)(sm + OFF_QK);   // 64 x 200 (Q|K)
    __half* s_v   = (__half*)(sm + OFF_V);    // 64 x 104 (V row-major)
    __half* s_a   = (__half*)(sm + OFF_A);    // 64 x 104
    float*  s_h   = (float*)(sm + OFF_QK);    // alias (residual fp32)
    __half* s_g   = (__half*)(sm + OFF_V);    // alias (gelu out 64x200)
    float*  s_fin = (float*)(sm + OFF_V);     // alias (final LN fp32)

    const uint32_t uQK = smem_u32(s_qk);
    const uint32_t uV  = smem_u32(s_v);
    const uint32_t uA  = smem_u32(s_a);
    const uint32_t uG  = smem_u32(s_g);

    const int tid = threadIdx.x;
    const int w0  = blockIdx.x * WPC;
    const int b   = blockIdx.y;
    const float* xb = x + (size_t)b * L_SEQ * 96;

    // LN1: gmem -> s_a (half)
    ln64<0, 1>(nullptr, xb, w0, s_a, nullptr, ln1_g, ln1_b, tid);
    __syncthreads();

    // G1: Q(*0.25),K -> s_qk; V -> s_v row-major (A frags cached across chunks)
    gemm6<3, 5>(uA, PAH, g_pb4 + PB4_Q, qkv_b, s_qk, PQK, nullptr, s_v, xb, w0, tid);
    __syncthreads();

    // attention (tensor cores) -> s_a
    attn_mma(uQK, uV, s_a, tid);
    __syncthreads();

    // G2: s_h = seg + attn @ Wo + bo  (aliases dead s_qk)
    gemm6<1, 2>(uA, PAH, g_pb4 + PB4_O, out_b, nullptr, 0, s_h, nullptr, xb, w0, tid);
    __syncthreads();

    // LN2: s_h -> s_a
    ln64<0, 0>(s_h, nullptr, 0, s_a, nullptr, ln2_g, ln2_b, tid);
    __syncthreads();

    // G3: gelu(s_a @ W1 + b1) -> s_g (aliases dead s_v)
    gemm6<2, 1>(uA, PAH, g_pb4 + PB4_F1, ffn_b1, s_g, PGH, nullptr, nullptr, xb, w0, tid);
    __syncthreads();

    // G4: s_h += s_g @ W2 + b2
    gemm12_acc(uG, PGH, g_pb4 + PB4_W2, ffn_b2, s_h, tid);
    __syncthreads();

    // final LN: s_h -> s_fin
    ln64<1, 0>(s_h, nullptr, 0, nullptr, s_fin, pln_g, pln_b, tid);
    __syncthreads();

    // scatter: intra-CTA overlaps combined; atomics only at CTA boundaries
    int nw = NUM_WIN - w0; if (nw > WPC) nw = WPC;
    const int LP = nw * 8 + 8;
    for (int i = tid; i < LP * 96; i += NT) {
        int lp = i / 96, d = i - lp * 96;
        int pos = w0 * STRIDE + lp;
        size_t oidx = ((size_t)b * L_SEQ + pos) * 96 + d;
        if (lp >= 8 && lp < nw * 8) {
            int wiH = lp >> 3, r = lp & 7;
            float vH = s_fin[(wiH * 16 + r) * 96 + d];
            float vL = s_fin[((wiH - 1) * 16 + r + 8) * 96 + d];
            out[oidx] = (vH + vL) * 0.5f;
        } else if (lp < 8) {
            float invc = (pos < STRIDE) ? 1.0f : 0.5f;
            atomicAdd(out + oidx, s_fin[lp * 96 + d] * invc);
        } else {
            int r = lp - (nw - 1) * 8;
            float invc = (pos >= L_SEQ - STRIDE) ? 1.0f : 0.5f;
            atomicAdd(out + oidx, s_fin[((nw - 1) * 16 + r) * 96 + d] * invc);
        }
    }
}

extern "C" void kernel_launch(void* const* d_in, const int* in_sizes, int n_in,
                              void* d_out, int out_size) {
    const float* x      = (const float*)d_in[0];
    const float* ln1_g  = (const float*)d_in[1];
    const float* ln1_b  = (const float*)d_in[2];
    const float* qkv_w  = (const float*)d_in[3];
    const float* qkv_b  = (const float*)d_in[4];
    const float* out_w  = (const float*)d_in[5];
    const float* out_b  = (const float*)d_in[6];
    const float* ln2_g  = (const float*)d_in[7];
    const float* ln2_b  = (const float*)d_in[8];
    const float* ffn_w1 = (const float*)d_in[9];
    const float* ffn_b1 = (const float*)d_in[10];
    const float* ffn_w2 = (const float*)d_in[11];
    const float* ffn_b2 = (const float*)d_in[12];
    const float* pln_g  = (const float*)d_in[13];
    const float* pln_b  = (const float*)d_in[14];
    float* out = (float*)d_out;

    const int B = in_sizes[0] / (L_SEQ * 96);
    const int nblk = (NUM_WIN + WPC - 1) / WPC;   // 256

    static int attr_set = 0;
    if (!attr_set) {
        cudaFuncSetAttribute(win_block_kernel,
                             cudaFuncAttributeMaxDynamicSharedMemorySize, SMEM_BYTES);
        attr_set = 1;
    }

    prep_kernel<<<(out_size + 255) / 256, 256>>>(qkv_w, out_w, ffn_w1, ffn_w2, out, out_size);

    dim3 grid(nblk, B);
    win_block_kernel<<<grid, NT, SMEM_BYTES>>>(
        x, ln1_g, ln1_b, qkv_b, out_b, ln2_g, ln2_b,
        ffn_b1, ffn_b2, pln_g, pln_b, out);
}

// round 12
// speedup vs baseline: 7.1653x; 1.1616x over previous
#include <cuda_runtime.h>
#include <cuda_fp16.h>
#include <cstdint>

#define WIN       16
#define STRIDE    8
#define L_SEQ     8192
#define NUM_WIN   1023
#define WPC       8
#define MROWS     128
#define NT        256

#define PQK       200        // s_qk pitch (halves): Q (pre-scaled) cols 0-95, K cols 96-191
#define PVH       104        // s_v pitch (halves)
#define PAH       104        // s_a pitch (halves)
#define PGH       200        // s_g pitch (halves)

// smem regions (aliased across phases):
// QK region: s_qk (128x200x2=51200) -> s_g (51200) -> s_fin fp32 (49152)
// V  region: s_v (128x104x2=26624) -> s_h half 128x96x2=24576
// A  region: s_a (128x104x2=26624)
#define OFF_QK    0
#define OFF_V     51200
#define OFF_A     77824
#define SMEM_BYTES 104448

// packed B fragments: uint4 = b-frags for two consecutive k16 steps
// chunk layout: [kp][ntile(12)][lane(32)]; 96-K chunk = 3*12*32 = 1152 uint4
#define PB4_Q     0          // 3 chunks (Q,K,V)
#define PB4_O     3456
#define PB4_F1    4608       // 2 chunks
#define PB4_W2    6912       // K=192: 6*12*32 = 2304
#define PB4_TOTAL 9216

__device__ __align__(16) uint4 g_pb4[PB4_TOTAL];

__global__ void prep_kernel(const float* __restrict__ qkv_w,
                            const float* __restrict__ out_w,
                            const float* __restrict__ w1,
                            const float* __restrict__ w2,
                            float* __restrict__ out, int out_n) {
    int i = blockIdx.x * blockDim.x + threadIdx.x;
    if (i < out_n) out[i] = 0.0f;
    if (i < PB4_TOTAL) {
        const float* W; int ldn, colbase, rem;
        if (i < PB4_O)       { int ch = i / 1152; rem = i % 1152; W = qkv_w; ldn = 288; colbase = ch * 96; }
        else if (i < PB4_F1) { rem = i - PB4_O; W = out_w; ldn = 96; colbase = 0; }
        else if (i < PB4_W2) { int ch = (i - PB4_F1) / 1152; rem = (i - PB4_F1) % 1152; W = w1; ldn = 192; colbase = ch * 96; }
        else                 { rem = i - PB4_W2; W = w2; ldn = 96; colbase = 0; }
        int kp   = rem / (12 * 32);
        int r2   = rem % (12 * 32);
        int nt   = r2 / 32;
        int lane = r2 % 32;
        int n   = colbase + nt * 8 + (lane >> 2);
        int kb0 = (2 * kp) * 16 + (lane & 3) * 2;
        int kb1 = kb0 + 16;
        __half2 vx = __floats2half2_rn(W[(size_t)kb0 * ldn + n],       W[(size_t)(kb0 + 1) * ldn + n]);
        __half2 vy = __floats2half2_rn(W[(size_t)(kb0 + 8) * ldn + n], W[(size_t)(kb0 + 9) * ldn + n]);
        __half2 vz = __floats2half2_rn(W[(size_t)kb1 * ldn + n],       W[(size_t)(kb1 + 1) * ldn + n]);
        __half2 vw = __floats2half2_rn(W[(size_t)(kb1 + 8) * ldn + n], W[(size_t)(kb1 + 9) * ldn + n]);
        uint4 v;
        v.x = *(uint32_t*)&vx; v.y = *(uint32_t*)&vy;
        v.z = *(uint32_t*)&vz; v.w = *(uint32_t*)&vw;
        g_pb4[i] = v;
    }
}

// ---- PTX wrappers ----
__device__ __forceinline__ uint32_t smem_u32(const void* p) {
    return (uint32_t)__cvta_generic_to_shared(p);
}
__device__ __forceinline__ void ldsm_x4(uint32_t& r0, uint32_t& r1, uint32_t& r2, uint32_t& r3, uint32_t a) {
    asm volatile("ldmatrix.sync.aligned.m8n8.x4.shared.b16 {%0,%1,%2,%3}, [%4];"
                 : "=r"(r0), "=r"(r1), "=r"(r2), "=r"(r3) : "r"(a));
}
__device__ __forceinline__ void ldsm_x4_t(uint32_t& r0, uint32_t& r1, uint32_t& r2, uint32_t& r3, uint32_t a) {
    asm volatile("ldmatrix.sync.aligned.m8n8.x4.trans.shared.b16 {%0,%1,%2,%3}, [%4];"
                 : "=r"(r0), "=r"(r1), "=r"(r2), "=r"(r3) : "r"(a));
}
__device__ __forceinline__ void mma16816(float c[4], uint32_t a0, uint32_t a1, uint32_t a2, uint32_t a3,
                                         uint32_t b0, uint32_t b1) {
    asm volatile("mma.sync.aligned.m16n8k16.row.col.f32.f16.f16.f32 "
                 "{%0,%1,%2,%3}, {%4,%5,%6,%7}, {%8,%9}, {%0,%1,%2,%3};"
                 : "+f"(c[0]), "+f"(c[1]), "+f"(c[2]), "+f"(c[3])
                 : "r"(a0), "r"(a1), "r"(a2), "r"(a3), "r"(b0), "r"(b1));
}

__device__ __forceinline__ float gelu_tanh(float x) {
    float x3 = x * x * x;
    float inner = 0.7978845608028654f * fmaf(0.044715f, x3, x);
    return 0.5f * x * (1.0f + tanhf(inner));
}
__device__ __forceinline__ int row_pos(int w0, int row) {
    int p = (w0 + (row >> 4)) * STRIDE + (row & 15);
    return p < (L_SEQ - 1) ? p : (L_SEQ - 1);
}

// ---- M=128 GEMM: 4 strips (32 rows) x 2 N-halves (48 cols), K=96 per chunk ----
// EPI 1: gelu->half Ch(col c*96)   2: half Hh = seg(gmem)+acc   5: qkv special
template <int NC, int EPI>
__device__ __forceinline__ void gemmM(uint32_t aBase,
                                      const uint4* __restrict__ pb4,
                                      const float* __restrict__ bias,
                                      __half* __restrict__ Ch, int CPh,
                                      __half* __restrict__ Hh,
                                      __half* __restrict__ Cv,
                                      const float* __restrict__ xb, int w0, int tid) {
    const int lane = tid & 31, wid = tid >> 5;
    const int strip = wid & 3;       // 32-row M strip
    const int nq = wid >> 2;         // 48-col N half
    const int g = lane >> 2, t = lane & 3;
    const int l15 = lane & 15;
    const int hi8 = (lane >= 16) ? 8 : 0;
    const uint32_t aRow = aBase + (uint32_t)((strip * 32 + l15) * PAH + hi8) * 2;

#pragma unroll
    for (int c = 0; c < NC; c++) {
        float acc[2][6][4];
#pragma unroll
        for (int i = 0; i < 6; i++) {
            float2 bv = *(const float2*)(bias + c * 96 + nq * 48 + i * 8 + t * 2);
#pragma unroll
            for (int rt = 0; rt < 2; rt++) {
                acc[rt][i][0] = bv.x; acc[rt][i][1] = bv.y;
                acc[rt][i][2] = bv.x; acc[rt][i][3] = bv.y;
            }
        }
        const uint4* pw = pb4 + c * 1152 + (nq * 6) * 32 + lane;
#pragma unroll
        for (int kp = 0; kp < 3; kp++) {
            uint4 bv[6];
#pragma unroll
            for (int i = 0; i < 6; i++) bv[i] = __ldg(&pw[(kp * 12 + i) * 32]);
#pragma unroll
            for (int rt = 0; rt < 2; rt++) {
                uint32_t rtOff = aRow + (uint32_t)(rt * 16 * PAH) * 2;
                uint32_t a0, a1, a2, a3;
                ldsm_x4(a0, a1, a2, a3, rtOff + (2 * kp) * 32);
#pragma unroll
                for (int i = 0; i < 6; i++)
                    mma16816(acc[rt][i], a0, a1, a2, a3, bv[i].x, bv[i].y);
                ldsm_x4(a0, a1, a2, a3, rtOff + (2 * kp + 1) * 32);
#pragma unroll
                for (int i = 0; i < 6; i++)
                    mma16816(acc[rt][i], a0, a1, a2, a3, bv[i].z, bv[i].w);
            }
        }
#pragma unroll
        for (int rt = 0; rt < 2; rt++) {
            const int ra = strip * 32 + rt * 16 + g, rb = ra + 8;
#pragma unroll
            for (int i = 0; i < 6; i++) {
                int j = nq * 48 + i * 8 + t * 2;
                if (EPI == 1) {
                    *(__half2*)(Ch + ra * CPh + c * 96 + j) = __floats2half2_rn(gelu_tanh(acc[rt][i][0]), gelu_tanh(acc[rt][i][1]));
                    *(__half2*)(Ch + rb * CPh + c * 96 + j) = __floats2half2_rn(gelu_tanh(acc[rt][i][2]), gelu_tanh(acc[rt][i][3]));
                } else if (EPI == 2) {
                    float2 sa = *(const float2*)(xb + (size_t)row_pos(w0, ra) * 96 + j);
                    float2 sb = *(const float2*)(xb + (size_t)row_pos(w0, rb) * 96 + j);
                    *(__half2*)(Hh + ra * 96 + j) = __floats2half2_rn(sa.x + acc[rt][i][0], sa.y + acc[rt][i][1]);
                    *(__half2*)(Hh + rb * 96 + j) = __floats2half2_rn(sb.x + acc[rt][i][2], sb.y + acc[rt][i][3]);
                } else {  // EPI 5 (qkv)
                    if (c == 0) {   // Q pre-scaled by 0.25
                        *(__half2*)(Ch + ra * CPh + j) = __floats2half2_rn(acc[rt][i][0] * 0.25f, acc[rt][i][1] * 0.25f);
                        *(__half2*)(Ch + rb * CPh + j) = __floats2half2_rn(acc[rt][i][2] * 0.25f, acc[rt][i][3] * 0.25f);
                    } else if (c == 1) {   // K
                        *(__half2*)(Ch + ra * CPh + 96 + j) = __floats2half2_rn(acc[rt][i][0], acc[rt][i][1]);
                        *(__half2*)(Ch + rb * CPh + 96 + j) = __floats2half2_rn(acc[rt][i][2], acc[rt][i][3]);
                    } else {               // V row-major
                        *(__half2*)(Cv + ra * PVH + j) = __floats2half2_rn(acc[rt][i][0], acc[rt][i][1]);
                        *(__half2*)(Cv + rb * PVH + j) = __floats2half2_rn(acc[rt][i][2], acc[rt][i][3]);
                    }
                }
            }
        }
    }
}

// ---- K=192 GEMM (ffn2): Hh(half) += acc ----
__device__ __forceinline__ void gemmW2(uint32_t aBase,
                                       const uint4* __restrict__ pb4,
                                       const float* __restrict__ bias,
                                       __half* __restrict__ Hh, int tid) {
    const int lane = tid & 31, wid = tid >> 5;
    const int strip = wid & 3;
    const int nq = wid >> 2;
    const int g = lane >> 2, t = lane & 3;
    const int l15 = lane & 15;
    const int hi8 = (lane >= 16) ? 8 : 0;
    const uint32_t aRow = aBase + (uint32_t)((strip * 32 + l15) * PGH + hi8) * 2;

    float acc[2][6][4];
#pragma unroll
    for (int i = 0; i < 6; i++) {
        float2 bv = *(const float2*)(bias + nq * 48 + i * 8 + t * 2);
#pragma unroll
        for (int rt = 0; rt < 2; rt++) {
            acc[rt][i][0] = bv.x; acc[rt][i][1] = bv.y;
            acc[rt][i][2] = bv.x; acc[rt][i][3] = bv.y;
        }
    }
    const uint4* pw = pb4 + (nq * 6) * 32 + lane;
#pragma unroll
    for (int kp = 0; kp < 6; kp++) {
        uint4 bv[6];
#pragma unroll
        for (int i = 0; i < 6; i++) bv[i] = __ldg(&pw[(kp * 12 + i) * 32]);
#pragma unroll
        for (int rt = 0; rt < 2; rt++) {
            uint32_t rtOff = aRow + (uint32_t)(rt * 16 * PGH) * 2;
            uint32_t a0, a1, a2, a3;
            ldsm_x4(a0, a1, a2, a3, rtOff + (2 * kp) * 32);
#pragma unroll
            for (int i = 0; i < 6; i++)
                mma16816(acc[rt][i], a0, a1, a2, a3, bv[i].x, bv[i].y);
            ldsm_x4(a0, a1, a2, a3, rtOff + (2 * kp + 1) * 32);
#pragma unroll
            for (int i = 0; i < 6; i++)
                mma16816(acc[rt][i], a0, a1, a2, a3, bv[i].z, bv[i].w);
        }
    }
#pragma unroll
    for (int rt = 0; rt < 2; rt++) {
        const int ra = strip * 32 + rt * 16 + g, rb = ra + 8;
#pragma unroll
        for (int i = 0; i < 6; i++) {
            int j = nq * 48 + i * 8 + t * 2;
            float2 ca = __half22float2(*(__half2*)(Hh + ra * 96 + j));
            float2 cb = __half22float2(*(__half2*)(Hh + rb * 96 + j));
            *(__half2*)(Hh + ra * 96 + j) = __floats2half2_rn(ca.x + acc[rt][i][0], ca.y + acc[rt][i][1]);
            *(__half2*)(Hh + rb * 96 + j) = __floats2half2_rn(cb.x + acc[rt][i][2], cb.y + acc[rt][i][3]);
        }
    }
}

// ---- tensor-core attention: 48 (win,head) pairs, 6 per warp ----
__device__ __forceinline__ void attn_mma(uint32_t uQK, uint32_t uV,
                                         __half* __restrict__ s_a, int tid) {
    const int lane = tid & 31, wid = tid >> 5;
    const int l15 = lane & 15;
    const int lh8 = (lane >= 16) ? 8 : 0;
    const int g = lane >> 2, t = lane & 3;
    const int c0 = 2 * t, c1 = 2 * t + 1, c2 = 2 * t + 8, c3 = 2 * t + 9;

#pragma unroll
    for (int it = 0; it < 6; it++) {
        const int pair = wid + it * 8;       // 0..47
        const int wi = pair / 6, h = pair % 6;
        const int rbase = wi * 16;

        uint32_t qA = uQK + (uint32_t)(((rbase + l15) * PQK + h * 16 + lh8) * 2);
        uint32_t kA = uQK + (uint32_t)(((rbase + l15) * PQK + 96 + h * 16 + lh8) * 2);
        uint32_t vA = uV  + (uint32_t)(((rbase + l15) * PVH + h * 16 + lh8) * 2);

        uint32_t a0, a1, a2, a3, k0, k1, k2, k3, v0, v1, v2, v3;
        ldsm_x4(a0, a1, a2, a3, qA);
        ldsm_x4(k0, k1, k2, k3, kA);
        ldsm_x4_t(v0, v1, v2, v3, vA);

        float s0[4] = {0.f, 0.f, 0.f, 0.f};
        float s1[4] = {0.f, 0.f, 0.f, 0.f};
        mma16816(s0, a0, a1, a2, a3, k0, k2);
        mma16816(s1, a0, a1, a2, a3, k1, k3);

        int g8 = g + 8;
        float e00 = (c0 <= g)  ? __expf(s0[0]) : 0.f;
        float e01 = (c1 <= g)  ? __expf(s0[1]) : 0.f;
        float e02 = (c2 <= g)  ? __expf(s1[0]) : 0.f;
        float e03 = (c3 <= g)  ? __expf(s1[1]) : 0.f;
        float e10 = (c0 <= g8) ? __expf(s0[2]) : 0.f;
        float e11 = (c1 <= g8) ? __expf(s0[3]) : 0.f;
        float e12 = (c2 <= g8) ? __expf(s1[2]) : 0.f;
        float e13 = (c3 <= g8) ? __expf(s1[3]) : 0.f;

        float d0 = e00 + e01 + e02 + e03;
        float d1 = e10 + e11 + e12 + e13;
        d0 += __shfl_xor_sync(0xffffffffu, d0, 1);
        d0 += __shfl_xor_sync(0xffffffffu, d0, 2);
        d1 += __shfl_xor_sync(0xffffffffu, d1, 1);
        d1 += __shfl_xor_sync(0xffffffffu, d1, 2);
        float i0 = 1.0f / d0, i1 = 1.0f / d1;

        __half2 p0 = __floats2half2_rn(e00 * i0, e01 * i0);
        __half2 p1 = __floats2half2_rn(e10 * i1, e11 * i1);
        __half2 p2 = __floats2half2_rn(e02 * i0, e03 * i0);
        __half2 p3 = __floats2half2_rn(e12 * i1, e13 * i1);
        uint32_t pa0 = *(uint32_t*)&p0, pa1 = *(uint32_t*)&p1;
        uint32_t pa2 = *(uint32_t*)&p2, pa3 = *(uint32_t*)&p3;

        float o0[4] = {0.f, 0.f, 0.f, 0.f};
        float o1[4] = {0.f, 0.f, 0.f, 0.f};
        mma16816(o0, pa0, pa1, pa2, pa3, v0, v1);
        mma16816(o1, pa0, pa1, pa2, pa3, v2, v3);

        __half* ba = s_a + (rbase + g) * PAH + h * 16;
        __half* bb = s_a + (rbase + g8) * PAH + h * 16;
        *(__half2*)(ba + 2 * t)     = __floats2half2_rn(o0[0], o0[1]);
        *(__half2*)(ba + 8 + 2 * t) = __floats2half2_rn(o1[0], o1[1]);
        *(__half2*)(bb + 2 * t)     = __floats2half2_rn(o0[2], o0[3]);
        *(__half2*)(bb + 8 + 2 * t) = __floats2half2_rn(o1[2], o1[3]);
    }
}

// ---- LayerNorm 128x96, 2 threads/row ----
// OUT 0: half->dst_h(PAH)  1: fp32->dst_f(96).  SRC 0: half smem (96)  1: gmem fp32 rows
template <int OUT, int SRC>
__device__ __forceinline__ void ln128(const __half* __restrict__ srcH, const float* __restrict__ xb, int w0,
                                      __half* __restrict__ dst_h, float* __restrict__ dst_f,
                                      const float* __restrict__ gg, const float* __restrict__ bb, int tid) {
    int row = tid >> 1, hf = tid & 1;
    float v[48];
    if (SRC == 1) {
        const float* rp = xb + (size_t)row_pos(w0, row) * 96 + hf * 48;
#pragma unroll
        for (int i = 0; i < 12; i++) {
            float4 f = *(const float4*)(rp + i * 4);
            v[4*i] = f.x; v[4*i+1] = f.y; v[4*i+2] = f.z; v[4*i+3] = f.w;
        }
    } else {
        const __half2* rp = (const __half2*)(srcH + row * 96 + hf * 48);
#pragma unroll
        for (int i = 0; i < 24; i++) {
            float2 f = __half22float2(rp[i]);
            v[2*i] = f.x; v[2*i+1] = f.y;
        }
    }
    float s = 0.f;
#pragma unroll
    for (int i = 0; i < 48; i++) s += v[i];
    s += __shfl_xor_sync(0xffffffffu, s, 1);
    float mean = s * (1.0f / 96.0f);
    float q = 0.f;
#pragma unroll
    for (int i = 0; i < 48; i++) { float d = v[i] - mean; q = fmaf(d, d, q); }
    q += __shfl_xor_sync(0xffffffffu, q, 1);
    float rstd = rsqrtf(q * (1.0f / 96.0f) + 1e-5f);
#pragma unroll
    for (int i = 0; i < 24; i++) {
        int d = hf * 48 + i * 2;
        float2 gv = *(const float2*)(gg + d);
        float2 bv = *(const float2*)(bb + d);
        float ox = (v[2*i]   - mean) * rstd * gv.x + bv.x;
        float oy = (v[2*i+1] - mean) * rstd * gv.y + bv.y;
        if (OUT == 0) {
            *(__half2*)(dst_h + row * PAH + d) = __floats2half2_rn(ox, oy);
        } else {
            *(float2*)(dst_f + row * 96 + d) = make_float2(ox, oy);
        }
    }
}

__global__ void __launch_bounds__(NT, 2)
win_block_kernel(const float* __restrict__ x,
                 const float* __restrict__ ln1_g, const float* __restrict__ ln1_b,
                 const float* __restrict__ qkv_b,
                 const float* __restrict__ out_b,
                 const float* __restrict__ ln2_g, const float* __restrict__ ln2_b,
                 const float* __restrict__ ffn_b1, const float* __restrict__ ffn_b2,
                 const float* __restrict__ pln_g, const float* __restrict__ pln_b,
                 float* __restrict__ out) {
    extern __shared__ char sm[];
    __half* s_qk  = (__half*)(sm + OFF_QK);   // 128 x 200 (Q|K)
    __half* s_v   = (__half*)(sm + OFF_V);    // 128 x 104 (V row-major)
    __half* s_a   = (__half*)(sm + OFF_A);    // 128 x 104
    __half* s_g   = (__half*)(sm + OFF_QK);   // alias (gelu out 128x200)
    float*  s_fin = (float*)(sm + OFF_QK);    // alias (final LN fp32 128x96)
    __half* s_h   = (__half*)(sm + OFF_V);    // alias (residual half 128x96)

    const uint32_t uQK = smem_u32(s_qk);
    const uint32_t uV  = smem_u32(s_v);
    const uint32_t uA  = smem_u32(s_a);
    const uint32_t uG  = smem_u32(s_g);

    const int tid = threadIdx.x;
    const int w0  = blockIdx.x * WPC;
    const int b   = blockIdx.y;
    const float* xb = x + (size_t)b * L_SEQ * 96;

    // LN1: gmem -> s_a (half)
    ln128<0, 1>(nullptr, xb, w0, s_a, nullptr, ln1_g, ln1_b, tid);
    __syncthreads();

    // G1: Q(*0.25),K -> s_qk; V -> s_v
    gemmM<3, 5>(uA, g_pb4 + PB4_Q, qkv_b, s_qk, PQK, nullptr, s_v, xb, w0, tid);
    __syncthreads();

    // attention -> s_a
    attn_mma(uQK, uV, s_a, tid);
    __syncthreads();

    // G2: s_h(half) = seg + attn @ Wo + bo  (s_h aliases dead s_v... V region)
    gemmM<1, 2>(uA, g_pb4 + PB4_O, out_b, nullptr, 0, s_h, nullptr, xb, w0, tid);
    __syncthreads();

    // LN2: s_h -> s_a
    ln128<0, 0>(s_h, nullptr, 0, s_a, nullptr, ln2_g, ln2_b, tid);
    __syncthreads();

    // G3: gelu(s_a @ W1 + b1) -> s_g (aliases dead s_qk)
    gemmM<2, 1>(uA, g_pb4 + PB4_F1, ffn_b1, s_g, PGH, nullptr, nullptr, xb, w0, tid);
    __syncthreads();

    // G4: s_h += s_g @ W2 + b2
    gemmW2(uG, g_pb4 + PB4_W2, ffn_b2, s_h, tid);
    __syncthreads();

    // final LN: s_h -> s_fin (fp32, QK region; s_g dead)
    ln128<1, 0>(s_h, nullptr, 0, nullptr, s_fin, pln_g, pln_b, tid);
    __syncthreads();

    // scatter: intra-CTA overlaps combined; atomics only at CTA boundaries
    int nw = NUM_WIN - w0; if (nw > WPC) nw = WPC;
    const int LP = nw * 8 + 8;
    for (int i = tid; i < LP * 96; i += NT) {
        int lp = i / 96, d = i - lp * 96;
        int pos = w0 * STRIDE + lp;
        size_t oidx = ((size_t)b * L_SEQ + pos) * 96 + d;
        if (lp >= 8 && lp < nw * 8) {
            int wiH = lp >> 3, r = lp & 7;
            float vH = s_fin[(wiH * 16 + r) * 96 + d];
            float vL = s_fin[((wiH - 1) * 16 + r + 8) * 96 + d];
            out[oidx] = (vH + vL) * 0.5f;
        } else if (lp < 8) {
            float invc = (pos < STRIDE) ? 1.0f : 0.5f;
            atomicAdd(out + oidx, s_fin[lp * 96 + d] * invc);
        } else {
            int r = lp - (nw - 1) * 8;
            float invc = (pos >= L_SEQ - STRIDE) ? 1.0f : 0.5f;
            atomicAdd(out + oidx, s_fin[((nw - 1) * 16 + r) * 96 + d] * invc);
        }
    }
}

extern "C" void kernel_launch(void* const* d_in, const int* in_sizes, int n_in,
                              void* d_out, int out_size) {
    const float* x      = (const float*)d_in[0];
    const float* ln1_g  = (const float*)d_in[1];
    const float* ln1_b  = (const float*)d_in[2];
    const float* qkv_w  = (const float*)d_in[3];
    const float* qkv_b  = (const float*)d_in[4];
    const float* out_w  = (const float*)d_in[5];
    const float* out_b  = (const float*)d_in[6];
    const float* ln2_g  = (const float*)d_in[7];
    const float* ln2_b  = (const float*)d_in[8];
    const float* ffn_w1 = (const float*)d_in[9];
    const float* ffn_b1 = (const float*)d_in[10];
    const float* ffn_w2 = (const float*)d_in[11];
    const float* ffn_b2 = (const float*)d_in[12];
    const float* pln_g  = (const float*)d_in[13];
    const float* pln_b  = (const float*)d_in[14];
    float* out = (float*)d_out;

    const int B = in_sizes[0] / (L_SEQ * 96);
    const int nblk = (NUM_WIN + WPC - 1) / WPC;   // 128

    static int attr_set = 0;
    if (!attr_set) {
        cudaFuncSetAttribute(win_block_kernel,
                             cudaFuncAttributeMaxDynamicSharedMemorySize, SMEM_BYTES);
        attr_set = 1;
    }

    prep_kernel<<<(out_size + 255) / 256, 256>>>(qkv_w, out_w, ffn_w1, ffn_w2, out, out_size);

    dim3 grid(nblk, B);
    win_block_kernel<<<grid, NT, SMEM_BYTES>>>(
        x, ln1_g, ln1_b, qkv_b, out_b, ln2_g, ln2_b,
        ffn_b1, ffn_b2, pln_g, pln_b, out);
}

// round 13
// speedup vs baseline: 7.1699x; 1.0006x over previous
#include <cuda_runtime.h>
#include <cuda_fp16.h>
#include <cstdint>

#define WIN       16
#define STRIDE    8
#define L_SEQ     8192
#define NUM_WIN   1023
#define WPC       8
#define MROWS     128
#define NT        256

#define PQK       200        // s_qk pitch (halves): Q (pre-scaled) cols 0-95, K cols 96-191
#define PVH       104        // s_v pitch (halves)
#define PAH       104        // s_a pitch (halves)
#define PGH       200        // s_g pitch (halves)

// smem regions (aliased across phases):
// QK region: s_qk (128x200x2=51200) -> s_g (51200) -> s_fin fp32 (49152)
// V  region: s_v (128x104x2=26624) -> s_h half 128x96x2=24576
// A  region: s_a (128x104x2=26624)
#define OFF_QK    0
#define OFF_V     51200
#define OFF_A     77824
#define SMEM_BYTES 104448

// packed B fragments: uint4 = b-frags for two consecutive k16 steps
// chunk layout: [kp][ntile(12)][lane(32)]; 96-K chunk = 3*12*32 = 1152 uint4
#define PB4_Q     0          // 3 chunks (Q,K,V)
#define PB4_O     3456
#define PB4_F1    4608       // 2 chunks
#define PB4_W2    6912       // K=192: 6*12*32 = 2304
#define PB4_TOTAL 9216

__device__ __align__(16) uint4 g_pb4[PB4_TOTAL];

__global__ void prep_kernel(const float* __restrict__ qkv_w,
                            const float* __restrict__ out_w,
                            const float* __restrict__ w1,
                            const float* __restrict__ w2,
                            float* __restrict__ out, int out_n) {
    int i = blockIdx.x * blockDim.x + threadIdx.x;
    if (i < out_n) out[i] = 0.0f;
    if (i < PB4_TOTAL) {
        const float* W; int ldn, colbase, rem;
        if (i < PB4_O)       { int ch = i / 1152; rem = i % 1152; W = qkv_w; ldn = 288; colbase = ch * 96; }
        else if (i < PB4_F1) { rem = i - PB4_O; W = out_w; ldn = 96; colbase = 0; }
        else if (i < PB4_W2) { int ch = (i - PB4_F1) / 1152; rem = (i - PB4_F1) % 1152; W = w1; ldn = 192; colbase = ch * 96; }
        else                 { rem = i - PB4_W2; W = w2; ldn = 96; colbase = 0; }
        int kp   = rem / (12 * 32);
        int r2   = rem % (12 * 32);
        int nt   = r2 / 32;
        int lane = r2 % 32;
        int n   = colbase + nt * 8 + (lane >> 2);
        int kb0 = (2 * kp) * 16 + (lane & 3) * 2;
        int kb1 = kb0 + 16;
        __half2 vx = __floats2half2_rn(W[(size_t)kb0 * ldn + n],       W[(size_t)(kb0 + 1) * ldn + n]);
        __half2 vy = __floats2half2_rn(W[(size_t)(kb0 + 8) * ldn + n], W[(size_t)(kb0 + 9) * ldn + n]);
        __half2 vz = __floats2half2_rn(W[(size_t)kb1 * ldn + n],       W[(size_t)(kb1 + 1) * ldn + n]);
        __half2 vw = __floats2half2_rn(W[(size_t)(kb1 + 8) * ldn + n], W[(size_t)(kb1 + 9) * ldn + n]);
        uint4 v;
        v.x = *(uint32_t*)&vx; v.y = *(uint32_t*)&vy;
        v.z = *(uint32_t*)&vz; v.w = *(uint32_t*)&vw;
        g_pb4[i] = v;
    }
}

// ---- PTX wrappers ----
__device__ __forceinline__ uint32_t smem_u32(const void* p) {
    return (uint32_t)__cvta_generic_to_shared(p);
}
__device__ __forceinline__ void ldsm_x4(uint32_t& r0, uint32_t& r1, uint32_t& r2, uint32_t& r3, uint32_t a) {
    asm volatile("ldmatrix.sync.aligned.m8n8.x4.shared.b16 {%0,%1,%2,%3}, [%4];"
                 : "=r"(r0), "=r"(r1), "=r"(r2), "=r"(r3) : "r"(a));
}
__device__ __forceinline__ void ldsm_x4_t(uint32_t& r0, uint32_t& r1, uint32_t& r2, uint32_t& r3, uint32_t a) {
    asm volatile("ldmatrix.sync.aligned.m8n8.x4.trans.shared.b16 {%0,%1,%2,%3}, [%4];"
                 : "=r"(r0), "=r"(r1), "=r"(r2), "=r"(r3) : "r"(a));
}
__device__ __forceinline__ void mma16816(float c[4], uint32_t a0, uint32_t a1, uint32_t a2, uint32_t a3,
                                         uint32_t b0, uint32_t b1) {
    asm volatile("mma.sync.aligned.m16n8k16.row.col.f32.f16.f16.f32 "
                 "{%0,%1,%2,%3}, {%4,%5,%6,%7}, {%8,%9}, {%0,%1,%2,%3};"
                 : "+f"(c[0]), "+f"(c[1]), "+f"(c[2]), "+f"(c[3])
                 : "r"(a0), "r"(a1), "r"(a2), "r"(a3), "r"(b0), "r"(b1));
}

__device__ __forceinline__ float gelu_tanh(float x) {
    float x3 = x * x * x;
    float inner = 0.7978845608028654f * fmaf(0.044715f, x3, x);
    return 0.5f * x * (1.0f + tanhf(inner));
}
__device__ __forceinline__ int row_pos(int w0, int row) {
    int p = (w0 + (row >> 4)) * STRIDE + (row & 15);
    return p < (L_SEQ - 1) ? p : (L_SEQ - 1);
}

// ---- M=128 GEMM: 4 strips (32 rows) x 2 N-halves (48 cols), K=96 per chunk ----
// EPI 1: gelu->half Ch(col c*96)   2: half Hh = seg(gmem)+acc   5: qkv special
template <int NC, int EPI>
__device__ __forceinline__ void gemmM(uint32_t aBase,
                                      const uint4* __restrict__ pb4,
                                      const float* __restrict__ bias,
                                      __half* __restrict__ Ch, int CPh,
                                      __half* __restrict__ Hh,
                                      __half* __restrict__ Cv,
                                      const float* __restrict__ xb, int w0, int tid) {
    const int lane = tid & 31, wid = tid >> 5;
    const int strip = wid & 3;       // 32-row M strip
    const int nq = wid >> 2;         // 48-col N half
    const int g = lane >> 2, t = lane & 3;
    const int l15 = lane & 15;
    const int hi8 = (lane >= 16) ? 8 : 0;
    const uint32_t aRow = aBase + (uint32_t)((strip * 32 + l15) * PAH + hi8) * 2;

#pragma unroll
    for (int c = 0; c < NC; c++) {
        float acc[2][6][4];
#pragma unroll
        for (int i = 0; i < 6; i++) {
            float2 bv = *(const float2*)(bias + c * 96 + nq * 48 + i * 8 + t * 2);
#pragma unroll
            for (int rt = 0; rt < 2; rt++) {
                acc[rt][i][0] = bv.x; acc[rt][i][1] = bv.y;
                acc[rt][i][2] = bv.x; acc[rt][i][3] = bv.y;
            }
        }
        const uint4* pw = pb4 + c * 1152 + (nq * 6) * 32 + lane;
#pragma unroll
        for (int kp = 0; kp < 3; kp++) {
            uint4 bv[6];
#pragma unroll
            for (int i = 0; i < 6; i++) bv[i] = __ldg(&pw[(kp * 12 + i) * 32]);
#pragma unroll
            for (int rt = 0; rt < 2; rt++) {
                uint32_t rtOff = aRow + (uint32_t)(rt * 16 * PAH) * 2;
                uint32_t a0, a1, a2, a3;
                ldsm_x4(a0, a1, a2, a3, rtOff + (2 * kp) * 32);
#pragma unroll
                for (int i = 0; i < 6; i++)
                    mma16816(acc[rt][i], a0, a1, a2, a3, bv[i].x, bv[i].y);
                ldsm_x4(a0, a1, a2, a3, rtOff + (2 * kp + 1) * 32);
#pragma unroll
                for (int i = 0; i < 6; i++)
                    mma16816(acc[rt][i], a0, a1, a2, a3, bv[i].z, bv[i].w);
            }
        }
#pragma unroll
        for (int rt = 0; rt < 2; rt++) {
            const int ra = strip * 32 + rt * 16 + g, rb = ra + 8;
#pragma unroll
            for (int i = 0; i < 6; i++) {
                int j = nq * 48 + i * 8 + t * 2;
                if (EPI == 1) {
                    *(__half2*)(Ch + ra * CPh + c * 96 + j) = __floats2half2_rn(gelu_tanh(acc[rt][i][0]), gelu_tanh(acc[rt][i][1]));
                    *(__half2*)(Ch + rb * CPh + c * 96 + j) = __floats2half2_rn(gelu_tanh(acc[rt][i][2]), gelu_tanh(acc[rt][i][3]));
                } else if (EPI == 2) {
                    float2 sa = *(const float2*)(xb + (size_t)row_pos(w0, ra) * 96 + j);
                    float2 sb = *(const float2*)(xb + (size_t)row_pos(w0, rb) * 96 + j);
                    *(__half2*)(Hh + ra * 96 + j) = __floats2half2_rn(sa.x + acc[rt][i][0], sa.y + acc[rt][i][1]);
                    *(__half2*)(Hh + rb * 96 + j) = __floats2half2_rn(sb.x + acc[rt][i][2], sb.y + acc[rt][i][3]);
                } else {  // EPI 5 (qkv)
                    if (c == 0) {   // Q pre-scaled by 0.25
                        *(__half2*)(Ch + ra * CPh + j) = __floats2half2_rn(acc[rt][i][0] * 0.25f, acc[rt][i][1] * 0.25f);
                        *(__half2*)(Ch + rb * CPh + j) = __floats2half2_rn(acc[rt][i][2] * 0.25f, acc[rt][i][3] * 0.25f);
                    } else if (c == 1) {   // K
                        *(__half2*)(Ch + ra * CPh + 96 + j) = __floats2half2_rn(acc[rt][i][0], acc[rt][i][1]);
                        *(__half2*)(Ch + rb * CPh + 96 + j) = __floats2half2_rn(acc[rt][i][2], acc[rt][i][3]);
                    } else {               // V row-major
                        *(__half2*)(Cv + ra * PVH + j) = __floats2half2_rn(acc[rt][i][0], acc[rt][i][1]);
                        *(__half2*)(Cv + rb * PVH + j) = __floats2half2_rn(acc[rt][i][2], acc[rt][i][3]);
                    }
                }
            }
        }
    }
}

// ---- K=192 GEMM (ffn2): Hh(half) += acc ----
__device__ __forceinline__ void gemmW2(uint32_t aBase,
                                       const uint4* __restrict__ pb4,
                                       const float* __restrict__ bias,
                                       __half* __restrict__ Hh, int tid) {
    const int lane = tid & 31, wid = tid >> 5;
    const int strip = wid & 3;
    const int nq = wid >> 2;
    const int g = lane >> 2, t = lane & 3;
    const int l15 = lane & 15;
    const int hi8 = (lane >= 16) ? 8 : 0;
    const uint32_t aRow = aBase + (uint32_t)((strip * 32 + l15) * PGH + hi8) * 2;

    float acc[2][6][4];
#pragma unroll
    for (int i = 0; i < 6; i++) {
        float2 bv = *(const float2*)(bias + nq * 48 + i * 8 + t * 2);
#pragma unroll
        for (int rt = 0; rt < 2; rt++) {
            acc[rt][i][0] = bv.x; acc[rt][i][1] = bv.y;
            acc[rt][i][2] = bv.x; acc[rt][i][3] = bv.y;
        }
    }
    const uint4* pw = pb4 + (nq * 6) * 32 + lane;
#pragma unroll
    for (int kp = 0; kp < 6; kp++) {
        uint4 bv[6];
#pragma unroll
        for (int i = 0; i < 6; i++) bv[i] = __ldg(&pw[(kp * 12 + i) * 32]);
#pragma unroll
        for (int rt = 0; rt < 2; rt++) {
            uint32_t rtOff = aRow + (uint32_t)(rt * 16 * PGH) * 2;
            uint32_t a0, a1, a2, a3;
            ldsm_x4(a0, a1, a2, a3, rtOff + (2 * kp) * 32);
#pragma unroll
            for (int i = 0; i < 6; i++)
                mma16816(acc[rt][i], a0, a1, a2, a3, bv[i].x, bv[i].y);
            ldsm_x4(a0, a1, a2, a3, rtOff + (2 * kp + 1) * 32);
#pragma unroll
            for (int i = 0; i < 6; i++)
                mma16816(acc[rt][i], a0, a1, a2, a3, bv[i].z, bv[i].w);
        }
    }
#pragma unroll
    for (int rt = 0; rt < 2; rt++) {
        const int ra = strip * 32 + rt * 16 + g, rb = ra + 8;
#pragma unroll
        for (int i = 0; i < 6; i++) {
            int j = nq * 48 + i * 8 + t * 2;
            float2 ca = __half22float2(*(__half2*)(Hh + ra * 96 + j));
            float2 cb = __half22float2(*(__half2*)(Hh + rb * 96 + j));
            *(__half2*)(Hh + ra * 96 + j) = __floats2half2_rn(ca.x + acc[rt][i][0], ca.y + acc[rt][i][1]);
            *(__half2*)(Hh + rb * 96 + j) = __floats2half2_rn(cb.x + acc[rt][i][2], cb.y + acc[rt][i][3]);
        }
    }
}

// ---- tensor-core attention: 48 (win,head) pairs, 6 per warp ----
__device__ __forceinline__ void attn_mma(uint32_t uQK, uint32_t uV,
                                         __half* __restrict__ s_a, int tid) {
    const int lane = tid & 31, wid = tid >> 5;
    const int l15 = lane & 15;
    const int lh8 = (lane >= 16) ? 8 : 0;
    const int g = lane >> 2, t = lane & 3;
    const int c0 = 2 * t, c1 = 2 * t + 1, c2 = 2 * t + 8, c3 = 2 * t + 9;

#pragma unroll
    for (int it = 0; it < 6; it++) {
        const int pair = wid + it * 8;       // 0..47
        const int wi = pair / 6, h = pair % 6;
        const int rbase = wi * 16;

        uint32_t qA = uQK + (uint32_t)(((rbase + l15) * PQK + h * 16 + lh8) * 2);
        uint32_t kA = uQK + (uint32_t)(((rbase + l15) * PQK + 96 + h * 16 + lh8) * 2);
        uint32_t vA = uV  + (uint32_t)(((rbase + l15) * PVH + h * 16 + lh8) * 2);

        uint32_t a0, a1, a2, a3, k0, k1, k2, k3, v0, v1, v2, v3;
        ldsm_x4(a0, a1, a2, a3, qA);
        ldsm_x4(k0, k1, k2, k3, kA);
        ldsm_x4_t(v0, v1, v2, v3, vA);

        float s0[4] = {0.f, 0.f, 0.f, 0.f};
        float s1[4] = {0.f, 0.f, 0.f, 0.f};
        mma16816(s0, a0, a1, a2, a3, k0, k2);
        mma16816(s1, a0, a1, a2, a3, k1, k3);

        int g8 = g + 8;
        float e00 = (c0 <= g)  ? __expf(s0[0]) : 0.f;
        float e01 = (c1 <= g)  ? __expf(s0[1]) : 0.f;
        float e02 = (c2 <= g)  ? __expf(s1[0]) : 0.f;
        float e03 = (c3 <= g)  ? __expf(s1[1]) : 0.f;
        float e10 = (c0 <= g8) ? __expf(s0[2]) : 0.f;
        float e11 = (c1 <= g8) ? __expf(s0[3]) : 0.f;
        float e12 = (c2 <= g8) ? __expf(s1[2]) : 0.f;
        float e13 = (c3 <= g8) ? __expf(s1[3]) : 0.f;

        float d0 = e00 + e01 + e02 + e03;
        float d1 = e10 + e11 + e12 + e13;
        d0 += __shfl_xor_sync(0xffffffffu, d0, 1);
        d0 += __shfl_xor_sync(0xffffffffu, d0, 2);
        d1 += __shfl_xor_sync(0xffffffffu, d1, 1);
        d1 += __shfl_xor_sync(0xffffffffu, d1, 2);
        float i0 = 1.0f / d0, i1 = 1.0f / d1;

        __half2 p0 = __floats2half2_rn(e00 * i0, e01 * i0);
        __half2 p1 = __floats2half2_rn(e10 * i1, e11 * i1);
        __half2 p2 = __floats2half2_rn(e02 * i0, e03 * i0);
        __half2 p3 = __floats2half2_rn(e12 * i1, e13 * i1);
        uint32_t pa0 = *(uint32_t*)&p0, pa1 = *(uint32_t*)&p1;
        uint32_t pa2 = *(uint32_t*)&p2, pa3 = *(uint32_t*)&p3;

        float o0[4] = {0.f, 0.f, 0.f, 0.f};
        float o1[4] = {0.f, 0.f, 0.f, 0.f};
        mma16816(o0, pa0, pa1, pa2, pa3, v0, v1);
        mma16816(o1, pa0, pa1, pa2, pa3, v2, v3);

        __half* ba = s_a + (rbase + g) * PAH + h * 16;
        __half* bb = s_a + (rbase + g8) * PAH + h * 16;
        *(__half2*)(ba + 2 * t)     = __floats2half2_rn(o0[0], o0[1]);
        *(__half2*)(ba + 8 + 2 * t) = __floats2half2_rn(o1[0], o1[1]);
        *(__half2*)(bb + 2 * t)     = __floats2half2_rn(o0[2], o0[3]);
        *(__half2*)(bb + 8 + 2 * t) = __floats2half2_rn(o1[2], o1[3]);
    }
}

// ---- LayerNorm 128x96, 2 threads/row ----
// OUT 0: half->dst_h(PAH)  1: fp32->dst_f(96).  SRC 0: half smem (96)  1: gmem fp32 rows
template <int OUT, int SRC>
__device__ __forceinline__ void ln128(const __half* __restrict__ srcH, const float* __restrict__ xb, int w0,
                                      __half* __restrict__ dst_h, float* __restrict__ dst_f,
                                      const float* __restrict__ gg, const float* __restrict__ bb, int tid) {
    int row = tid >> 1, hf = tid & 1;
    float v[48];
    if (SRC == 1) {
        const float* rp = xb + (size_t)row_pos(w0, row) * 96 + hf * 48;
#pragma unroll
        for (int i = 0; i < 12; i++) {
            float4 f = *(const float4*)(rp + i * 4);
            v[4*i] = f.x; v[4*i+1] = f.y; v[4*i+2] = f.z; v[4*i+3] = f.w;
        }
    } else {
        const __half2* rp = (const __half2*)(srcH + row * 96 + hf * 48);
#pragma unroll
        for (int i = 0; i < 24; i++) {
            float2 f = __half22float2(rp[i]);
            v[2*i] = f.x; v[2*i+1] = f.y;
        }
    }
    float s = 0.f;
#pragma unroll
    for (int i = 0; i < 48; i++) s += v[i];
    s += __shfl_xor_sync(0xffffffffu, s, 1);
    float mean = s * (1.0f / 96.0f);
    float q = 0.f;
#pragma unroll
    for (int i = 0; i < 48; i++) { float d = v[i] - mean; q = fmaf(d, d, q); }
    q += __shfl_xor_sync(0xffffffffu, q, 1);
    float rstd = rsqrtf(q * (1.0f / 96.0f) + 1e-5f);
#pragma unroll
    for (int i = 0; i < 24; i++) {
        int d = hf * 48 + i * 2;
        float2 gv = *(const float2*)(gg + d);
        float2 bv = *(const float2*)(bb + d);
        float ox = (v[2*i]   - mean) * rstd * gv.x + bv.x;
        float oy = (v[2*i+1] - mean) * rstd * gv.y + bv.y;
        if (OUT == 0) {
            *(__half2*)(dst_h + row * PAH + d) = __floats2half2_rn(ox, oy);
        } else {
            *(float2*)(dst_f + row * 96 + d) = make_float2(ox, oy);
        }
    }
}

__global__ void __launch_bounds__(NT, 2)
win_block_kernel(const float* __restrict__ x,
                 const float* __restrict__ ln1_g, const float* __restrict__ ln1_b,
                 const float* __restrict__ qkv_b,
                 const float* __restrict__ out_b,
                 const float* __restrict__ ln2_g, const float* __restrict__ ln2_b,
                 const float* __restrict__ ffn_b1, const float* __restrict__ ffn_b2,
                 const float* __restrict__ pln_g, const float* __restrict__ pln_b,
                 float* __restrict__ out) {
    extern __shared__ char sm[];
    __half* s_qk  = (__half*)(sm + OFF_QK);   // 128 x 200 (Q|K)
    __half* s_v   = (__half*)(sm + OFF_V);    // 128 x 104 (V row-major)
    __half* s_a   = (__half*)(sm + OFF_A);    // 128 x 104
    __half* s_g   = (__half*)(sm + OFF_QK);   // alias (gelu out 128x200)
    float*  s_fin = (float*)(sm + OFF_QK);    // alias (final LN fp32 128x96)
    __half* s_h   = (__half*)(sm + OFF_V);    // alias (residual half 128x96)

    const uint32_t uQK = smem_u32(s_qk);
    const uint32_t uV  = smem_u32(s_v);
    const uint32_t uA  = smem_u32(s_a);
    const uint32_t uG  = smem_u32(s_g);

    const int tid = threadIdx.x;
    const int w0  = blockIdx.x * WPC;
    const int b   = blockIdx.y;
    const float* xb = x + (size_t)b * L_SEQ * 96;

    // LN1: gmem -> s_a (half)
    ln128<0, 1>(nullptr, xb, w0, s_a, nullptr, ln1_g, ln1_b, tid);
    __syncthreads();

    // G1: Q(*0.25),K -> s_qk; V -> s_v
    gemmM<3, 5>(uA, g_pb4 + PB4_Q, qkv_b, s_qk, PQK, nullptr, s_v, xb, w0, tid);
    __syncthreads();

    // attention -> s_a
    attn_mma(uQK, uV, s_a, tid);
    __syncthreads();

    // G2: s_h(half) = seg + attn @ Wo + bo  (s_h aliases dead s_v... V region)
    gemmM<1, 2>(uA, g_pb4 + PB4_O, out_b, nullptr, 0, s_h, nullptr, xb, w0, tid);
    __syncthreads();

    // LN2: s_h -> s_a
    ln128<0, 0>(s_h, nullptr, 0, s_a, nullptr, ln2_g, ln2_b, tid);
    __syncthreads();

    // G3: gelu(s_a @ W1 + b1) -> s_g (aliases dead s_qk)
    gemmM<2, 1>(uA, g_pb4 + PB4_F1, ffn_b1, s_g, PGH, nullptr, nullptr, xb, w0, tid);
    __syncthreads();

    // G4: s_h += s_g @ W2 + b2
    gemmW2(uG, g_pb4 + PB4_W2, ffn_b2, s_h, tid);
    __syncthreads();

    // final LN: s_h -> s_fin (fp32, QK region; s_g dead)
    ln128<1, 0>(s_h, nullptr, 0, nullptr, s_fin, pln_g, pln_b, tid);
    __syncthreads();

    // scatter: intra-CTA overlaps combined; atomics only at CTA boundaries
    int nw = NUM_WIN - w0; if (nw > WPC) nw = WPC;
    const int LP = nw * 8 + 8;
    for (int i = tid; i < LP * 96; i += NT) {
        int lp = i / 96, d = i - lp * 96;
        int pos = w0 * STRIDE + lp;
        size_t oidx = ((size_t)b * L_SEQ + pos) * 96 + d;
        if (lp >= 8 && lp < nw * 8) {
            int wiH = lp >> 3, r = lp & 7;
            float vH = s_fin[(wiH * 16 + r) * 96 + d];
            float vL = s_fin[((wiH - 1) * 16 + r + 8) * 96 + d];
            out[oidx] = (vH + vL) * 0.5f;
        } else if (lp < 8) {
            float invc = (pos < STRIDE) ? 1.0f : 0.5f;
            atomicAdd(out + oidx, s_fin[lp * 96 + d] * invc);
        } else {
            int r = lp - (nw - 1) * 8;
            float invc = (pos >= L_SEQ - STRIDE) ? 1.0f : 0.5f;
            atomicAdd(out + oidx, s_fin[((nw - 1) * 16 + r) * 96 + d] * invc);
        }
    }
}

extern "C" void kernel_launch(void* const* d_in, const int* in_sizes, int n_in,
                              void* d_out, int out_size) {
    const float* x      = (const float*)d_in[0];
    const float* ln1_g  = (const float*)d_in[1];
    const float* ln1_b  = (const float*)d_in[2];
    const float* qkv_w  = (const float*)d_in[3];
    const float* qkv_b  = (const float*)d_in[4];
    const float* out_w  = (const float*)d_in[5];
    const float* out_b  = (const float*)d_in[6];
    const float* ln2_g  = (const float*)d_in[7];
    const float* ln2_b  = (const float*)d_in[8];
    const float* ffn_w1 = (const float*)d_in[9];
    const float* ffn_b1 = (const float*)d_in[10];
    const float* ffn_w2 = (const float*)d_in[11];
    const float* ffn_b2 = (const float*)d_in[12];
    const float* pln_g  = (const float*)d_in[13];
    const float* pln_b  = (const float*)d_in[14];
    float* out = (float*)d_out;

    const int B = in_sizes[0] / (L_SEQ * 96);
    const int nblk = (NUM_WIN + WPC - 1) / WPC;   // 128

    static int attr_set = 0;
    if (!attr_set) {
        cudaFuncSetAttribute(win_block_kernel,
                             cudaFuncAttributeMaxDynamicSharedMemorySize, SMEM_BYTES);
        attr_set = 1;
    }

    prep_kernel<<<(out_size + 255) / 256, 256>>>(qkv_w, out_w, ffn_w1, ffn_w2, out, out_size);

    dim3 grid(nblk, B);
    win_block_kernel<<<grid, NT, SMEM_BYTES>>>(
        x, ln1_g, ln1_b, qkv_b, out_b, ln2_g, ln2_b,
        ffn_b1, ffn_b2, pln_g, pln_b, out);
}

// round 14
// speedup vs baseline: 7.4682x; 1.0416x over previous
#include <cuda_runtime.h>
#include <cuda_fp16.h>
#include <cstdint>

#define WIN       16
#define STRIDE    8
#define L_SEQ     8192
#define NUM_WIN   1023
#define WPC       8
#define MROWS     128
#define NT        512

#define PQK       200
#define PVH       104
#define PAH       104
#define PGH       200

#define OFF_QK    0
#define OFF_V     51200
#define OFF_A     77824
#define SMEM_BYTES 104448

// packed B fragments: uint4 = b-frags for two consecutive k16 steps
// chunk layout: [kp][ntile(12)][lane(32)]; 96-K chunk = 3*12*32 = 1152 uint4
#define PB4_Q     0
#define PB4_O     3456
#define PB4_F1    4608
#define PB4_W2    6912
#define PB4_TOTAL 9216

__device__ __align__(16) uint4 g_pb4[PB4_TOTAL];

__global__ void prep_kernel(const float* __restrict__ qkv_w,
                            const float* __restrict__ out_w,
                            const float* __restrict__ w1,
                            const float* __restrict__ w2,
                            float* __restrict__ out, int out_n) {
    int i = blockIdx.x * blockDim.x + threadIdx.x;
    if (i < out_n) out[i] = 0.0f;
    if (i < PB4_TOTAL) {
        const float* W; int ldn, colbase, rem;
        if (i < PB4_O)       { int ch = i / 1152; rem = i % 1152; W = qkv_w; ldn = 288; colbase = ch * 96; }
        else if (i < PB4_F1) { rem = i - PB4_O; W = out_w; ldn = 96; colbase = 0; }
        else if (i < PB4_W2) { int ch = (i - PB4_F1) / 1152; rem = (i - PB4_F1) % 1152; W = w1; ldn = 192; colbase = ch * 96; }
        else                 { rem = i - PB4_W2; W = w2; ldn = 96; colbase = 0; }
        int kp   = rem / (12 * 32);
        int r2   = rem % (12 * 32);
        int nt   = r2 / 32;
        int lane = r2 % 32;
        int n   = colbase + nt * 8 + (lane >> 2);
        int kb0 = (2 * kp) * 16 + (lane & 3) * 2;
        int kb1 = kb0 + 16;
        __half2 vx = __floats2half2_rn(W[(size_t)kb0 * ldn + n],       W[(size_t)(kb0 + 1) * ldn + n]);
        __half2 vy = __floats2half2_rn(W[(size_t)(kb0 + 8) * ldn + n], W[(size_t)(kb0 + 9) * ldn + n]);
        __half2 vz = __floats2half2_rn(W[(size_t)kb1 * ldn + n],       W[(size_t)(kb1 + 1) * ldn + n]);
        __half2 vw = __floats2half2_rn(W[(size_t)(kb1 + 8) * ldn + n], W[(size_t)(kb1 + 9) * ldn + n]);
        uint4 v;
        v.x = *(uint32_t*)&vx; v.y = *(uint32_t*)&vy;
        v.z = *(uint32_t*)&vz; v.w = *(uint32_t*)&vw;
        g_pb4[i] = v;
    }
}

__device__ __forceinline__ uint32_t smem_u32(const void* p) {
    return (uint32_t)__cvta_generic_to_shared(p);
}
__device__ __forceinline__ void ldsm_x4(uint32_t& r0, uint32_t& r1, uint32_t& r2, uint32_t& r3, uint32_t a) {
    asm volatile("ldmatrix.sync.aligned.m8n8.x4.shared.b16 {%0,%1,%2,%3}, [%4];"
                 : "=r"(r0), "=r"(r1), "=r"(r2), "=r"(r3) : "r"(a));
}
__device__ __forceinline__ void ldsm_x4_t(uint32_t& r0, uint32_t& r1, uint32_t& r2, uint32_t& r3, uint32_t a) {
    asm volatile("ldmatrix.sync.aligned.m8n8.x4.trans.shared.b16 {%0,%1,%2,%3}, [%4];"
                 : "=r"(r0), "=r"(r1), "=r"(r2), "=r"(r3) : "r"(a));
}
__device__ __forceinline__ void mma16816(float c[4], uint32_t a0, uint32_t a1, uint32_t a2, uint32_t a3,
                                         uint32_t b0, uint32_t b1) {
    asm volatile("mma.sync.aligned.m16n8k16.row.col.f32.f16.f16.f32 "
                 "{%0,%1,%2,%3}, {%4,%5,%6,%7}, {%8,%9}, {%0,%1,%2,%3};"
                 : "+f"(c[0]), "+f"(c[1]), "+f"(c[2]), "+f"(c[3])
                 : "r"(a0), "r"(a1), "r"(a2), "r"(a3), "r"(b0), "r"(b1));
}

__device__ __forceinline__ float gelu_tanh(float x) {
    float x3 = x * x * x;
    float inner = 0.7978845608028654f * fmaf(0.044715f, x3, x);
    return 0.5f * x * (1.0f + tanhf(inner));
}
__device__ __forceinline__ int row_pos(int w0, int row) {
    int p = (w0 + (row >> 4)) * STRIDE + (row & 15);
    return p < (L_SEQ - 1) ? p : (L_SEQ - 1);
}

// ---- M=128 GEMM: 16 warps = 4 strips (32 rows) x 4 N-quarters (24 cols) ----
// EPI 1: gelu->half Ch(col c*96)   2: half Hh = seg(gmem)+acc   5: qkv special
template <int NC, int EPI>
__device__ __forceinline__ void gemmM(uint32_t aBase,
                                      const uint4* __restrict__ pb4,
                                      const float* __restrict__ bias,
                                      __half* __restrict__ Ch, int CPh,
                                      __half* __restrict__ Hh,
                                      __half* __restrict__ Cv,
                                      const float* __restrict__ xb, int w0, int tid) {
    const int lane = tid & 31, wid = tid >> 5;
    const int strip = wid & 3;       // 32-row M strip
    const int nq = wid >> 2;         // 24-col N quarter (0..3)
    const int g = lane >> 2, t = lane & 3;
    const int l15 = lane & 15;
    const int hi8 = (lane >= 16) ? 8 : 0;
    const uint32_t aRow = aBase + (uint32_t)((strip * 32 + l15) * PAH + hi8) * 2;

#pragma unroll
    for (int c = 0; c < NC; c++) {
        float acc[2][3][4];
#pragma unroll
        for (int i = 0; i < 3; i++) {
            float2 bv = *(const float2*)(bias + c * 96 + nq * 24 + i * 8 + t * 2);
#pragma unroll
            for (int rt = 0; rt < 2; rt++) {
                acc[rt][i][0] = bv.x; acc[rt][i][1] = bv.y;
                acc[rt][i][2] = bv.x; acc[rt][i][3] = bv.y;
            }
        }
        const uint4* pw = pb4 + c * 1152 + (nq * 3) * 32 + lane;
#pragma unroll
        for (int kp = 0; kp < 3; kp++) {
            uint4 bv[3];
#pragma unroll
            for (int i = 0; i < 3; i++) bv[i] = __ldg(&pw[(kp * 12 + i) * 32]);
#pragma unroll
            for (int rt = 0; rt < 2; rt++) {
                uint32_t rtOff = aRow + (uint32_t)(rt * 16 * PAH) * 2;
                uint32_t a0, a1, a2, a3;
                ldsm_x4(a0, a1, a2, a3, rtOff + (2 * kp) * 32);
#pragma unroll
                for (int i = 0; i < 3; i++)
                    mma16816(acc[rt][i], a0, a1, a2, a3, bv[i].x, bv[i].y);
                ldsm_x4(a0, a1, a2, a3, rtOff + (2 * kp + 1) * 32);
#pragma unroll
                for (int i = 0; i < 3; i++)
                    mma16816(acc[rt][i], a0, a1, a2, a3, bv[i].z, bv[i].w);
            }
        }
#pragma unroll
        for (int rt = 0; rt < 2; rt++) {
            const int ra = strip * 32 + rt * 16 + g, rb = ra + 8;
#pragma unroll
            for (int i = 0; i < 3; i++) {
                int j = nq * 24 + i * 8 + t * 2;
                if (EPI == 1) {
                    *(__half2*)(Ch + ra * CPh + c * 96 + j) = __floats2half2_rn(gelu_tanh(acc[rt][i][0]), gelu_tanh(acc[rt][i][1]));
                    *(__half2*)(Ch + rb * CPh + c * 96 + j) = __floats2half2_rn(gelu_tanh(acc[rt][i][2]), gelu_tanh(acc[rt][i][3]));
                } else if (EPI == 2) {
                    float2 sa = *(const float2*)(xb + (size_t)row_pos(w0, ra) * 96 + j);
                    float2 sb = *(const float2*)(xb + (size_t)row_pos(w0, rb) * 96 + j);
                    *(__half2*)(Hh + ra * 96 + j) = __floats2half2_rn(sa.x + acc[rt][i][0], sa.y + acc[rt][i][1]);
                    *(__half2*)(Hh + rb * 96 + j) = __floats2half2_rn(sb.x + acc[rt][i][2], sb.y + acc[rt][i][3]);
                } else {  // EPI 5 (qkv)
                    if (c == 0) {
                        *(__half2*)(Ch + ra * CPh + j) = __floats2half2_rn(acc[rt][i][0] * 0.25f, acc[rt][i][1] * 0.25f);
                        *(__half2*)(Ch + rb * CPh + j) = __floats2half2_rn(acc[rt][i][2] * 0.25f, acc[rt][i][3] * 0.25f);
                    } else if (c == 1) {
                        *(__half2*)(Ch + ra * CPh + 96 + j) = __floats2half2_rn(acc[rt][i][0], acc[rt][i][1]);
                        *(__half2*)(Ch + rb * CPh + 96 + j) = __floats2half2_rn(acc[rt][i][2], acc[rt][i][3]);
                    } else {
                        *(__half2*)(Cv + ra * PVH + j) = __floats2half2_rn(acc[rt][i][0], acc[rt][i][1]);
                        *(__half2*)(Cv + rb * PVH + j) = __floats2half2_rn(acc[rt][i][2], acc[rt][i][3]);
                    }
                }
            }
        }
    }
}

// ---- K=192 GEMM (ffn2): Hh(half) += acc ----
__device__ __forceinline__ void gemmW2(uint32_t aBase,
                                       const uint4* __restrict__ pb4,
                                       const float* __restrict__ bias,
                                       __half* __restrict__ Hh, int tid) {
    const int lane = tid & 31, wid = tid >> 5;
    const int strip = wid & 3;
    const int nq = wid >> 2;
    const int g = lane >> 2, t = lane & 3;
    const int l15 = lane & 15;
    const int hi8 = (lane >= 16) ? 8 : 0;
    const uint32_t aRow = aBase + (uint32_t)((strip * 32 + l15) * PGH + hi8) * 2;

    float acc[2][3][4];
#pragma unroll
    for (int i = 0; i < 3; i++) {
        float2 bv = *(const float2*)(bias + nq * 24 + i * 8 + t * 2);
#pragma unroll
        for (int rt = 0; rt < 2; rt++) {
            acc[rt][i][0] = bv.x; acc[rt][i][1] = bv.y;
            acc[rt][i][2] = bv.x; acc[rt][i][3] = bv.y;
        }
    }
    const uint4* pw = pb4 + (nq * 3) * 32 + lane;
#pragma unroll
    for (int kp = 0; kp < 6; kp++) {
        uint4 bv[3];
#pragma unroll
        for (int i = 0; i < 3; i++) bv[i] = __ldg(&pw[(kp * 12 + i) * 32]);
#pragma unroll
        for (int rt = 0; rt < 2; rt++) {
            uint32_t rtOff = aRow + (uint32_t)(rt * 16 * PGH) * 2;
            uint32_t a0, a1, a2, a3;
            ldsm_x4(a0, a1, a2, a3, rtOff + (2 * kp) * 32);
#pragma unroll
            for (int i = 0; i < 3; i++)
                mma16816(acc[rt][i], a0, a1, a2, a3, bv[i].x, bv[i].y);
            ldsm_x4(a0, a1, a2, a3, rtOff + (2 * kp + 1) * 32);
#pragma unroll
            for (int i = 0; i < 3; i++)
                mma16816(acc[rt][i], a0, a1, a2, a3, bv[i].z, bv[i].w);
        }
    }
#pragma unroll
    for (int rt = 0; rt < 2; rt++) {
        const int ra = strip * 32 + rt * 16 + g, rb = ra + 8;
#pragma unroll
        for (int i = 0; i < 3; i++) {
            int j = nq * 24 + i * 8 + t * 2;
            float2 ca = __half22float2(*(__half2*)(Hh + ra * 96 + j));
            float2 cb = __half22float2(*(__half2*)(Hh + rb * 96 + j));
            *(__half2*)(Hh + ra * 96 + j) = __floats2half2_rn(ca.x + acc[rt][i][0], ca.y + acc[rt][i][1]);
            *(__half2*)(Hh + rb * 96 + j) = __floats2half2_rn(cb.x + acc[rt][i][2], cb.y + acc[rt][i][3]);
        }
    }
}

// ---- tensor-core attention: 48 (win,head) pairs over 16 warps, 3 per warp ----
__device__ __forceinline__ void attn_mma(uint32_t uQK, uint32_t uV,
                                         __half* __restrict__ s_a, int tid) {
    const int lane = tid & 31, wid = tid >> 5;
    const int l15 = lane & 15;
    const int lh8 = (lane >= 16) ? 8 : 0;
    const int g = lane >> 2, t = lane & 3;
    const int c0 = 2 * t, c1 = 2 * t + 1, c2 = 2 * t + 8, c3 = 2 * t + 9;

#pragma unroll
    for (int it = 0; it < 3; it++) {
        const int pair = wid + it * 16;      // 0..47
        const int wi = pair / 6, h = pair % 6;
        const int rbase = wi * 16;

        uint32_t qA = uQK + (uint32_t)(((rbase + l15) * PQK + h * 16 + lh8) * 2);
        uint32_t kA = uQK + (uint32_t)(((rbase + l15) * PQK + 96 + h * 16 + lh8) * 2);
        uint32_t vA = uV  + (uint32_t)(((rbase + l15) * PVH + h * 16 + lh8) * 2);

        uint32_t a0, a1, a2, a3, k0, k1, k2, k3, v0, v1, v2, v3;
        ldsm_x4(a0, a1, a2, a3, qA);
        ldsm_x4(k0, k1, k2, k3, kA);
        ldsm_x4_t(v0, v1, v2, v3, vA);

        float s0[4] = {0.f, 0.f, 0.f, 0.f};
        float s1[4] = {0.f, 0.f, 0.f, 0.f};
        mma16816(s0, a0, a1, a2, a3, k0, k2);
        mma16816(s1, a0, a1, a2, a3, k1, k3);

        int g8 = g + 8;
        float e00 = (c0 <= g)  ? __expf(s0[0]) : 0.f;
        float e01 = (c1 <= g)  ? __expf(s0[1]) : 0.f;
        float e02 = (c2 <= g)  ? __expf(s1[0]) : 0.f;
        float e03 = (c3 <= g)  ? __expf(s1[1]) : 0.f;
        float e10 = (c0 <= g8) ? __expf(s0[2]) : 0.f;
        float e11 = (c1 <= g8) ? __expf(s0[3]) : 0.f;
        float e12 = (c2 <= g8) ? __expf(s1[2]) : 0.f;
        float e13 = (c3 <= g8) ? __expf(s1[3]) : 0.f;

        float d0 = e00 + e01 + e02 + e03;
        float d1 = e10 + e11 + e12 + e13;
        d0 += __shfl_xor_sync(0xffffffffu, d0, 1);
        d0 += __shfl_xor_sync(0xffffffffu, d0, 2);
        d1 += __shfl_xor_sync(0xffffffffu, d1, 1);
        d1 += __shfl_xor_sync(0xffffffffu, d1, 2);
        float i0 = 1.0f / d0, i1 = 1.0f / d1;

        __half2 p0 = __floats2half2_rn(e00 * i0, e01 * i0);
        __half2 p1 = __floats2half2_rn(e10 * i1, e11 * i1);
        __half2 p2 = __floats2half2_rn(e02 * i0, e03 * i0);
        __half2 p3 = __floats2half2_rn(e12 * i1, e13 * i1);
        uint32_t pa0 = *(uint32_t*)&p0, pa1 = *(uint32_t*)&p1;
        uint32_t pa2 = *(uint32_t*)&p2, pa3 = *(uint32_t*)&p3;

        float o0[4] = {0.f, 0.f, 0.f, 0.f};
        float o1[4] = {0.f, 0.f, 0.f, 0.f};
        mma16816(o0, pa0, pa1, pa2, pa3, v0, v1);
        mma16816(o1, pa0, pa1, pa2, pa3, v2, v3);

        __half* ba = s_a + (rbase + g) * PAH + h * 16;
        __half* bb = s_a + (rbase + g8) * PAH + h * 16;
        *(__half2*)(ba + 2 * t)     = __floats2half2_rn(o0[0], o0[1]);
        *(__half2*)(ba + 8 + 2 * t) = __floats2half2_rn(o1[0], o1[1]);
        *(__half2*)(bb + 2 * t)     = __floats2half2_rn(o0[2], o0[3]);
        *(__half2*)(bb + 8 + 2 * t) = __floats2half2_rn(o1[2], o1[3]);
    }
}

// ---- LayerNorm 128x96, 4 threads/row (512 threads) ----
// OUT 0: half->dst_h(PAH)  1: fp32->dst_f(96).  SRC 0: half smem (96)  1: gmem fp32 rows
template <int OUT, int SRC>
__device__ __forceinline__ void ln128(const __half* __restrict__ srcH, const float* __restrict__ xb, int w0,
                                      __half* __restrict__ dst_h, float* __restrict__ dst_f,
                                      const float* __restrict__ gg, const float* __restrict__ bb, int tid) {
    int row = tid >> 2, qt = tid & 3;
    float v[24];
    if (SRC == 1) {
        const float* rp = xb + (size_t)row_pos(w0, row) * 96 + qt * 24;
#pragma unroll
        for (int i = 0; i < 6; i++) {
            float4 f = *(const float4*)(rp + i * 4);
            v[4*i] = f.x; v[4*i+1] = f.y; v[4*i+2] = f.z; v[4*i+3] = f.w;
        }
    } else {
        const __half2* rp = (const __half2*)(srcH + row * 96 + qt * 24);
#pragma unroll
        for (int i = 0; i < 12; i++) {
            float2 f = __half22float2(rp[i]);
            v[2*i] = f.x; v[2*i+1] = f.y;
        }
    }
    float s = 0.f;
#pragma unroll
    for (int i = 0; i < 24; i++) s += v[i];
    s += __shfl_xor_sync(0xffffffffu, s, 1);
    s += __shfl_xor_sync(0xffffffffu, s, 2);
    float mean = s * (1.0f / 96.0f);
    float q = 0.f;
#pragma unroll
    for (int i = 0; i < 24; i++) { float d = v[i] - mean; q = fmaf(d, d, q); }
    q += __shfl_xor_sync(0xffffffffu, q, 1);
    q += __shfl_xor_sync(0xffffffffu, q, 2);
    float rstd = rsqrtf(q * (1.0f / 96.0f) + 1e-5f);
#pragma unroll
    for (int i = 0; i < 12; i++) {
        int d = qt * 24 + i * 2;
        float2 gv = *(const float2*)(gg + d);
        float2 bv = *(const float2*)(bb + d);
        float ox = (v[2*i]   - mean) * rstd * gv.x + bv.x;
        float oy = (v[2*i+1] - mean) * rstd * gv.y + bv.y;
        if (OUT == 0) {
            *(__half2*)(dst_h + row * PAH + d) = __floats2half2_rn(ox, oy);
        } else {
            *(float2*)(dst_f + row * 96 + d) = make_float2(ox, oy);
        }
    }
}

__global__ void __launch_bounds__(NT, 2)
win_block_kernel(const float* __restrict__ x,
                 const float* __restrict__ ln1_g, const float* __restrict__ ln1_b,
                 const float* __restrict__ qkv_b,
                 const float* __restrict__ out_b,
                 const float* __restrict__ ln2_g, const float* __restrict__ ln2_b,
                 const float* __restrict__ ffn_b1, const float* __restrict__ ffn_b2,
                 const float* __restrict__ pln_g, const float* __restrict__ pln_b,
                 float* __restrict__ out) {
    extern __shared__ char sm[];
    __half* s_qk  = (__half*)(sm + OFF_QK);   // 128 x 200 (Q|K)
    __half* s_v   = (__half*)(sm + OFF_V);    // 128 x 104 (V row-major)
    __half* s_a   = (__half*)(sm + OFF_A);    // 128 x 104
    __half* s_g   = (__half*)(sm + OFF_QK);   // alias (gelu out 128x200)
    float*  s_fin = (float*)(sm + OFF_QK);    // alias (final LN fp32)
    __half* s_h   = (__half*)(sm + OFF_V);    // alias (residual half 128x96)

    const uint32_t uQK = smem_u32(s_qk);
    const uint32_t uV  = smem_u32(s_v);
    const uint32_t uA  = smem_u32(s_a);
    const uint32_t uG  = smem_u32(s_g);

    const int tid = threadIdx.x;
    const int w0  = blockIdx.x * WPC;
    const int b   = blockIdx.y;
    const float* xb = x + (size_t)b * L_SEQ * 96;

    ln128<0, 1>(nullptr, xb, w0, s_a, nullptr, ln1_g, ln1_b, tid);
    __syncthreads();

    gemmM<3, 5>(uA, g_pb4 + PB4_Q, qkv_b, s_qk, PQK, nullptr, s_v, xb, w0, tid);
    __syncthreads();

    attn_mma(uQK, uV, s_a, tid);
    __syncthreads();

    gemmM<1, 2>(uA, g_pb4 + PB4_O, out_b, nullptr, 0, s_h, nullptr, xb, w0, tid);
    __syncthreads();

    ln128<0, 0>(s_h, nullptr, 0, s_a, nullptr, ln2_g, ln2_b, tid);
    __syncthreads();

    gemmM<2, 1>(uA, g_pb4 + PB4_F1, ffn_b1, s_g, PGH, nullptr, nullptr, xb, w0, tid);
    __syncthreads();

    gemmW2(uG, g_pb4 + PB4_W2, ffn_b2, s_h, tid);
    __syncthreads();

    ln128<1, 0>(s_h, nullptr, 0, nullptr, s_fin, pln_g, pln_b, tid);
    __syncthreads();

    int nw = NUM_WIN - w0; if (nw > WPC) nw = WPC;
    const int LP = nw * 8 + 8;
    for (int i = tid; i < LP * 96; i += NT) {
        int lp = i / 96, d = i - lp * 96;
        int pos = w0 * STRIDE + lp;
        size_t oidx = ((size_t)b * L_SEQ + pos) * 96 + d;
        if (lp >= 8 && lp < nw * 8) {
            int wiH = lp >> 3, r = lp & 7;
            float vH = s_fin[(wiH * 16 + r) * 96 + d];
            float vL = s_fin[((wiH - 1) * 16 + r + 8) * 96 + d];
            out[oidx] = (vH + vL) * 0.5f;
        } else if (lp < 8) {
            float invc = (pos < STRIDE) ? 1.0f : 0.5f;
            atomicAdd(out + oidx, s_fin[lp * 96 + d] * invc);
        } else {
            int r = lp - (nw - 1) * 8;
            float invc = (pos >= L_SEQ - STRIDE) ? 1.0f : 0.5f;
            atomicAdd(out + oidx, s_fin[((nw - 1) * 16 + r) * 96 + d] * invc);
        }
    }
}

extern "C" void kernel_launch(void* const* d_in, const int* in_sizes, int n_in,
                              void* d_out, int out_size) {
    const float* x      = (const float*)d_in[0];
    const float* ln1_g  = (const float*)d_in[1];
    const float* ln1_b  = (const float*)d_in[2];
    const float* qkv_w  = (const float*)d_in[3];
    const float* qkv_b  = (const float*)d_in[4];
    const float* out_w  = (const float*)d_in[5];
    const float* out_b  = (const float*)d_in[6];
    const float* ln2_g  = (const float*)d_in[7];
    const float* ln2_b  = (const float*)d_in[8];
    const float* ffn_w1 = (const float*)d_in[9];
    const float* ffn_b1 = (const float*)d_in[10];
    const float* ffn_w2 = (const float*)d_in[11];
    const float* ffn_b2 = (const float*)d_in[12];
    const float* pln_g  = (const float*)d_in[13];
    const float* pln_b  = (const float*)d_in[14];
    float* out = (float*)d_out;

    const int B = in_sizes[0] / (L_SEQ * 96);
    const int nblk = (NUM_WIN + WPC - 1) / WPC;   // 128

    static int attr_set = 0;
    if (!attr_set) {
        cudaFuncSetAttribute(win_block_kernel,
                             cudaFuncAttributeMaxDynamicSharedMemorySize, SMEM_BYTES);
        attr_set = 1;
    }

    prep_kernel<<<(out_size + 255) / 256, 256>>>(qkv_w, out_w, ffn_w1, ffn_w2, out, out_size);

    dim3 grid(nblk, B);
    win_block_kernel<<<grid, NT, SMEM_BYTES>>>(
        x, ln1_g, ln1_b, qkv_b, out_b, ln2_g, ln2_b,
        ffn_b1, ffn_b2, pln_g, pln_b, out);
}